// round 1
// baseline (speedup 1.0000x reference)
#include <cuda_runtime.h>
#include <math.h>

#define Bsz   2
#define Lseq  1024
#define Dm    512
#define Kp    32
#define NLY   4
#define FFd   2048
#define Vocab 32000
#define NTOK  (Bsz*Lseq)   // 2048

// ---------------- scratch (no allocs allowed) ----------------
__device__ float g_h  [NTOK*Dm];
__device__ float g_x  [NTOK*Dm];
__device__ float g_t1 [NTOK*Dm];
__device__ float g_cp [NTOK*Kp];
__device__ float g_C  [NTOK*Kp];
__device__ float g_S  [NTOK*Kp];
__device__ float g_v  [NTOK*Dm];
__device__ float g_A  [Bsz*Lseq*Lseq];
__device__ float g_ret[NTOK*Dm];
__device__ float g_rln[NTOK*Dm];
__device__ float g_o  [NTOK*Dm];
__device__ float g_mid[NTOK*FFd];
__device__ float g_hn [NTOK*Dm];

// ---------------- embed gather ----------------
__global__ void gather_kernel(const int* __restrict__ tokens,
                              const float* __restrict__ embed,
                              float* __restrict__ h) {
    int row = blockIdx.x;
    int tok = tokens[row];
    const float4* src = (const float4*)(embed + (size_t)tok * Dm);
    float4* dst = (float4*)(h + (size_t)row * Dm);
    dst[threadIdx.x] = src[threadIdx.x];   // 128 threads * 4 = 512
}

// ---------------- layernorm (D=512, 128 threads/row) ----------------
__global__ void ln_kernel(const float* __restrict__ in,
                          const float* __restrict__ g,
                          const float* __restrict__ b,
                          float* __restrict__ out) {
    int row = blockIdx.x;
    int tid = threadIdx.x;
    const float4* x4 = (const float4*)(in + (size_t)row * Dm);
    float4 v = x4[tid];
    float s = v.x + v.y + v.z + v.w;
    float q = v.x*v.x + v.y*v.y + v.z*v.z + v.w*v.w;
    #pragma unroll
    for (int off = 16; off; off >>= 1) {
        s += __shfl_xor_sync(0xffffffffu, s, off);
        q += __shfl_xor_sync(0xffffffffu, q, off);
    }
    __shared__ float ss[4], sq[4];
    int w = tid >> 5;
    if ((tid & 31) == 0) { ss[w] = s; sq[w] = q; }
    __syncthreads();
    s = ss[0] + ss[1] + ss[2] + ss[3];
    q = sq[0] + sq[1] + sq[2] + sq[3];
    float mean = s * (1.0f / Dm);
    float var  = q * (1.0f / Dm) - mean * mean;
    float r = rsqrtf(var + 1e-5f);
    const float4* g4 = (const float4*)g;
    const float4* b4 = (const float4*)b;
    float4 gv = g4[tid], bv = b4[tid], o;
    o.x = (v.x - mean) * r * gv.x + bv.x;
    o.y = (v.y - mean) * r * gv.y + bv.y;
    o.z = (v.z - mean) * r * gv.z + bv.z;
    o.w = (v.w - mean) * r * gv.w + bv.w;
    ((float4*)(out + (size_t)row * Dm))[tid] = o;
}

// ---------------- generic tiled fp32 GEMM ----------------
// C[M,N] = act(A[M,Kd] @ B + bias). NT=false: B is [Kd,N] row-major.
// NT=true:  B is [N,Kd] row-major (dot of rows) — used for tied head.
// ACT: 0 none, 1 tanh, 2 tanh*pi, 3 exact gelu
template<int ACT, bool NT>
__global__ void gemm_kernel(const float* __restrict__ A, const float* __restrict__ Bm,
                            const float* __restrict__ bias, float* __restrict__ Cc,
                            int M, int N, int Kd) {
    const int BK = 16;
    __shared__ __align__(16) float As[16][64];
    __shared__ __align__(16) float Bs[16][64];
    int tid = threadIdx.x;
    int tx = tid & 15, ty = tid >> 4;
    int row0 = blockIdx.y * 64, col0 = blockIdx.x * 64;
    float acc[4][4] = {};
    int ar = tid >> 2, ac = (tid & 3) << 2;

    for (int k0 = 0; k0 < Kd; k0 += BK) {
        float4 av = make_float4(0.f, 0.f, 0.f, 0.f);
        int gr = row0 + ar;
        if (gr < M) av = *(const float4*)(A + (size_t)gr * Kd + k0 + ac);
        As[ac+0][ar] = av.x; As[ac+1][ar] = av.y;
        As[ac+2][ar] = av.z; As[ac+3][ar] = av.w;
        if (!NT) {
            int br = tid >> 4, bc = (tid & 15) << 2;
            float4 bv = make_float4(0.f, 0.f, 0.f, 0.f);
            int gc = col0 + bc;
            if (gc < N) bv = *(const float4*)(Bm + (size_t)(k0 + br) * N + gc);
            *(float4*)&Bs[br][bc] = bv;
        } else {
            int bn = tid >> 2, bk = (tid & 3) << 2;
            float4 bv = make_float4(0.f, 0.f, 0.f, 0.f);
            int gn = col0 + bn;
            if (gn < N) bv = *(const float4*)(Bm + (size_t)gn * Kd + k0 + bk);
            Bs[bk+0][bn] = bv.x; Bs[bk+1][bn] = bv.y;
            Bs[bk+2][bn] = bv.z; Bs[bk+3][bn] = bv.w;
        }
        __syncthreads();
        #pragma unroll
        for (int k = 0; k < BK; k++) {
            float4 a4 = *(const float4*)&As[k][ty << 2];
            float4 b4 = *(const float4*)&Bs[k][tx << 2];
            float ax[4] = {a4.x, a4.y, a4.z, a4.w};
            float bx[4] = {b4.x, b4.y, b4.z, b4.w};
            #pragma unroll
            for (int i = 0; i < 4; i++)
                #pragma unroll
                for (int j = 0; j < 4; j++)
                    acc[i][j] += ax[i] * bx[j];
        }
        __syncthreads();
    }
    #pragma unroll
    for (int i = 0; i < 4; i++) {
        int row = row0 + (ty << 2) + i;
        if (row >= M) continue;
        #pragma unroll
        for (int j = 0; j < 4; j++) {
            int col = col0 + (tx << 2) + j;
            if (col >= N) continue;
            float vv = acc[i][j];
            if (bias) vv += bias[col];
            if (ACT == 1)      vv = tanhf(vv);
            else if (ACT == 2) vv = tanhf(vv) * 3.14159274101257324f;
            else if (ACT == 3) vv = 0.5f * vv * (1.0f + erff(vv * 0.70710678118654752f));
            Cc[(size_t)row * N + col] = vv;
        }
    }
}

// ---------------- phase (cos/sin of target phase) ----------------
__global__ void phase_kernel(const float* __restrict__ cp,
                             const float* __restrict__ ps,
                             const float* __restrict__ cs, int layer,
                             float* __restrict__ C, float* __restrict__ S) {
    int idx = blockIdx.x * 256 + threadIdx.x;
    if (idx >= NTOK * Kp) return;
    int k = idx & (Kp - 1);
    int l = (idx >> 5) & (Lseq - 1);
    float freq = (float)exp(-(double)k / (double)Kp * 9.210340371976184); // ln 1e4
    float tp = ps[layer] * ((float)l * freq) + cs[layer] * cp[idx];
    C[idx] = cosf(tp);
    S[idx] = sinf(tp);
}

// ---------------- causal kernel matrix A = (C C^T + S S^T) * inv_norm[l] ----------------
__global__ void build_A_kernel(const float* __restrict__ C, const float* __restrict__ S,
                               float* __restrict__ A) {
    __shared__ float cl[16][33], sl[16][33], ct[16][33], st[16][33];
    int b = blockIdx.z;
    int tid = threadIdx.y * 16 + threadIdx.x;
    int l0 = blockIdx.y * 16, t0 = blockIdx.x * 16;
    const float* Cb = C + (size_t)b * Lseq * Kp;
    const float* Sb = S + (size_t)b * Lseq * Kp;
    for (int i = tid; i < 16 * 32; i += 256) {
        int r = i >> 5, c = i & 31;
        cl[r][c] = Cb[(size_t)(l0 + r) * Kp + c];
        sl[r][c] = Sb[(size_t)(l0 + r) * Kp + c];
        ct[r][c] = Cb[(size_t)(t0 + r) * Kp + c];
        st[r][c] = Sb[(size_t)(t0 + r) * Kp + c];
    }
    __syncthreads();
    int l = l0 + threadIdx.y, t = t0 + threadIdx.x;
    float acc = 0.f;
    #pragma unroll
    for (int k = 0; k < 32; k++)
        acc += cl[threadIdx.y][k] * ct[threadIdx.x][k]
             + sl[threadIdx.y][k] * st[threadIdx.x][k];
    float out = (t <= l) ? acc * rsqrtf((float)((l + 1) * Kp)) : 0.f;
    A[((size_t)b * Lseq + l) * Lseq + t] = out;
}

// ---------------- residual adds ----------------
__global__ void add3_kernel(float* __restrict__ h, const float* __restrict__ x,
                            const float* __restrict__ o) {
    int i = blockIdx.x * 256 + threadIdx.x;
    h[i] += x[i] + o[i];
}
__global__ void add2_kernel(float* __restrict__ h, const float* __restrict__ o) {
    int i = blockIdx.x * 256 + threadIdx.x;
    h[i] += o[i];
}

// ---------------- driver ----------------
extern "C" void kernel_launch(void* const* d_in, const int* in_sizes, int n_in,
                              void* d_out, int out_size) {
    const int*   tokens  = (const int*)  d_in[0];
    const float* embed   = (const float*)d_in[1];
    const float* ln1_g   = (const float*)d_in[2];
    const float* ln1_b   = (const float*)d_in[3];
    const float* cp_w1   = (const float*)d_in[4];
    const float* cp_b1   = (const float*)d_in[5];
    const float* cp_w2   = (const float*)d_in[6];
    const float* cp_b2   = (const float*)d_in[7];
    const float* pscale  = (const float*)d_in[8];
    const float* cscale  = (const float*)d_in[9];
    const float* val_w   = (const float*)d_in[10];
    const float* val_b   = (const float*)d_in[11];
    const float* oln_g   = (const float*)d_in[12];
    const float* oln_b   = (const float*)d_in[13];
    const float* out_w   = (const float*)d_in[14];
    const float* out_b   = (const float*)d_in[15];
    const float* ln2_g   = (const float*)d_in[16];
    const float* ln2_b   = (const float*)d_in[17];
    const float* ffn_w1  = (const float*)d_in[18];
    const float* ffn_b1  = (const float*)d_in[19];
    const float* ffn_w2  = (const float*)d_in[20];
    const float* ffn_b2  = (const float*)d_in[21];
    const float* no_g    = (const float*)d_in[22];
    const float* no_b    = (const float*)d_in[23];
    const float* head_b  = (const float*)d_in[24];
    float* logits = (float*)d_out;

    float *h, *x, *t1, *cp, *Cb, *Sb, *v, *A, *ret, *rln, *o, *mid, *hn;
    cudaGetSymbolAddress((void**)&h,   g_h);
    cudaGetSymbolAddress((void**)&x,   g_x);
    cudaGetSymbolAddress((void**)&t1,  g_t1);
    cudaGetSymbolAddress((void**)&cp,  g_cp);
    cudaGetSymbolAddress((void**)&Cb,  g_C);
    cudaGetSymbolAddress((void**)&Sb,  g_S);
    cudaGetSymbolAddress((void**)&v,   g_v);
    cudaGetSymbolAddress((void**)&A,   g_A);
    cudaGetSymbolAddress((void**)&ret, g_ret);
    cudaGetSymbolAddress((void**)&rln, g_rln);
    cudaGetSymbolAddress((void**)&o,   g_o);
    cudaGetSymbolAddress((void**)&mid, g_mid);
    cudaGetSymbolAddress((void**)&hn,  g_hn);

    gather_kernel<<<NTOK, 128>>>(tokens, embed, h);

    dim3 gD((Dm  + 63) / 64, (NTOK + 63) / 64);   // 2048 x 512
    dim3 gK((Kp  + 63) / 64, (NTOK + 63) / 64);   // 2048 x 32
    dim3 gF((FFd + 63) / 64, (NTOK + 63) / 64);   // 2048 x 2048
    dim3 gR((Dm  + 63) / 64, (Lseq + 63) / 64);   // 1024 x 512 (per batch)

    for (int i = 0; i < NLY; i++) {
        ln_kernel<<<NTOK, 128>>>(h, ln1_g + i * Dm, ln1_b + i * Dm, x);
        gemm_kernel<1, false><<<gD, 256>>>(x, cp_w1 + (size_t)i * Dm * Dm,
                                           cp_b1 + i * Dm, t1, NTOK, Dm, Dm);
        gemm_kernel<2, false><<<gK, 256>>>(t1, cp_w2 + (size_t)i * Dm * Kp,
                                           cp_b2 + i * Kp, cp, NTOK, Kp, Dm);
        phase_kernel<<<(NTOK * Kp + 255) / 256, 256>>>(cp, pscale, cscale, i, Cb, Sb);
        gemm_kernel<0, false><<<gD, 256>>>(x, val_w + (size_t)i * Dm * Dm,
                                           val_b + i * Dm, v, NTOK, Dm, Dm);
        build_A_kernel<<<dim3(Lseq / 16, Lseq / 16, Bsz), dim3(16, 16)>>>(Cb, Sb, A);
        for (int b = 0; b < Bsz; b++)
            gemm_kernel<0, false><<<gR, 256>>>(A + (size_t)b * Lseq * Lseq,
                                               v + (size_t)b * Lseq * Dm, (const float*)0,
                                               ret + (size_t)b * Lseq * Dm,
                                               Lseq, Dm, Lseq);
        ln_kernel<<<NTOK, 128>>>(ret, oln_g + i * Dm, oln_b + i * Dm, rln);
        gemm_kernel<0, false><<<gD, 256>>>(rln, out_w + (size_t)i * Dm * Dm,
                                           out_b + i * Dm, o, NTOK, Dm, Dm);
        add3_kernel<<<(NTOK * Dm) / 256, 256>>>(h, x, o);
        ln_kernel<<<NTOK, 128>>>(h, ln2_g + i * Dm, ln2_b + i * Dm, x); // x := y
        gemm_kernel<3, false><<<gF, 256>>>(x, ffn_w1 + (size_t)i * Dm * FFd,
                                           ffn_b1 + i * FFd, mid, NTOK, FFd, Dm);
        gemm_kernel<0, false><<<gD, 256>>>(mid, ffn_w2 + (size_t)i * FFd * Dm,
                                           ffn_b2 + i * Dm, o, NTOK, Dm, FFd);
        add2_kernel<<<(NTOK * Dm) / 256, 256>>>(h, o);
    }

    ln_kernel<<<NTOK, 128>>>(h, no_g, no_b, hn);
    dim3 gH((Vocab + 63) / 64, (NTOK + 63) / 64);
    gemm_kernel<0, true><<<gH, 256>>>(hn, embed, head_b, logits, NTOK, Vocab, Dm);
}

// round 2
// speedup vs baseline: 2.3155x; 2.3155x over previous
#include <cuda_runtime.h>
#include <math.h>

#define Bsz   2
#define Lseq  1024
#define Dm    512
#define Kp    32
#define NLY   4
#define FFd   2048
#define Vocab 32000
#define NTOK  (Bsz*Lseq)   // 2048

// ---------------- scratch (no allocs allowed) ----------------
__device__ float g_h  [NTOK*Dm];
__device__ float g_x  [NTOK*Dm];
__device__ float g_t1 [NTOK*Dm];
__device__ float g_cp [NTOK*Kp];
__device__ float g_C  [NTOK*Kp];
__device__ float g_S  [NTOK*Kp];
__device__ float g_v  [NTOK*Dm];
__device__ float g_A  [Bsz*Lseq*Lseq];
__device__ float g_ret[NTOK*Dm];
__device__ float g_rln[NTOK*Dm];
__device__ float g_o  [NTOK*Dm];
__device__ float g_mid[NTOK*FFd];
__device__ float g_hn [NTOK*Dm];

// ---------------- embed gather ----------------
__global__ void gather_kernel(const int* __restrict__ tokens,
                              const float* __restrict__ embed,
                              float* __restrict__ h) {
    int row = blockIdx.x;
    int tok = tokens[row];
    const float4* src = (const float4*)(embed + (size_t)tok * Dm);
    float4* dst = (float4*)(h + (size_t)row * Dm);
    dst[threadIdx.x] = src[threadIdx.x];
}

// ---------------- layernorm (D=512, 128 threads/row) ----------------
__global__ void ln_kernel(const float* __restrict__ in,
                          const float* __restrict__ g,
                          const float* __restrict__ b,
                          float* __restrict__ out) {
    int row = blockIdx.x;
    int tid = threadIdx.x;
    const float4* x4 = (const float4*)(in + (size_t)row * Dm);
    float4 v = x4[tid];
    float s = v.x + v.y + v.z + v.w;
    float q = v.x*v.x + v.y*v.y + v.z*v.z + v.w*v.w;
    #pragma unroll
    for (int off = 16; off; off >>= 1) {
        s += __shfl_xor_sync(0xffffffffu, s, off);
        q += __shfl_xor_sync(0xffffffffu, q, off);
    }
    __shared__ float ss[4], sq[4];
    int w = tid >> 5;
    if ((tid & 31) == 0) { ss[w] = s; sq[w] = q; }
    __syncthreads();
    s = ss[0] + ss[1] + ss[2] + ss[3];
    q = sq[0] + sq[1] + sq[2] + sq[3];
    float mean = s * (1.0f / Dm);
    float var  = q * (1.0f / Dm) - mean * mean;
    float r = rsqrtf(var + 1e-5f);
    const float4* g4 = (const float4*)g;
    const float4* b4 = (const float4*)b;
    float4 gv = g4[tid], bv = b4[tid], o;
    o.x = (v.x - mean) * r * gv.x + bv.x;
    o.y = (v.y - mean) * r * gv.y + bv.y;
    o.z = (v.z - mean) * r * gv.z + bv.z;
    o.w = (v.w - mean) * r * gv.w + bv.w;
    ((float4*)(out + (size_t)row * Dm))[tid] = o;
}

// ---------------- cp.async helper (zfill when invalid) ----------------
__device__ __forceinline__ void cpa16(void* dst, const void* src, bool valid) {
    unsigned d = (unsigned)__cvta_generic_to_shared(dst);
    int sz = valid ? 16 : 0;
    asm volatile("cp.async.cg.shared.global [%0], [%1], 16, %2;\n"
                 :: "r"(d), "l"(src), "r"(sz));
}
#define CP_COMMIT() asm volatile("cp.async.commit_group;\n" ::)
#define CP_WAIT0()  asm volatile("cp.async.wait_group 0;\n" ::)

// ---------------- tf32 tensor-core GEMM ----------------
// C[M,N] = act(A[M,K] @ B + bias).
//   NT=false: B is [K,N] row-major.   NT=true: B is [N,K] row-major (tied head).
// Requires: M % 128 == 0, K % 16 == 0. N guarded.
// Block tile 128x128x16, 8 warps (2x4), warp tile 64x32, mma m16n8k8.
// ACT: 0 none, 1 tanh, 2 tanh*pi, 3 exact gelu
template<int ACT, bool NT>
__global__ __launch_bounds__(256, 2)
void mma_gemm(const float* __restrict__ A, const float* __restrict__ Bm,
              const float* __restrict__ bias, float* __restrict__ C,
              int M, int N, int K) {
    __shared__ __align__(16) float As[2][128][20];   // pad 4 -> conflict-free frags
    __shared__ __align__(16) float Bs[2][16][136];   // pad 8 -> conflict-free frags
    const int tid = threadIdx.x;
    const int lane = tid & 31;
    const int wid = tid >> 5;
    const int wm = (wid >> 2) * 64;      // warp row offset in tile
    const int wn = (wid & 3) * 32;       // warp col offset in tile
    const int tr = lane >> 2, tc = lane & 3;
    const int row0 = blockIdx.y * 128, col0 = blockIdx.x * 128;

    float acc[4][4][4];
    #pragma unroll
    for (int i = 0; i < 4; i++)
        #pragma unroll
        for (int j = 0; j < 4; j++)
            #pragma unroll
            for (int l = 0; l < 4; l++) acc[i][j][l] = 0.f;

    const int KT = K >> 4;

    // stage loaders
    auto load_stage = [&](int st, int k0) {
        // A: 128 rows x 16 cols -> 512 16B chunks
        #pragma unroll
        for (int i = 0; i < 2; i++) {
            int id = tid + i * 256;
            int r = id >> 2, cc = (id & 3) << 2;
            cpa16(&As[st][r][cc], A + (size_t)(row0 + r) * K + k0 + cc, true);
        }
        if (!NT) {
            #pragma unroll
            for (int i = 0; i < 2; i++) {
                int id = tid + i * 256;
                int r = id >> 5, c4 = (id & 31) << 2;
                bool ok = (col0 + c4) < N;
                const float* src = Bm + (size_t)(k0 + r) * N + (ok ? (col0 + c4) : 0);
                cpa16(&Bs[st][r][c4], src, ok);
            }
        } else {
            #pragma unroll
            for (int i = 0; i < 2; i++) {
                int id = tid + i * 256;
                int n = id >> 2, kc = (id & 3) << 2;
                float4 v = make_float4(0.f, 0.f, 0.f, 0.f);
                if (col0 + n < N)
                    v = *(const float4*)(Bm + (size_t)(col0 + n) * K + k0 + kc);
                Bs[st][kc + 0][n] = v.x; Bs[st][kc + 1][n] = v.y;
                Bs[st][kc + 2][n] = v.z; Bs[st][kc + 3][n] = v.w;
            }
        }
    };

    load_stage(0, 0);
    CP_COMMIT();

    for (int kt = 0; kt < KT; kt++) {
        CP_WAIT0();
        __syncthreads();
        if (kt + 1 < KT) {
            load_stage((kt + 1) & 1, (kt + 1) << 4);
            CP_COMMIT();
        }
        const int st = kt & 1;
        #pragma unroll
        for (int k8 = 0; k8 < 2; k8++) {
            const int kb = k8 << 3;
            unsigned a[4][4], b[4][2];
            #pragma unroll
            for (int mt = 0; mt < 4; mt++) {
                const float* p = &As[st][wm + mt * 16 + tr][kb + tc];
                a[mt][0] = __float_as_uint(p[0]);
                a[mt][1] = __float_as_uint(p[8 * 20]);
                a[mt][2] = __float_as_uint(p[4]);
                a[mt][3] = __float_as_uint(p[8 * 20 + 4]);
            }
            #pragma unroll
            for (int nt = 0; nt < 4; nt++) {
                const float* p = &Bs[st][kb + tc][wn + nt * 8 + tr];
                b[nt][0] = __float_as_uint(p[0]);
                b[nt][1] = __float_as_uint(p[4 * 136]);
            }
            #pragma unroll
            for (int mt = 0; mt < 4; mt++)
                #pragma unroll
                for (int nt = 0; nt < 4; nt++)
                    asm volatile(
                        "mma.sync.aligned.m16n8k8.row.col.f32.tf32.tf32.f32 "
                        "{%0,%1,%2,%3}, {%4,%5,%6,%7}, {%8,%9}, {%0,%1,%2,%3};\n"
                        : "+f"(acc[mt][nt][0]), "+f"(acc[mt][nt][1]),
                          "+f"(acc[mt][nt][2]), "+f"(acc[mt][nt][3])
                        : "r"(a[mt][0]), "r"(a[mt][1]), "r"(a[mt][2]), "r"(a[mt][3]),
                          "r"(b[nt][0]), "r"(b[nt][1]));
        }
    }

    // epilogue
    #pragma unroll
    for (int mt = 0; mt < 4; mt++) {
        int r0 = row0 + wm + mt * 16 + tr;
        #pragma unroll
        for (int nt = 0; nt < 4; nt++) {
            int c0 = col0 + wn + nt * 8 + 2 * tc;
            if (c0 >= N) continue;
            float bcol0 = bias ? bias[c0] : 0.f;
            float bcol1 = bias ? bias[c0 + 1] : 0.f;
            #pragma unroll
            for (int half = 0; half < 2; half++) {
                int r = r0 + half * 8;
                float v0 = acc[mt][nt][half * 2 + 0] + bcol0;
                float v1 = acc[mt][nt][half * 2 + 1] + bcol1;
                if (ACT == 1) { v0 = tanhf(v0); v1 = tanhf(v1); }
                else if (ACT == 2) {
                    v0 = tanhf(v0) * 3.14159274101257324f;
                    v1 = tanhf(v1) * 3.14159274101257324f;
                } else if (ACT == 3) {
                    v0 = 0.5f * v0 * (1.0f + erff(v0 * 0.70710678118654752f));
                    v1 = 0.5f * v1 * (1.0f + erff(v1 * 0.70710678118654752f));
                }
                *(float2*)(C + (size_t)r * N + c0) = make_float2(v0, v1);
            }
        }
    }
}

// ---------------- phase (cos/sin of target phase) ----------------
__global__ void phase_kernel(const float* __restrict__ cp,
                             const float* __restrict__ ps,
                             const float* __restrict__ cs, int layer,
                             float* __restrict__ C, float* __restrict__ S) {
    int idx = blockIdx.x * 256 + threadIdx.x;
    if (idx >= NTOK * Kp) return;
    int k = idx & (Kp - 1);
    int l = (idx >> 5) & (Lseq - 1);
    float freq = (float)exp(-(double)k / (double)Kp * 9.210340371976184); // ln 1e4
    float tp = ps[layer] * ((float)l * freq) + cs[layer] * cp[idx];
    C[idx] = cosf(tp);
    S[idx] = sinf(tp);
}

// ---------------- causal A = (C C^T + S S^T) * inv_norm[l] ----------------
__global__ void build_A_kernel(const float* __restrict__ C, const float* __restrict__ S,
                               float* __restrict__ A) {
    __shared__ float cl[16][33], sl[16][33], ct[16][33], st[16][33];
    int b = blockIdx.z;
    int tid = threadIdx.y * 16 + threadIdx.x;
    int l0 = blockIdx.y * 16, t0 = blockIdx.x * 16;
    const float* Cb = C + (size_t)b * Lseq * Kp;
    const float* Sb = S + (size_t)b * Lseq * Kp;
    for (int i = tid; i < 16 * 32; i += 256) {
        int r = i >> 5, c = i & 31;
        cl[r][c] = Cb[(size_t)(l0 + r) * Kp + c];
        sl[r][c] = Sb[(size_t)(l0 + r) * Kp + c];
        ct[r][c] = Cb[(size_t)(t0 + r) * Kp + c];
        st[r][c] = Sb[(size_t)(t0 + r) * Kp + c];
    }
    __syncthreads();
    int l = l0 + threadIdx.y, t = t0 + threadIdx.x;
    float acc = 0.f;
    #pragma unroll
    for (int k = 0; k < 32; k++)
        acc += cl[threadIdx.y][k] * ct[threadIdx.x][k]
             + sl[threadIdx.y][k] * st[threadIdx.x][k];
    float out = (t <= l) ? acc * rsqrtf((float)((l + 1) * Kp)) : 0.f;
    A[((size_t)b * Lseq + l) * Lseq + t] = out;
}

// ---------------- residual adds ----------------
__global__ void add3_kernel(float* __restrict__ h, const float* __restrict__ x,
                            const float* __restrict__ o) {
    int i = blockIdx.x * 256 + threadIdx.x;
    h[i] += x[i] + o[i];
}
__global__ void add2_kernel(float* __restrict__ h, const float* __restrict__ o) {
    int i = blockIdx.x * 256 + threadIdx.x;
    h[i] += o[i];
}

// ---------------- driver ----------------
extern "C" void kernel_launch(void* const* d_in, const int* in_sizes, int n_in,
                              void* d_out, int out_size) {
    const int*   tokens  = (const int*)  d_in[0];
    const float* embed   = (const float*)d_in[1];
    const float* ln1_g   = (const float*)d_in[2];
    const float* ln1_b   = (const float*)d_in[3];
    const float* cp_w1   = (const float*)d_in[4];
    const float* cp_b1   = (const float*)d_in[5];
    const float* cp_w2   = (const float*)d_in[6];
    const float* cp_b2   = (const float*)d_in[7];
    const float* pscale  = (const float*)d_in[8];
    const float* cscale  = (const float*)d_in[9];
    const float* val_w   = (const float*)d_in[10];
    const float* val_b   = (const float*)d_in[11];
    const float* oln_g   = (const float*)d_in[12];
    const float* oln_b   = (const float*)d_in[13];
    const float* out_w   = (const float*)d_in[14];
    const float* out_b   = (const float*)d_in[15];
    const float* ln2_g   = (const float*)d_in[16];
    const float* ln2_b   = (const float*)d_in[17];
    const float* ffn_w1  = (const float*)d_in[18];
    const float* ffn_b1  = (const float*)d_in[19];
    const float* ffn_w2  = (const float*)d_in[20];
    const float* ffn_b2  = (const float*)d_in[21];
    const float* no_g    = (const float*)d_in[22];
    const float* no_b    = (const float*)d_in[23];
    const float* head_b  = (const float*)d_in[24];
    float* logits = (float*)d_out;

    float *h, *x, *t1, *cp, *Cb, *Sb, *v, *A, *ret, *rln, *o, *mid, *hn;
    cudaGetSymbolAddress((void**)&h,   g_h);
    cudaGetSymbolAddress((void**)&x,   g_x);
    cudaGetSymbolAddress((void**)&t1,  g_t1);
    cudaGetSymbolAddress((void**)&cp,  g_cp);
    cudaGetSymbolAddress((void**)&Cb,  g_C);
    cudaGetSymbolAddress((void**)&Sb,  g_S);
    cudaGetSymbolAddress((void**)&v,   g_v);
    cudaGetSymbolAddress((void**)&A,   g_A);
    cudaGetSymbolAddress((void**)&ret, g_ret);
    cudaGetSymbolAddress((void**)&rln, g_rln);
    cudaGetSymbolAddress((void**)&o,   g_o);
    cudaGetSymbolAddress((void**)&mid, g_mid);
    cudaGetSymbolAddress((void**)&hn,  g_hn);

    gather_kernel<<<NTOK, 128>>>(tokens, embed, h);

    dim3 gD((Dm  + 127) / 128, NTOK / 128);    // 4 x 16
    dim3 gK(1,                 NTOK / 128);    // 1 x 16  (N=32)
    dim3 gF((FFd + 127) / 128, NTOK / 128);    // 16 x 16
    dim3 gR((Dm  + 127) / 128, Lseq / 128);    // 4 x 8 (per batch)

    for (int i = 0; i < NLY; i++) {
        ln_kernel<<<NTOK, 128>>>(h, ln1_g + i * Dm, ln1_b + i * Dm, x);
        mma_gemm<1, false><<<gD, 256>>>(x, cp_w1 + (size_t)i * Dm * Dm,
                                        cp_b1 + i * Dm, t1, NTOK, Dm, Dm);
        mma_gemm<2, false><<<gK, 256>>>(t1, cp_w2 + (size_t)i * Dm * Kp,
                                        cp_b2 + i * Kp, cp, NTOK, Kp, Dm);
        phase_kernel<<<(NTOK * Kp + 255) / 256, 256>>>(cp, pscale, cscale, i, Cb, Sb);
        mma_gemm<0, false><<<gD, 256>>>(x, val_w + (size_t)i * Dm * Dm,
                                        val_b + i * Dm, v, NTOK, Dm, Dm);
        build_A_kernel<<<dim3(Lseq / 16, Lseq / 16, Bsz), dim3(16, 16)>>>(Cb, Sb, A);
        for (int b = 0; b < Bsz; b++)
            mma_gemm<0, false><<<gR, 256>>>(A + (size_t)b * Lseq * Lseq,
                                            v + (size_t)b * Lseq * Dm, (const float*)0,
                                            ret + (size_t)b * Lseq * Dm,
                                            Lseq, Dm, Lseq);
        ln_kernel<<<NTOK, 128>>>(ret, oln_g + i * Dm, oln_b + i * Dm, rln);
        mma_gemm<0, false><<<gD, 256>>>(rln, out_w + (size_t)i * Dm * Dm,
                                        out_b + i * Dm, o, NTOK, Dm, Dm);
        add3_kernel<<<(NTOK * Dm) / 256, 256>>>(h, x, o);
        ln_kernel<<<NTOK, 128>>>(h, ln2_g + i * Dm, ln2_b + i * Dm, x); // x := y
        mma_gemm<3, false><<<gF, 256>>>(x, ffn_w1 + (size_t)i * Dm * FFd,
                                        ffn_b1 + i * FFd, mid, NTOK, FFd, Dm);
        mma_gemm<0, false><<<gD, 256>>>(mid, ffn_w2 + (size_t)i * FFd * Dm,
                                        ffn_b2 + i * Dm, o, NTOK, Dm, FFd);
        add2_kernel<<<(NTOK * Dm) / 256, 256>>>(h, o);
    }

    ln_kernel<<<NTOK, 128>>>(h, no_g, no_b, hn);
    dim3 gH(Vocab / 128, NTOK / 128);          // 250 x 16
    mma_gemm<0, true><<<gH, 256>>>(hn, embed, head_b, logits, NTOK, Vocab, Dm);
}

// round 3
// speedup vs baseline: 2.3897x; 1.0320x over previous
#include <cuda_runtime.h>
#include <math.h>

#define Bsz   2
#define Lseq  1024
#define Dm    512
#define Kp    32
#define NLY   4
#define FFd   2048
#define Vocab 32000
#define NTOK  (Bsz*Lseq)   // 2048

// ---------------- scratch (no allocs allowed) ----------------
__device__ float g_h  [NTOK*Dm];
__device__ float g_x  [NTOK*Dm];
__device__ float g_t1 [NTOK*Dm];
__device__ float g_C  [NTOK*Kp];
__device__ float g_S  [NTOK*Kp];
__device__ float g_v  [NTOK*Dm];
__device__ float g_A  [Bsz*Lseq*Lseq];
__device__ float g_ret[NTOK*Dm];
__device__ float g_rln[NTOK*Dm];
__device__ float g_o  [NTOK*Dm];
__device__ float g_mid[NTOK*FFd];

// ---------------- embed gather ----------------
__global__ void gather_kernel(const int* __restrict__ tokens,
                              const float* __restrict__ embed,
                              float* __restrict__ h) {
    int row = blockIdx.x;
    int tok = tokens[row];
    const float4* src = (const float4*)(embed + (size_t)tok * Dm);
    float4* dst = (float4*)(h + (size_t)row * Dm);
    dst[threadIdx.x] = src[threadIdx.x];
}

// ---------------- layernorm core ----------------
__device__ __forceinline__ void ln_row(float4 v, const float* g, const float* b,
                                       int tid, float* out_row) {
    float s = v.x + v.y + v.z + v.w;
    float q = v.x*v.x + v.y*v.y + v.z*v.z + v.w*v.w;
    #pragma unroll
    for (int off = 16; off; off >>= 1) {
        s += __shfl_xor_sync(0xffffffffu, s, off);
        q += __shfl_xor_sync(0xffffffffu, q, off);
    }
    __shared__ float ss[4], sq[4];
    int w = tid >> 5;
    if ((tid & 31) == 0) { ss[w] = s; sq[w] = q; }
    __syncthreads();
    s = ss[0] + ss[1] + ss[2] + ss[3];
    q = sq[0] + sq[1] + sq[2] + sq[3];
    float mean = s * (1.0f / Dm);
    float var  = q * (1.0f / Dm) - mean * mean;
    float r = rsqrtf(var + 1e-5f);
    float4 gv = ((const float4*)g)[tid], bv = ((const float4*)b)[tid], o;
    o.x = (v.x - mean) * r * gv.x + bv.x;
    o.y = (v.y - mean) * r * gv.y + bv.y;
    o.z = (v.z - mean) * r * gv.z + bv.z;
    o.w = (v.w - mean) * r * gv.w + bv.w;
    ((float4*)out_row)[tid] = o;
}

__global__ void ln_kernel(const float* __restrict__ in,
                          const float* __restrict__ g,
                          const float* __restrict__ b,
                          float* __restrict__ out) {
    int row = blockIdx.x, tid = threadIdx.x;
    float4 v = ((const float4*)(in + (size_t)row * Dm))[tid];
    ln_row(v, g, b, tid, out + (size_t)row * Dm);
}

// fused residual-add + layernorm.  THREE: h += x + o, else h += o.  out = LN(h)
template<bool THREE>
__global__ void add_ln_kernel(float* __restrict__ h, const float* __restrict__ x,
                              const float* __restrict__ o,
                              const float* __restrict__ g, const float* __restrict__ b,
                              float* __restrict__ out) {
    int row = blockIdx.x, tid = threadIdx.x;
    size_t base = (size_t)row * Dm;
    float4 hv = ((const float4*)(h + base))[tid];
    float4 ov = ((const float4*)(o + base))[tid];
    if (THREE) {
        float4 xv = ((const float4*)(x + base))[tid];
        hv.x += xv.x + ov.x; hv.y += xv.y + ov.y;
        hv.z += xv.z + ov.z; hv.w += xv.w + ov.w;
    } else {
        hv.x += ov.x; hv.y += ov.y; hv.z += ov.z; hv.w += ov.w;
    }
    ((float4*)(h + base))[tid] = hv;
    ln_row(hv, g, b, tid, out + base);
}

// ---------------- cp.async helpers ----------------
__device__ __forceinline__ void cpa16(void* dst, const void* src, bool valid) {
    unsigned d = (unsigned)__cvta_generic_to_shared(dst);
    int sz = valid ? 16 : 0;
    asm volatile("cp.async.cg.shared.global [%0], [%1], 16, %2;\n"
                 :: "r"(d), "l"(src), "r"(sz));
}
#define CP_COMMIT() asm volatile("cp.async.commit_group;\n" ::)
#define CP_WAIT0()  asm volatile("cp.async.wait_group 0;\n" ::)

__device__ __forceinline__ unsigned rna(float x) {
    unsigned r;
    asm("cvt.rna.tf32.f32 %0, %1;\n" : "=r"(r) : "f"(x));
    return r;
}

// ---------------- tf32 tensor-core GEMM ----------------
// C[M,N] = act(A[M,K] @ B + bias).  NT=false: B[K,N] row-major. NT=true: B[N,K].
// MT: 4 -> 128-row block tile (warp 64x32), 2 -> 64-row block tile (warp 32x32).
// ACT: 0 none, 1 tanh, 3 exact gelu, 4 phase-epilogue (writes cos/sin).
template<int ACT, bool NT, int MT>
__global__ __launch_bounds__(256, MT == 4 ? 2 : 3)
void mma_gemm(const float* __restrict__ A, const float* __restrict__ Bm,
              const float* __restrict__ bias, float* __restrict__ C,
              int M, int N, int K,
              size_t sA, size_t sB, size_t sC,
              float* __restrict__ S_out, const float* __restrict__ psc,
              const float* __restrict__ csc, int layer) {
    const int BM = MT * 32;
    __shared__ __align__(16) float As[2][MT * 32][20];
    __shared__ __align__(16) float Bs[2][16][136];
    A += (size_t)blockIdx.z * sA;
    Bm += (size_t)blockIdx.z * sB;
    C += (size_t)blockIdx.z * sC;

    const int tid = threadIdx.x;
    const int lane = tid & 31;
    const int wid = tid >> 5;
    const int wm = (wid >> 2) * (MT * 16);
    const int wn = (wid & 3) * 32;
    const int tr = lane >> 2, tc = lane & 3;
    const int row0 = blockIdx.y * BM, col0 = blockIdx.x * 128;

    float acc[MT][4][4];
    #pragma unroll
    for (int i = 0; i < MT; i++)
        #pragma unroll
        for (int j = 0; j < 4; j++)
            #pragma unroll
            for (int l = 0; l < 4; l++) acc[i][j][l] = 0.f;

    const int KT = K >> 4;

    auto load_stage = [&](int st, int k0) {
        #pragma unroll
        for (int i = 0; i < MT / 2; i++) {
            int id = tid + i * 256;
            int r = id >> 2, cc = (id & 3) << 2;
            cpa16(&As[st][r][cc], A + (size_t)(row0 + r) * K + k0 + cc, true);
        }
        if (!NT) {
            #pragma unroll
            for (int i = 0; i < 2; i++) {
                int id = tid + i * 256;
                int r = id >> 5, c4 = (id & 31) << 2;
                bool ok = (col0 + c4) < N;
                const float* src = Bm + (size_t)(k0 + r) * N + (ok ? (col0 + c4) : 0);
                cpa16(&Bs[st][r][c4], src, ok);
            }
        } else {
            #pragma unroll
            for (int i = 0; i < 2; i++) {
                int id = tid + i * 256;
                int n = id >> 2, kc = (id & 3) << 2;
                float4 v = make_float4(0.f, 0.f, 0.f, 0.f);
                if (col0 + n < N)
                    v = *(const float4*)(Bm + (size_t)(col0 + n) * K + k0 + kc);
                Bs[st][kc + 0][n] = v.x; Bs[st][kc + 1][n] = v.y;
                Bs[st][kc + 2][n] = v.z; Bs[st][kc + 3][n] = v.w;
            }
        }
    };

    load_stage(0, 0);
    CP_COMMIT();

    for (int kt = 0; kt < KT; kt++) {
        CP_WAIT0();
        __syncthreads();
        if (kt + 1 < KT) {
            load_stage((kt + 1) & 1, (kt + 1) << 4);
            CP_COMMIT();
        }
        const int st = kt & 1;
        #pragma unroll
        for (int k8 = 0; k8 < 2; k8++) {
            const int kb = k8 << 3;
            unsigned a[MT][4], b[4][2];
            #pragma unroll
            for (int mt = 0; mt < MT; mt++) {
                const float* p = &As[st][wm + mt * 16 + tr][kb + tc];
                a[mt][0] = rna(p[0]);
                a[mt][1] = rna(p[8 * 20]);
                a[mt][2] = rna(p[4]);
                a[mt][3] = rna(p[8 * 20 + 4]);
            }
            #pragma unroll
            for (int nt = 0; nt < 4; nt++) {
                const float* p = &Bs[st][kb + tc][wn + nt * 8 + tr];
                b[nt][0] = rna(p[0]);
                b[nt][1] = rna(p[4 * 136]);
            }
            #pragma unroll
            for (int mt = 0; mt < MT; mt++)
                #pragma unroll
                for (int nt = 0; nt < 4; nt++)
                    asm volatile(
                        "mma.sync.aligned.m16n8k8.row.col.f32.tf32.tf32.f32 "
                        "{%0,%1,%2,%3}, {%4,%5,%6,%7}, {%8,%9}, {%0,%1,%2,%3};\n"
                        : "+f"(acc[mt][nt][0]), "+f"(acc[mt][nt][1]),
                          "+f"(acc[mt][nt][2]), "+f"(acc[mt][nt][3])
                        : "r"(a[mt][0]), "r"(a[mt][1]), "r"(a[mt][2]), "r"(a[mt][3]),
                          "r"(b[nt][0]), "r"(b[nt][1]));
        }
    }

    // epilogue
    #pragma unroll
    for (int mt = 0; mt < MT; mt++) {
        int r0 = row0 + wm + mt * 16 + tr;
        #pragma unroll
        for (int nt = 0; nt < 4; nt++) {
            int c0 = col0 + wn + nt * 8 + 2 * tc;
            if (c0 >= N) continue;
            float bcol0 = bias ? bias[c0] : 0.f;
            float bcol1 = bias ? bias[c0 + 1] : 0.f;
            #pragma unroll
            for (int half = 0; half < 2; half++) {
                int r = r0 + half * 8;
                float v0 = acc[mt][nt][half * 2 + 0] + bcol0;
                float v1 = acc[mt][nt][half * 2 + 1] + bcol1;
                if (ACT == 1) { v0 = tanhf(v0); v1 = tanhf(v1); }
                else if (ACT == 3) {
                    v0 = 0.5f * v0 * (1.0f + erff(v0 * 0.70710678118654752f));
                    v1 = 0.5f * v1 * (1.0f + erff(v1 * 0.70710678118654752f));
                }
                if (ACT == 4) {
                    // tp = ps*pos_phase + cs*(tanh(acc)*pi); write cos,sin
                    int l = r & (Lseq - 1);
                    float ps = psc[layer], cs = csc[layer];
                    #pragma unroll
                    for (int cc = 0; cc < 2; cc++) {
                        int c = c0 + cc;
                        float val = tanhf(cc ? v1 : v0) * 3.14159274101257324f;
                        float fr = (float)exp(-(double)c * (9.210340371976184 / 32.0));
                        float tp = ps * ((float)l * fr) + cs * val;
                        C[(size_t)r * N + c] = cosf(tp);
                        S_out[(size_t)r * N + c] = sinf(tp);
                    }
                } else {
                    *(float2*)(C + (size_t)r * N + c0) = make_float2(v0, v1);
                }
            }
        }
    }
}

// ---------------- causal A = (C C^T + S S^T) * inv_norm[l] ----------------
__global__ void build_A_kernel(const float* __restrict__ C, const float* __restrict__ S,
                               float* __restrict__ A) {
    __shared__ float cl[16][33], sl[16][33], ct[16][33], st[16][33];
    int b = blockIdx.z;
    int tid = threadIdx.y * 16 + threadIdx.x;
    int l0 = blockIdx.y * 16, t0 = blockIdx.x * 16;
    const float* Cb = C + (size_t)b * Lseq * Kp;
    const float* Sb = S + (size_t)b * Lseq * Kp;
    for (int i = tid; i < 16 * 32; i += 256) {
        int r = i >> 5, c = i & 31;
        cl[r][c] = Cb[(size_t)(l0 + r) * Kp + c];
        sl[r][c] = Sb[(size_t)(l0 + r) * Kp + c];
        ct[r][c] = Cb[(size_t)(t0 + r) * Kp + c];
        st[r][c] = Sb[(size_t)(t0 + r) * Kp + c];
    }
    __syncthreads();
    int l = l0 + threadIdx.y, t = t0 + threadIdx.x;
    float acc = 0.f;
    #pragma unroll
    for (int k = 0; k < 32; k++)
        acc += cl[threadIdx.y][k] * ct[threadIdx.x][k]
             + sl[threadIdx.y][k] * st[threadIdx.x][k];
    float out = (t <= l) ? acc * rsqrtf((float)((l + 1) * Kp)) : 0.f;
    A[((size_t)b * Lseq + l) * Lseq + t] = out;
}

// ---------------- driver ----------------
extern "C" void kernel_launch(void* const* d_in, const int* in_sizes, int n_in,
                              void* d_out, int out_size) {
    const int*   tokens  = (const int*)  d_in[0];
    const float* embed   = (const float*)d_in[1];
    const float* ln1_g   = (const float*)d_in[2];
    const float* ln1_b   = (const float*)d_in[3];
    const float* cp_w1   = (const float*)d_in[4];
    const float* cp_b1   = (const float*)d_in[5];
    const float* cp_w2   = (const float*)d_in[6];
    const float* cp_b2   = (const float*)d_in[7];
    const float* pscale  = (const float*)d_in[8];
    const float* cscale  = (const float*)d_in[9];
    const float* val_w   = (const float*)d_in[10];
    const float* val_b   = (const float*)d_in[11];
    const float* oln_g   = (const float*)d_in[12];
    const float* oln_b   = (const float*)d_in[13];
    const float* out_w   = (const float*)d_in[14];
    const float* out_b   = (const float*)d_in[15];
    const float* ln2_g   = (const float*)d_in[16];
    const float* ln2_b   = (const float*)d_in[17];
    const float* ffn_w1  = (const float*)d_in[18];
    const float* ffn_b1  = (const float*)d_in[19];
    const float* ffn_w2  = (const float*)d_in[20];
    const float* ffn_b2  = (const float*)d_in[21];
    const float* no_g    = (const float*)d_in[22];
    const float* no_b    = (const float*)d_in[23];
    const float* head_b  = (const float*)d_in[24];
    float* logits = (float*)d_out;

    float *h, *x, *t1, *Cb, *Sb, *v, *A, *ret, *rln, *o, *mid;
    cudaGetSymbolAddress((void**)&h,   g_h);
    cudaGetSymbolAddress((void**)&x,   g_x);
    cudaGetSymbolAddress((void**)&t1,  g_t1);
    cudaGetSymbolAddress((void**)&Cb,  g_C);
    cudaGetSymbolAddress((void**)&Sb,  g_S);
    cudaGetSymbolAddress((void**)&v,   g_v);
    cudaGetSymbolAddress((void**)&A,   g_A);
    cudaGetSymbolAddress((void**)&ret, g_ret);
    cudaGetSymbolAddress((void**)&rln, g_rln);
    cudaGetSymbolAddress((void**)&o,   g_o);
    cudaGetSymbolAddress((void**)&mid, g_mid);

    gather_kernel<<<NTOK, 128>>>(tokens, embed, h);
    ln_kernel<<<NTOK, 128>>>(h, ln1_g, ln1_b, x);

    dim3 gD((Dm  + 127) / 128, NTOK / 64);        // 4 x 32
    dim3 gK(1,                 NTOK / 64);        // 1 x 32 (N=32)
    dim3 gF((FFd + 127) / 128, NTOK / 64);        // 16 x 32
    dim3 gAv((Dm + 127) / 128, Lseq / 64, Bsz);   // 4 x 16 x 2

    for (int i = 0; i < NLY; i++) {
        mma_gemm<1, false, 2><<<gD, 256>>>(x, cp_w1 + (size_t)i * Dm * Dm,
            cp_b1 + i * Dm, t1, NTOK, Dm, Dm, 0, 0, 0, nullptr, nullptr, nullptr, 0);
        mma_gemm<4, false, 2><<<gK, 256>>>(t1, cp_w2 + (size_t)i * Dm * Kp,
            cp_b2 + i * Kp, Cb, NTOK, Kp, Dm, 0, 0, 0, Sb, pscale, cscale, i);
        mma_gemm<0, false, 2><<<gD, 256>>>(x, val_w + (size_t)i * Dm * Dm,
            val_b + i * Dm, v, NTOK, Dm, Dm, 0, 0, 0, nullptr, nullptr, nullptr, 0);
        build_A_kernel<<<dim3(Lseq / 16, Lseq / 16, Bsz), dim3(16, 16)>>>(Cb, Sb, A);
        mma_gemm<0, false, 2><<<gAv, 256>>>(A, v, nullptr, ret,
            Lseq, Dm, Lseq,
            (size_t)Lseq * Lseq, (size_t)Lseq * Dm, (size_t)Lseq * Dm,
            nullptr, nullptr, nullptr, 0);
        ln_kernel<<<NTOK, 128>>>(ret, oln_g + i * Dm, oln_b + i * Dm, rln);
        mma_gemm<0, false, 2><<<gD, 256>>>(rln, out_w + (size_t)i * Dm * Dm,
            out_b + i * Dm, o, NTOK, Dm, Dm, 0, 0, 0, nullptr, nullptr, nullptr, 0);
        add_ln_kernel<true><<<NTOK, 128>>>(h, x, o, ln2_g + i * Dm, ln2_b + i * Dm, x);
        mma_gemm<3, false, 2><<<gF, 256>>>(x, ffn_w1 + (size_t)i * Dm * FFd,
            ffn_b1 + i * FFd, mid, NTOK, FFd, Dm, 0, 0, 0, nullptr, nullptr, nullptr, 0);
        mma_gemm<0, false, 2><<<gD, 256>>>(mid, ffn_w2 + (size_t)i * FFd * Dm,
            ffn_b2 + i * Dm, o, NTOK, Dm, FFd, 0, 0, 0, nullptr, nullptr, nullptr, 0);
        const float* ng = (i < NLY - 1) ? (ln1_g + (i + 1) * Dm) : no_g;
        const float* nb = (i < NLY - 1) ? (ln1_b + (i + 1) * Dm) : no_b;
        add_ln_kernel<false><<<NTOK, 128>>>(h, nullptr, o, ng, nb, x);
    }

    dim3 gH(Vocab / 128, NTOK / 128);             // 250 x 16
    mma_gemm<0, true, 4><<<gH, 256>>>(x, embed, head_b, logits,
        NTOK, Vocab, Dm, 0, 0, 0, nullptr, nullptr, nullptr, 0);
}

// round 4
// speedup vs baseline: 3.0499x; 1.2762x over previous
#include <cuda_runtime.h>
#include <math.h>

#define Bsz   2
#define Lseq  1024
#define Dm    512
#define Kp    32
#define NLY   4
#define FFd   2048
#define Vocab 32000
#define NTOK  (Bsz*Lseq)   // 2048

// ---------------- scratch (no allocs allowed) ----------------
__device__ float g_h  [NTOK*Dm];
__device__ float g_x  [NTOK*Dm];
__device__ float g_t1 [NTOK*Dm];
__device__ float g_C  [NTOK*Kp];
__device__ float g_S  [NTOK*Kp];
__device__ float g_v  [NTOK*Dm];
__device__ float g_A  [Bsz*Lseq*Lseq];
__device__ float g_ret[NTOK*Dm];
__device__ float g_rln[NTOK*Dm];
__device__ float g_o  [NTOK*Dm];
__device__ float g_mid[NTOK*FFd];

// ---------------- embed gather ----------------
__global__ void gather_kernel(const int* __restrict__ tokens,
                              const float* __restrict__ embed,
                              float* __restrict__ h) {
    int row = blockIdx.x;
    int tok = tokens[row];
    const float4* src = (const float4*)(embed + (size_t)tok * Dm);
    float4* dst = (float4*)(h + (size_t)row * Dm);
    dst[threadIdx.x] = src[threadIdx.x];
}

// ---------------- layernorm core ----------------
__device__ __forceinline__ void ln_row(float4 v, const float* g, const float* b,
                                       int tid, float* out_row) {
    float s = v.x + v.y + v.z + v.w;
    float q = v.x*v.x + v.y*v.y + v.z*v.z + v.w*v.w;
    #pragma unroll
    for (int off = 16; off; off >>= 1) {
        s += __shfl_xor_sync(0xffffffffu, s, off);
        q += __shfl_xor_sync(0xffffffffu, q, off);
    }
    __shared__ float ss[4], sq[4];
    int w = tid >> 5;
    if ((tid & 31) == 0) { ss[w] = s; sq[w] = q; }
    __syncthreads();
    s = ss[0] + ss[1] + ss[2] + ss[3];
    q = sq[0] + sq[1] + sq[2] + sq[3];
    float mean = s * (1.0f / Dm);
    float var  = q * (1.0f / Dm) - mean * mean;
    float r = rsqrtf(var + 1e-5f);
    float4 gv = ((const float4*)g)[tid], bv = ((const float4*)b)[tid], o;
    o.x = (v.x - mean) * r * gv.x + bv.x;
    o.y = (v.y - mean) * r * gv.y + bv.y;
    o.z = (v.z - mean) * r * gv.z + bv.z;
    o.w = (v.w - mean) * r * gv.w + bv.w;
    ((float4*)out_row)[tid] = o;
}

__global__ void ln_kernel(const float* __restrict__ in,
                          const float* __restrict__ g,
                          const float* __restrict__ b,
                          float* __restrict__ out) {
    int row = blockIdx.x, tid = threadIdx.x;
    float4 v = ((const float4*)(in + (size_t)row * Dm))[tid];
    ln_row(v, g, b, tid, out + (size_t)row * Dm);
}

// fused residual-add + layernorm.  THREE: h += x + o, else h += o.  out = LN(h)
template<bool THREE>
__global__ void add_ln_kernel(float* __restrict__ h, const float* __restrict__ x,
                              const float* __restrict__ o,
                              const float* __restrict__ g, const float* __restrict__ b,
                              float* __restrict__ out) {
    int row = blockIdx.x, tid = threadIdx.x;
    size_t base = (size_t)row * Dm;
    float4 hv = ((const float4*)(h + base))[tid];
    float4 ov = ((const float4*)(o + base))[tid];
    if (THREE) {
        float4 xv = ((const float4*)(x + base))[tid];
        hv.x += xv.x + ov.x; hv.y += xv.y + ov.y;
        hv.z += xv.z + ov.z; hv.w += xv.w + ov.w;
    } else {
        hv.x += ov.x; hv.y += ov.y; hv.z += ov.z; hv.w += ov.w;
    }
    ((float4*)(h + base))[tid] = hv;
    ln_row(hv, g, b, tid, out + base);
}

// ---------------- cp.async helpers ----------------
__device__ __forceinline__ void cpa16(void* dst, const void* src, bool valid) {
    unsigned d = (unsigned)__cvta_generic_to_shared(dst);
    int sz = valid ? 16 : 0;
    asm volatile("cp.async.cg.shared.global [%0], [%1], 16, %2;\n"
                 :: "r"(d), "l"(src), "r"(sz));
}
#define CP_COMMIT() asm volatile("cp.async.commit_group;\n" ::)
#define CP_WAIT1()  asm volatile("cp.async.wait_group 1;\n" ::)

__device__ __forceinline__ unsigned rna(float x) {
    unsigned r;
    asm("cvt.rna.tf32.f32 %0, %1;\n" : "=r"(r) : "f"(x));
    return r;
}

// ---------------- tf32 tensor-core GEMM, 3-stage cp.async pipeline ----------
// C[M,N] = act(A[M,K] @ B + bias).  NT=false: B[K,N] row-major. NT=true: B[N,K].
// MT: 4 -> 128-row tile (warp 64x32), 2 -> 64-row tile (warp 32x32).
// ACT: 0 none, 1 tanh, 3 exact gelu, 4 phase-epilogue (writes cos/sin),
//      5 dual-op (z=0: tanh -> C; z=1: none -> C2, weights Bm2/bias2).
// CAUSAL: A@v with K clamped to row0+BM (A upper triangle is zero).
template<int ACT, bool NT, int MT, bool CAUSAL>
__global__ __launch_bounds__(256, MT == 4 ? 2 : 3)
void mma_gemm(const float* __restrict__ A, const float* __restrict__ Bm,
              const float* __restrict__ bias, float* __restrict__ C,
              int M, int N, int K,
              size_t sA, size_t sB, size_t sC,
              float* __restrict__ S_out, const float* __restrict__ psc,
              const float* __restrict__ csc, int layer,
              const float* __restrict__ Bm2, const float* __restrict__ bias2,
              float* __restrict__ C2) {
    const int BM = MT * 32;
    __shared__ __align__(16) float As[3][MT * 32][20];
    __shared__ __align__(16) float Bs[NT ? 1 : 3][16][136];   // [k][n]
    __shared__ __align__(16) float Bs2[NT ? 3 : 1][128][20];  // [n][k]

    A  += (size_t)blockIdx.z * sA;
    Bm += (size_t)blockIdx.z * sB;
    C  += (size_t)blockIdx.z * sC;
    if (ACT == 5 && blockIdx.z == 1) { Bm = Bm2; bias = bias2; C = C2; }

    const int tid = threadIdx.x;
    const int lane = tid & 31;
    const int wid = tid >> 5;
    const int wm = (wid >> 2) * (MT * 16);
    const int wn = (wid & 3) * 32;
    const int tr = lane >> 2, tc = lane & 3;
    const int row0 = blockIdx.y * BM, col0 = blockIdx.x * 128;
    const bool wact = (col0 + wn) < N;    // warp has valid columns

    float acc[MT][4][4];
    #pragma unroll
    for (int i = 0; i < MT; i++)
        #pragma unroll
        for (int j = 0; j < 4; j++)
            #pragma unroll
            for (int l = 0; l < 4; l++) acc[i][j][l] = 0.f;

    int KT = K >> 4;
    if (CAUSAL) { int kc = (row0 + BM) >> 4; KT = kc < KT ? kc : KT; }

    auto load_stage = [&](int st, int k0) {
        #pragma unroll
        for (int i = 0; i < MT / 2; i++) {
            int id = tid + i * 256;
            int r = id >> 2, cc = (id & 3) << 2;
            cpa16(&As[st][r][cc], A + (size_t)(row0 + r) * K + k0 + cc, true);
        }
        if (!NT) {
            #pragma unroll
            for (int i = 0; i < 2; i++) {
                int id = tid + i * 256;
                int r = id >> 5, c4 = (id & 31) << 2;
                bool ok = (col0 + c4) < N;
                const float* src = Bm + (size_t)(k0 + r) * N + (ok ? (col0 + c4) : 0);
                cpa16(&Bs[st][r][c4], src, ok);
            }
        } else {
            #pragma unroll
            for (int i = 0; i < 2; i++) {
                int id = tid + i * 256;
                int n = id >> 2, kc = (id & 3) << 2;
                bool ok = (col0 + n) < N;
                const float* src = Bm + (size_t)(col0 + (ok ? n : 0)) * K + k0 + kc;
                cpa16(&Bs2[st][n][kc], src, ok);
            }
        }
    };

    load_stage(0, 0);
    CP_COMMIT();
    if (KT > 1) load_stage(1, 16);
    CP_COMMIT();

    for (int kt = 0; kt < KT; kt++) {
        CP_WAIT1();
        __syncthreads();
        if (kt + 2 < KT) load_stage((kt + 2) % 3, (kt + 2) << 4);
        CP_COMMIT();
        const int st = kt % 3;
        if (wact) {
            #pragma unroll
            for (int k8 = 0; k8 < 2; k8++) {
                const int kb = k8 << 3;
                unsigned a[MT][4], b[4][2];
                #pragma unroll
                for (int mt = 0; mt < MT; mt++) {
                    const float* p = &As[st][wm + mt * 16 + tr][kb + tc];
                    a[mt][0] = rna(p[0]);
                    a[mt][1] = rna(p[8 * 20]);
                    a[mt][2] = rna(p[4]);
                    a[mt][3] = rna(p[8 * 20 + 4]);
                }
                #pragma unroll
                for (int nt = 0; nt < 4; nt++) {
                    if (!NT) {
                        const float* p = &Bs[st][kb + tc][wn + nt * 8 + tr];
                        b[nt][0] = rna(p[0]);
                        b[nt][1] = rna(p[4 * 136]);
                    } else {
                        const float* p = &Bs2[st][wn + nt * 8 + tr][kb + tc];
                        b[nt][0] = rna(p[0]);
                        b[nt][1] = rna(p[4]);
                    }
                }
                #pragma unroll
                for (int mt = 0; mt < MT; mt++)
                    #pragma unroll
                    for (int nt = 0; nt < 4; nt++)
                        asm volatile(
                            "mma.sync.aligned.m16n8k8.row.col.f32.tf32.tf32.f32 "
                            "{%0,%1,%2,%3}, {%4,%5,%6,%7}, {%8,%9}, {%0,%1,%2,%3};\n"
                            : "+f"(acc[mt][nt][0]), "+f"(acc[mt][nt][1]),
                              "+f"(acc[mt][nt][2]), "+f"(acc[mt][nt][3])
                            : "r"(a[mt][0]), "r"(a[mt][1]), "r"(a[mt][2]), "r"(a[mt][3]),
                              "r"(b[nt][0]), "r"(b[nt][1]));
            }
        }
    }

    if (!wact) return;
    // epilogue
    #pragma unroll
    for (int mt = 0; mt < MT; mt++) {
        int r0 = row0 + wm + mt * 16 + tr;
        #pragma unroll
        for (int nt = 0; nt < 4; nt++) {
            int c0 = col0 + wn + nt * 8 + 2 * tc;
            if (c0 >= N) continue;
            float bcol0 = bias ? bias[c0] : 0.f;
            float bcol1 = bias ? bias[c0 + 1] : 0.f;
            #pragma unroll
            for (int half = 0; half < 2; half++) {
                int r = r0 + half * 8;
                float v0 = acc[mt][nt][half * 2 + 0] + bcol0;
                float v1 = acc[mt][nt][half * 2 + 1] + bcol1;
                if (ACT == 1) { v0 = tanhf(v0); v1 = tanhf(v1); }
                else if (ACT == 3) {
                    v0 = 0.5f * v0 * (1.0f + erff(v0 * 0.70710678118654752f));
                    v1 = 0.5f * v1 * (1.0f + erff(v1 * 0.70710678118654752f));
                } else if (ACT == 5) {
                    if (blockIdx.z == 0) { v0 = tanhf(v0); v1 = tanhf(v1); }
                }
                if (ACT == 4) {
                    // tp = ps*pos_phase + cs*(tanh(acc)*pi); write cos,sin
                    int l = r & (Lseq - 1);
                    float ps = psc[layer], cs = csc[layer];
                    float fl = (float)l;
                    #pragma unroll
                    for (int cc = 0; cc < 2; cc++) {
                        int c = c0 + cc;
                        float val = tanhf(cc ? v1 : v0) * 3.14159274101257324f;
                        float fr = expf((float)c * (-9.210340371976184f / 32.0f));
                        float tp = ps * (fl * fr) + cs * val;
                        float sv, cv;
                        sincosf(tp, &sv, &cv);
                        C[(size_t)r * N + c] = cv;
                        S_out[(size_t)r * N + c] = sv;
                    }
                } else {
                    *(float2*)(C + (size_t)r * N + c0) = make_float2(v0, v1);
                }
            }
        }
    }
}

// ---------------- causal A = (C C^T + S S^T) * inv_norm[l] ----------------
__global__ void build_A_kernel(const float* __restrict__ C, const float* __restrict__ S,
                               float* __restrict__ A) {
    __shared__ float cl[16][33], sl[16][33], ct[16][33], st[16][33];
    int b = blockIdx.z;
    int tid = threadIdx.y * 16 + threadIdx.x;
    int l0 = blockIdx.y * 16, t0 = blockIdx.x * 16;
    const float* Cb = C + (size_t)b * Lseq * Kp;
    const float* Sb = S + (size_t)b * Lseq * Kp;
    for (int i = tid; i < 16 * 32; i += 256) {
        int r = i >> 5, c = i & 31;
        cl[r][c] = Cb[(size_t)(l0 + r) * Kp + c];
        sl[r][c] = Sb[(size_t)(l0 + r) * Kp + c];
        ct[r][c] = Cb[(size_t)(t0 + r) * Kp + c];
        st[r][c] = Sb[(size_t)(t0 + r) * Kp + c];
    }
    __syncthreads();
    int l = l0 + threadIdx.y, t = t0 + threadIdx.x;
    float acc = 0.f;
    #pragma unroll
    for (int k = 0; k < 32; k++)
        acc += cl[threadIdx.y][k] * ct[threadIdx.x][k]
             + sl[threadIdx.y][k] * st[threadIdx.x][k];
    float out = (t <= l) ? acc * rsqrtf((float)((l + 1) * Kp)) : 0.f;
    A[((size_t)b * Lseq + l) * Lseq + t] = out;
}

// ---------------- driver ----------------
extern "C" void kernel_launch(void* const* d_in, const int* in_sizes, int n_in,
                              void* d_out, int out_size) {
    const int*   tokens  = (const int*)  d_in[0];
    const float* embed   = (const float*)d_in[1];
    const float* ln1_g   = (const float*)d_in[2];
    const float* ln1_b   = (const float*)d_in[3];
    const float* cp_w1   = (const float*)d_in[4];
    const float* cp_b1   = (const float*)d_in[5];
    const float* cp_w2   = (const float*)d_in[6];
    const float* cp_b2   = (const float*)d_in[7];
    const float* pscale  = (const float*)d_in[8];
    const float* cscale  = (const float*)d_in[9];
    const float* val_w   = (const float*)d_in[10];
    const float* val_b   = (const float*)d_in[11];
    const float* oln_g   = (const float*)d_in[12];
    const float* oln_b   = (const float*)d_in[13];
    const float* out_w   = (const float*)d_in[14];
    const float* out_b   = (const float*)d_in[15];
    const float* ln2_g   = (const float*)d_in[16];
    const float* ln2_b   = (const float*)d_in[17];
    const float* ffn_w1  = (const float*)d_in[18];
    const float* ffn_b1  = (const float*)d_in[19];
    const float* ffn_w2  = (const float*)d_in[20];
    const float* ffn_b2  = (const float*)d_in[21];
    const float* no_g    = (const float*)d_in[22];
    const float* no_b    = (const float*)d_in[23];
    const float* head_b  = (const float*)d_in[24];
    float* logits = (float*)d_out;

    float *h, *x, *t1, *Cb, *Sb, *v, *A, *ret, *rln, *o, *mid;
    cudaGetSymbolAddress((void**)&h,   g_h);
    cudaGetSymbolAddress((void**)&x,   g_x);
    cudaGetSymbolAddress((void**)&t1,  g_t1);
    cudaGetSymbolAddress((void**)&Cb,  g_C);
    cudaGetSymbolAddress((void**)&Sb,  g_S);
    cudaGetSymbolAddress((void**)&v,   g_v);
    cudaGetSymbolAddress((void**)&A,   g_A);
    cudaGetSymbolAddress((void**)&ret, g_ret);
    cudaGetSymbolAddress((void**)&rln, g_rln);
    cudaGetSymbolAddress((void**)&o,   g_o);
    cudaGetSymbolAddress((void**)&mid, g_mid);

    gather_kernel<<<NTOK, 128>>>(tokens, embed, h);
    ln_kernel<<<NTOK, 128>>>(h, ln1_g, ln1_b, x);

    dim3 gDual((Dm + 127) / 128, NTOK / 64, 2);   // 4 x 32 x 2
    dim3 gD((Dm  + 127) / 128, NTOK / 64);        // 4 x 32
    dim3 gK(1,                 NTOK / 64);        // 1 x 32 (N=32)
    dim3 gF((FFd + 127) / 128, NTOK / 64);        // 16 x 32
    dim3 gAv((Dm + 127) / 128, Lseq / 64, Bsz);   // 4 x 16 x 2

    for (int i = 0; i < NLY; i++) {
        // z=0: t1 = tanh(x @ cp_w1 + cp_b1); z=1: v = x @ val_w + val_b
        mma_gemm<5, false, 2, false><<<gDual, 256>>>(x, cp_w1 + (size_t)i * Dm * Dm,
            cp_b1 + i * Dm, t1, NTOK, Dm, Dm, 0, 0, 0, nullptr, nullptr, nullptr, 0,
            val_w + (size_t)i * Dm * Dm, val_b + i * Dm, v);
        mma_gemm<4, false, 2, false><<<gK, 256>>>(t1, cp_w2 + (size_t)i * Dm * Kp,
            cp_b2 + i * Kp, Cb, NTOK, Kp, Dm, 0, 0, 0, Sb, pscale, cscale, i,
            nullptr, nullptr, nullptr);
        build_A_kernel<<<dim3(Lseq / 16, Lseq / 16, Bsz), dim3(16, 16)>>>(Cb, Sb, A);
        mma_gemm<0, false, 2, true><<<gAv, 256>>>(A, v, nullptr, ret,
            Lseq, Dm, Lseq,
            (size_t)Lseq * Lseq, (size_t)Lseq * Dm, (size_t)Lseq * Dm,
            nullptr, nullptr, nullptr, 0, nullptr, nullptr, nullptr);
        ln_kernel<<<NTOK, 128>>>(ret, oln_g + i * Dm, oln_b + i * Dm, rln);
        mma_gemm<0, false, 2, false><<<gD, 256>>>(rln, out_w + (size_t)i * Dm * Dm,
            out_b + i * Dm, o, NTOK, Dm, Dm, 0, 0, 0,
            nullptr, nullptr, nullptr, 0, nullptr, nullptr, nullptr);
        add_ln_kernel<true><<<NTOK, 128>>>(h, x, o, ln2_g + i * Dm, ln2_b + i * Dm, x);
        mma_gemm<3, false, 2, false><<<gF, 256>>>(x, ffn_w1 + (size_t)i * Dm * FFd,
            ffn_b1 + i * FFd, mid, NTOK, FFd, Dm, 0, 0, 0,
            nullptr, nullptr, nullptr, 0, nullptr, nullptr, nullptr);
        mma_gemm<0, false, 2, false><<<gD, 256>>>(mid, ffn_w2 + (size_t)i * FFd * Dm,
            ffn_b2 + i * Dm, o, NTOK, Dm, FFd, 0, 0, 0,
            nullptr, nullptr, nullptr, 0, nullptr, nullptr, nullptr);
        const float* ng = (i < NLY - 1) ? (ln1_g + (i + 1) * Dm) : no_g;
        const float* nb = (i < NLY - 1) ? (ln1_b + (i + 1) * Dm) : no_b;
        add_ln_kernel<false><<<NTOK, 128>>>(h, nullptr, o, ng, nb, x);
    }

    dim3 gH(Vocab / 128, NTOK / 128);             // 250 x 16
    mma_gemm<0, true, 4, false><<<gH, 256>>>(x, embed, head_b, logits,
        NTOK, Vocab, Dm, 0, 0, 0, nullptr, nullptr, nullptr, 0,
        nullptr, nullptr, nullptr);
}

// round 5
// speedup vs baseline: 3.2978x; 1.0813x over previous
#include <cuda_runtime.h>
#include <math.h>

#define Bsz   2
#define Lseq  1024
#define Dm    512
#define Kp    32
#define NLY   4
#define FFd   2048
#define Vocab 32000
#define NTOK  (Bsz*Lseq)   // 2048

// ---------------- scratch (no allocs allowed) ----------------
__device__ float g_h  [NTOK*Dm];
__device__ float g_x  [NTOK*Dm];    // exact LN1 output (residual add)
__device__ float g_xr [NTOK*Dm];    // tf32-rounded GEMM input
__device__ float g_t1 [NTOK*Dm];
__device__ float g_C  [NTOK*Kp];
__device__ float g_S  [NTOK*Kp];
__device__ float g_v  [NTOK*Dm];
__device__ float g_A  [Bsz*Lseq*Lseq];
__device__ float g_ret[NTOK*Dm];
__device__ float g_rln[NTOK*Dm];
__device__ float g_o  [NTOK*Dm];
__device__ float g_mid[NTOK*FFd];
// pre-rounded (tf32-representable) weights
__device__ float g_embr[Vocab*Dm];
__device__ float g_w1r [NLY*Dm*Dm];
__device__ float g_w2r [NLY*Dm*Kp];
__device__ float g_vwr [NLY*Dm*Dm];
__device__ float g_owr [NLY*Dm*Dm];
__device__ float g_f1r [NLY*Dm*FFd];
__device__ float g_f2r [NLY*FFd*Dm];

__device__ __forceinline__ unsigned rna(float x) {
    unsigned r;
    asm("cvt.rna.tf32.f32 %0, %1;\n" : "=r"(r) : "f"(x));
    return r;
}
__device__ __forceinline__ float rnaf(float x) { return __uint_as_float(rna(x)); }

// ---------------- tf32 pre-round ----------------
__global__ void round_kernel(const float* __restrict__ in, float* __restrict__ out,
                             int n4) {
    int i = blockIdx.x * 256 + threadIdx.x;
    if (i >= n4) return;
    float4 v = ((const float4*)in)[i];
    v.x = rnaf(v.x); v.y = rnaf(v.y); v.z = rnaf(v.z); v.w = rnaf(v.w);
    ((float4*)out)[i] = v;
}

// ---------------- embed gather ----------------
__global__ void gather_kernel(const int* __restrict__ tokens,
                              const float* __restrict__ embed,
                              float* __restrict__ h) {
    int row = blockIdx.x;
    int tok = tokens[row];
    const float4* src = (const float4*)(embed + (size_t)tok * Dm);
    float4* dst = (float4*)(h + (size_t)row * Dm);
    dst[threadIdx.x] = src[threadIdx.x];
}

// ---------------- layernorm core (writes exact and/or rounded) ----------------
__device__ __forceinline__ void ln_row(float4 v, const float* g, const float* b,
                                       int tid, float* out_row, float* outr_row) {
    float s = v.x + v.y + v.z + v.w;
    float q = v.x*v.x + v.y*v.y + v.z*v.z + v.w*v.w;
    #pragma unroll
    for (int off = 16; off; off >>= 1) {
        s += __shfl_xor_sync(0xffffffffu, s, off);
        q += __shfl_xor_sync(0xffffffffu, q, off);
    }
    __shared__ float ss[4], sq[4];
    int w = tid >> 5;
    if ((tid & 31) == 0) { ss[w] = s; sq[w] = q; }
    __syncthreads();
    s = ss[0] + ss[1] + ss[2] + ss[3];
    q = sq[0] + sq[1] + sq[2] + sq[3];
    float mean = s * (1.0f / Dm);
    float var  = q * (1.0f / Dm) - mean * mean;
    float r = rsqrtf(var + 1e-5f);
    float4 gv = ((const float4*)g)[tid], bv = ((const float4*)b)[tid], o;
    o.x = (v.x - mean) * r * gv.x + bv.x;
    o.y = (v.y - mean) * r * gv.y + bv.y;
    o.z = (v.z - mean) * r * gv.z + bv.z;
    o.w = (v.w - mean) * r * gv.w + bv.w;
    if (out_row)  ((float4*)out_row)[tid] = o;
    if (outr_row) {
        float4 t;
        t.x = rnaf(o.x); t.y = rnaf(o.y); t.z = rnaf(o.z); t.w = rnaf(o.w);
        ((float4*)outr_row)[tid] = t;
    }
}

__global__ void ln_kernel(const float* __restrict__ in,
                          const float* __restrict__ g,
                          const float* __restrict__ b,
                          float* __restrict__ out, float* __restrict__ outr) {
    int row = blockIdx.x, tid = threadIdx.x;
    float4 v = ((const float4*)(in + (size_t)row * Dm))[tid];
    ln_row(v, g, b, tid, out ? out + (size_t)row * Dm : nullptr,
           outr ? outr + (size_t)row * Dm : nullptr);
}

// fused residual-add + layernorm. THREE: h += x + o, else h += o.
template<bool THREE>
__global__ void add_ln_kernel(float* __restrict__ h, const float* __restrict__ x,
                              const float* __restrict__ o,
                              const float* __restrict__ g, const float* __restrict__ b,
                              float* __restrict__ out, float* __restrict__ outr) {
    int row = blockIdx.x, tid = threadIdx.x;
    size_t base = (size_t)row * Dm;
    float4 hv = ((const float4*)(h + base))[tid];
    float4 ov = ((const float4*)(o + base))[tid];
    if (THREE) {
        float4 xv = ((const float4*)(x + base))[tid];
        hv.x += xv.x + ov.x; hv.y += xv.y + ov.y;
        hv.z += xv.z + ov.z; hv.w += xv.w + ov.w;
    } else {
        hv.x += ov.x; hv.y += ov.y; hv.z += ov.z; hv.w += ov.w;
    }
    ((float4*)(h + base))[tid] = hv;
    ln_row(hv, g, b, tid, out ? out + base : nullptr, outr ? outr + base : nullptr);
}

// ---------------- cp.async helpers ----------------
__device__ __forceinline__ void cpa16(void* dst, const void* src, bool valid) {
    unsigned d = (unsigned)__cvta_generic_to_shared(dst);
    int sz = valid ? 16 : 0;
    asm volatile("cp.async.cg.shared.global [%0], [%1], 16, %2;\n"
                 :: "r"(d), "l"(src), "r"(sz));
}
#define CP_COMMIT() asm volatile("cp.async.commit_group;\n" ::)
#define CP_WAIT1()  asm volatile("cp.async.wait_group 1;\n" ::)

// ---------------- tf32 tensor-core GEMM, 3-stage cp.async pipeline ----------
// All GEMM inputs are PRE-ROUNDED to tf32-representable f32 -> no cvt in loop.
// NT=false: B[K,N] row-major. NT=true: B[N,K]. MT: rows = MT*32.
// ACT: 0 none, 3 gelu, 4 phase-epilogue, 5 dual-op (z=0 tanh->C, z=1 none->C2).
// CAUSAL: clamp K at row0+BM. SWAPG: row blocks in x, col blocks in y.
// RND: round stored outputs to tf32 (when they feed another GEMM).
template<int ACT, bool NT, int MT, bool CAUSAL, bool SWAPG, bool RND>
__global__ __launch_bounds__(256, MT == 4 ? 2 : 3)
void mma_gemm(const float* __restrict__ A, const float* __restrict__ Bm,
              const float* __restrict__ bias, float* __restrict__ C,
              int M, int N, int K,
              size_t sA, size_t sB, size_t sC,
              float* __restrict__ S_out, const float* __restrict__ psc,
              const float* __restrict__ csc, int layer,
              const float* __restrict__ Bm2, const float* __restrict__ bias2,
              float* __restrict__ C2) {
    const int BM = MT * 32;
    __shared__ __align__(16) float As[3][MT * 32][20];
    __shared__ __align__(16) float Bs[NT ? 1 : 3][16][136];   // [k][n]
    __shared__ __align__(16) float Bs2[NT ? 3 : 1][128][20];  // [n][k]

    A  += (size_t)blockIdx.z * sA;
    Bm += (size_t)blockIdx.z * sB;
    C  += (size_t)blockIdx.z * sC;
    if (ACT == 5 && blockIdx.z == 1) { Bm = Bm2; bias = bias2; C = C2; }

    const int tid = threadIdx.x;
    const int lane = tid & 31;
    const int wid = tid >> 5;
    const int wm = (wid >> 2) * (MT * 16);
    const int wn = (wid & 3) * 32;
    const int tr = lane >> 2, tc = lane & 3;
    const int row0 = (SWAPG ? blockIdx.x : blockIdx.y) * BM;
    const int col0 = (SWAPG ? blockIdx.y : blockIdx.x) * 128;
    const bool wact = (col0 + wn) < N;

    float acc[MT][4][4];
    #pragma unroll
    for (int i = 0; i < MT; i++)
        #pragma unroll
        for (int j = 0; j < 4; j++)
            #pragma unroll
            for (int l = 0; l < 4; l++) acc[i][j][l] = 0.f;

    int KT = K >> 4;
    if (CAUSAL) { int kc = (row0 + BM) >> 4; KT = kc < KT ? kc : KT; }

    auto load_stage = [&](int st, int k0) {
        #pragma unroll
        for (int i = 0; i < MT / 2; i++) {
            int id = tid + i * 256;
            int r = id >> 2, cc = (id & 3) << 2;
            cpa16(&As[st][r][cc], A + (size_t)(row0 + r) * K + k0 + cc, true);
        }
        if (!NT) {
            #pragma unroll
            for (int i = 0; i < 2; i++) {
                int id = tid + i * 256;
                int r = id >> 5, c4 = (id & 31) << 2;
                bool ok = (col0 + c4) < N;
                const float* src = Bm + (size_t)(k0 + r) * N + (ok ? (col0 + c4) : 0);
                cpa16(&Bs[st][r][c4], src, ok);
            }
        } else {
            #pragma unroll
            for (int i = 0; i < 2; i++) {
                int id = tid + i * 256;
                int n = id >> 2, kc = (id & 3) << 2;
                bool ok = (col0 + n) < N;
                const float* src = Bm + (size_t)(col0 + (ok ? n : 0)) * K + k0 + kc;
                cpa16(&Bs2[st][n][kc], src, ok);
            }
        }
    };

    load_stage(0, 0);
    CP_COMMIT();
    if (KT > 1) load_stage(1, 16);
    CP_COMMIT();

    for (int kt = 0; kt < KT; kt++) {
        CP_WAIT1();
        __syncthreads();
        if (kt + 2 < KT) load_stage((kt + 2) % 3, (kt + 2) << 4);
        CP_COMMIT();
        const int st = kt % 3;
        if (wact) {
            #pragma unroll
            for (int k8 = 0; k8 < 2; k8++) {
                const int kb = k8 << 3;
                unsigned a[MT][4], b[4][2];
                #pragma unroll
                for (int mt = 0; mt < MT; mt++) {
                    const float* p = &As[st][wm + mt * 16 + tr][kb + tc];
                    a[mt][0] = __float_as_uint(p[0]);
                    a[mt][1] = __float_as_uint(p[8 * 20]);
                    a[mt][2] = __float_as_uint(p[4]);
                    a[mt][3] = __float_as_uint(p[8 * 20 + 4]);
                }
                #pragma unroll
                for (int nt = 0; nt < 4; nt++) {
                    if (!NT) {
                        const float* p = &Bs[st][kb + tc][wn + nt * 8 + tr];
                        b[nt][0] = __float_as_uint(p[0]);
                        b[nt][1] = __float_as_uint(p[4 * 136]);
                    } else {
                        const float* p = &Bs2[st][wn + nt * 8 + tr][kb + tc];
                        b[nt][0] = __float_as_uint(p[0]);
                        b[nt][1] = __float_as_uint(p[4]);
                    }
                }
                #pragma unroll
                for (int mt = 0; mt < MT; mt++)
                    #pragma unroll
                    for (int nt = 0; nt < 4; nt++)
                        asm volatile(
                            "mma.sync.aligned.m16n8k8.row.col.f32.tf32.tf32.f32 "
                            "{%0,%1,%2,%3}, {%4,%5,%6,%7}, {%8,%9}, {%0,%1,%2,%3};\n"
                            : "+f"(acc[mt][nt][0]), "+f"(acc[mt][nt][1]),
                              "+f"(acc[mt][nt][2]), "+f"(acc[mt][nt][3])
                            : "r"(a[mt][0]), "r"(a[mt][1]), "r"(a[mt][2]), "r"(a[mt][3]),
                              "r"(b[nt][0]), "r"(b[nt][1]));
            }
        }
    }

    if (!wact) return;
    // epilogue
    #pragma unroll
    for (int mt = 0; mt < MT; mt++) {
        int r0 = row0 + wm + mt * 16 + tr;
        #pragma unroll
        for (int nt = 0; nt < 4; nt++) {
            int c0 = col0 + wn + nt * 8 + 2 * tc;
            if (c0 >= N) continue;
            float bcol0 = bias ? bias[c0] : 0.f;
            float bcol1 = bias ? bias[c0 + 1] : 0.f;
            #pragma unroll
            for (int half = 0; half < 2; half++) {
                int r = r0 + half * 8;
                float v0 = acc[mt][nt][half * 2 + 0] + bcol0;
                float v1 = acc[mt][nt][half * 2 + 1] + bcol1;
                if (ACT == 3) {
                    v0 = 0.5f * v0 * (1.0f + erff(v0 * 0.70710678118654752f));
                    v1 = 0.5f * v1 * (1.0f + erff(v1 * 0.70710678118654752f));
                } else if (ACT == 5) {
                    if (blockIdx.z == 0) { v0 = tanhf(v0); v1 = tanhf(v1); }
                }
                if (ACT == 4) {
                    int l = r & (Lseq - 1);
                    float ps = psc[layer], cs = csc[layer];
                    float fl = (float)l;
                    #pragma unroll
                    for (int cc = 0; cc < 2; cc++) {
                        int c = c0 + cc;
                        float val = tanhf(cc ? v1 : v0) * 3.14159274101257324f;
                        float fr = expf((float)c * (-9.210340371976184f / 32.0f));
                        float tp = ps * (fl * fr) + cs * val;
                        float sv, cv;
                        sincosf(tp, &sv, &cv);
                        C[(size_t)r * N + c] = cv;
                        S_out[(size_t)r * N + c] = sv;
                    }
                } else {
                    if (RND) { v0 = rnaf(v0); v1 = rnaf(v1); }
                    *(float2*)(C + (size_t)r * N + c0) = make_float2(v0, v1);
                }
            }
        }
    }
}

// ---------------- causal A = (C C^T + S S^T) * inv_norm[l], tf32-rounded ----
__global__ void build_A_kernel(const float* __restrict__ C, const float* __restrict__ S,
                               float* __restrict__ A) {
    __shared__ float cl[16][33], sl[16][33], ct[16][33], st[16][33];
    int b = blockIdx.z;
    int tid = threadIdx.y * 16 + threadIdx.x;
    int l0 = blockIdx.y * 16, t0 = blockIdx.x * 16;
    const float* Cb = C + (size_t)b * Lseq * Kp;
    const float* Sb = S + (size_t)b * Lseq * Kp;
    for (int i = tid; i < 16 * 32; i += 256) {
        int r = i >> 5, c = i & 31;
        cl[r][c] = Cb[(size_t)(l0 + r) * Kp + c];
        sl[r][c] = Sb[(size_t)(l0 + r) * Kp + c];
        ct[r][c] = Cb[(size_t)(t0 + r) * Kp + c];
        st[r][c] = Sb[(size_t)(t0 + r) * Kp + c];
    }
    __syncthreads();
    int l = l0 + threadIdx.y, t = t0 + threadIdx.x;
    float acc = 0.f;
    #pragma unroll
    for (int k = 0; k < 32; k++)
        acc += cl[threadIdx.y][k] * ct[threadIdx.x][k]
             + sl[threadIdx.y][k] * st[threadIdx.x][k];
    float out = (t <= l) ? rnaf(acc * rsqrtf((float)((l + 1) * Kp))) : 0.f;
    A[((size_t)b * Lseq + l) * Lseq + t] = out;
}

// ---------------- driver ----------------
extern "C" void kernel_launch(void* const* d_in, const int* in_sizes, int n_in,
                              void* d_out, int out_size) {
    const int*   tokens  = (const int*)  d_in[0];
    const float* embed   = (const float*)d_in[1];
    const float* ln1_g   = (const float*)d_in[2];
    const float* ln1_b   = (const float*)d_in[3];
    const float* cp_w1   = (const float*)d_in[4];
    const float* cp_b1   = (const float*)d_in[5];
    const float* cp_w2   = (const float*)d_in[6];
    const float* cp_b2   = (const float*)d_in[7];
    const float* pscale  = (const float*)d_in[8];
    const float* cscale  = (const float*)d_in[9];
    const float* val_w   = (const float*)d_in[10];
    const float* val_b   = (const float*)d_in[11];
    const float* oln_g   = (const float*)d_in[12];
    const float* oln_b   = (const float*)d_in[13];
    const float* out_w   = (const float*)d_in[14];
    const float* out_b   = (const float*)d_in[15];
    const float* ln2_g   = (const float*)d_in[16];
    const float* ln2_b   = (const float*)d_in[17];
    const float* ffn_w1  = (const float*)d_in[18];
    const float* ffn_b1  = (const float*)d_in[19];
    const float* ffn_w2  = (const float*)d_in[20];
    const float* ffn_b2  = (const float*)d_in[21];
    const float* no_g    = (const float*)d_in[22];
    const float* no_b    = (const float*)d_in[23];
    const float* head_b  = (const float*)d_in[24];
    float* logits = (float*)d_out;

    float *h, *x, *xr, *t1, *Cb, *Sb, *v, *A, *ret, *rln, *o, *mid;
    float *embr, *w1r, *w2r, *vwr, *owr, *f1r, *f2r;
    cudaGetSymbolAddress((void**)&h,    g_h);
    cudaGetSymbolAddress((void**)&x,    g_x);
    cudaGetSymbolAddress((void**)&xr,   g_xr);
    cudaGetSymbolAddress((void**)&t1,   g_t1);
    cudaGetSymbolAddress((void**)&Cb,   g_C);
    cudaGetSymbolAddress((void**)&Sb,   g_S);
    cudaGetSymbolAddress((void**)&v,    g_v);
    cudaGetSymbolAddress((void**)&A,    g_A);
    cudaGetSymbolAddress((void**)&ret,  g_ret);
    cudaGetSymbolAddress((void**)&rln,  g_rln);
    cudaGetSymbolAddress((void**)&o,    g_o);
    cudaGetSymbolAddress((void**)&mid,  g_mid);
    cudaGetSymbolAddress((void**)&embr, g_embr);
    cudaGetSymbolAddress((void**)&w1r,  g_w1r);
    cudaGetSymbolAddress((void**)&w2r,  g_w2r);
    cudaGetSymbolAddress((void**)&vwr,  g_vwr);
    cudaGetSymbolAddress((void**)&owr,  g_owr);
    cudaGetSymbolAddress((void**)&f1r,  g_f1r);
    cudaGetSymbolAddress((void**)&f2r,  g_f2r);

    auto rnd = [&](const float* src, float* dst, int n) {
        int n4 = n >> 2;
        round_kernel<<<(n4 + 255) / 256, 256>>>(src, dst, n4);
    };
    rnd(embed,  embr, Vocab * Dm);
    rnd(cp_w1,  w1r,  NLY * Dm * Dm);
    rnd(cp_w2,  w2r,  NLY * Dm * Kp);
    rnd(val_w,  vwr,  NLY * Dm * Dm);
    rnd(out_w,  owr,  NLY * Dm * Dm);
    rnd(ffn_w1, f1r,  NLY * Dm * FFd);
    rnd(ffn_w2, f2r,  NLY * FFd * Dm);

    gather_kernel<<<NTOK, 128>>>(tokens, embed, h);
    ln_kernel<<<NTOK, 128>>>(h, ln1_g, ln1_b, x, xr);

    dim3 gDual((Dm + 127) / 128, NTOK / 64, 2);
    dim3 gD((Dm  + 127) / 128, NTOK / 64);
    dim3 gK(1,                 NTOK / 64);
    dim3 gF((FFd + 127) / 128, NTOK / 64);
    dim3 gAv((Dm + 127) / 128, Lseq / 64, Bsz);

    for (int i = 0; i < NLY; i++) {
        // z=0: t1 = tanh(xr @ w1 + b1); z=1: v = xr @ vw + vb   (both tf32-rounded)
        mma_gemm<5, false, 2, false, false, true><<<gDual, 256>>>(
            xr, w1r + (size_t)i * Dm * Dm, cp_b1 + i * Dm, t1, NTOK, Dm, Dm,
            0, 0, 0, nullptr, nullptr, nullptr, 0,
            vwr + (size_t)i * Dm * Dm, val_b + i * Dm, v);
        mma_gemm<4, false, 2, false, false, false><<<gK, 256>>>(
            t1, w2r + (size_t)i * Dm * Kp, cp_b2 + i * Kp, Cb, NTOK, Kp, Dm,
            0, 0, 0, Sb, pscale, cscale, i, nullptr, nullptr, nullptr);
        build_A_kernel<<<dim3(Lseq / 16, Lseq / 16, Bsz), dim3(16, 16)>>>(Cb, Sb, A);
        mma_gemm<0, false, 2, true, false, false><<<gAv, 256>>>(
            A, v, nullptr, ret, Lseq, Dm, Lseq,
            (size_t)Lseq * Lseq, (size_t)Lseq * Dm, (size_t)Lseq * Dm,
            nullptr, nullptr, nullptr, 0, nullptr, nullptr, nullptr);
        ln_kernel<<<NTOK, 128>>>(ret, oln_g + i * Dm, oln_b + i * Dm, nullptr, rln);
        mma_gemm<0, false, 2, false, false, false><<<gD, 256>>>(
            rln, owr + (size_t)i * Dm * Dm, out_b + i * Dm, o, NTOK, Dm, Dm,
            0, 0, 0, nullptr, nullptr, nullptr, 0, nullptr, nullptr, nullptr);
        add_ln_kernel<true><<<NTOK, 128>>>(h, x, o, ln2_g + i * Dm, ln2_b + i * Dm,
                                           nullptr, xr);
        mma_gemm<3, false, 2, false, false, true><<<gF, 256>>>(
            xr, f1r + (size_t)i * Dm * FFd, ffn_b1 + i * FFd, mid, NTOK, FFd, Dm,
            0, 0, 0, nullptr, nullptr, nullptr, 0, nullptr, nullptr, nullptr);
        mma_gemm<0, false, 2, false, false, false><<<gD, 256>>>(
            mid, f2r + (size_t)i * FFd * Dm, ffn_b2 + i * Dm, o, NTOK, Dm, FFd,
            0, 0, 0, nullptr, nullptr, nullptr, 0, nullptr, nullptr, nullptr);
        const float* ng = (i < NLY - 1) ? (ln1_g + (i + 1) * Dm) : no_g;
        const float* nb = (i < NLY - 1) ? (ln1_b + (i + 1) * Dm) : no_b;
        add_ln_kernel<false><<<NTOK, 128>>>(h, nullptr, o, ng, nb, x, xr);
    }

    // head: row-blocks in x (16), col-blocks in y (250) -> embed slices stay in L2
    dim3 gH(NTOK / 128, Vocab / 128);
    mma_gemm<0, true, 4, false, true, false><<<gH, 256>>>(
        xr, embr, head_b, logits, NTOK, Vocab, Dm,
        0, 0, 0, nullptr, nullptr, nullptr, 0, nullptr, nullptr, nullptr);
}

// round 6
// speedup vs baseline: 3.3031x; 1.0016x over previous
#include <cuda_runtime.h>
#include <math.h>

#define Bsz   2
#define Lseq  1024
#define Dm    512
#define Kp    32
#define NLY   4
#define FFd   2048
#define Vocab 32000
#define NTOK  (Bsz*Lseq)   // 2048

// ---------------- scratch (no allocs allowed) ----------------
__device__ float g_h  [NTOK*Dm];
__device__ float g_x  [NTOK*Dm];    // exact LN1 output (residual add)
__device__ float g_xr [NTOK*Dm];    // tf32-rounded GEMM input
__device__ float g_t1 [NTOK*Dm];
__device__ float g_C  [NTOK*Kp];
__device__ float g_S  [NTOK*Kp];
__device__ float g_v  [NTOK*Dm];
__device__ float g_A  [Bsz*Lseq*Lseq];
__device__ float g_ret[NTOK*Dm];
__device__ float g_rln[NTOK*Dm];
__device__ float g_o  [NTOK*Dm];
__device__ float g_mid[NTOK*FFd];

__device__ __forceinline__ unsigned rna(float x) {
    unsigned r;
    asm("cvt.rna.tf32.f32 %0, %1;\n" : "=r"(r) : "f"(x));
    return r;
}
__device__ __forceinline__ float rnaf(float x) { return __uint_as_float(rna(x)); }

// ---------------- embed gather ----------------
__global__ void gather_kernel(const int* __restrict__ tokens,
                              const float* __restrict__ embed,
                              float* __restrict__ h) {
    int row = blockIdx.x;
    int tok = tokens[row];
    const float4* src = (const float4*)(embed + (size_t)tok * Dm);
    float4* dst = (float4*)(h + (size_t)row * Dm);
    dst[threadIdx.x] = src[threadIdx.x];
}

// ---------------- layernorm core (writes exact and/or rounded) ----------------
__device__ __forceinline__ void ln_row(float4 v, const float* g, const float* b,
                                       int tid, float* out_row, float* outr_row) {
    float s = v.x + v.y + v.z + v.w;
    float q = v.x*v.x + v.y*v.y + v.z*v.z + v.w*v.w;
    #pragma unroll
    for (int off = 16; off; off >>= 1) {
        s += __shfl_xor_sync(0xffffffffu, s, off);
        q += __shfl_xor_sync(0xffffffffu, q, off);
    }
    __shared__ float ss[4], sq[4];
    int w = tid >> 5;
    if ((tid & 31) == 0) { ss[w] = s; sq[w] = q; }
    __syncthreads();
    s = ss[0] + ss[1] + ss[2] + ss[3];
    q = sq[0] + sq[1] + sq[2] + sq[3];
    float mean = s * (1.0f / Dm);
    float var  = q * (1.0f / Dm) - mean * mean;
    float r = rsqrtf(var + 1e-5f);
    float4 gv = ((const float4*)g)[tid], bv = ((const float4*)b)[tid], o;
    o.x = (v.x - mean) * r * gv.x + bv.x;
    o.y = (v.y - mean) * r * gv.y + bv.y;
    o.z = (v.z - mean) * r * gv.z + bv.z;
    o.w = (v.w - mean) * r * gv.w + bv.w;
    if (out_row)  ((float4*)out_row)[tid] = o;
    if (outr_row) {
        float4 t;
        t.x = rnaf(o.x); t.y = rnaf(o.y); t.z = rnaf(o.z); t.w = rnaf(o.w);
        ((float4*)outr_row)[tid] = t;
    }
}

__global__ void ln_kernel(const float* __restrict__ in,
                          const float* __restrict__ g,
                          const float* __restrict__ b,
                          float* __restrict__ out, float* __restrict__ outr) {
    int row = blockIdx.x, tid = threadIdx.x;
    float4 v = ((const float4*)(in + (size_t)row * Dm))[tid];
    ln_row(v, g, b, tid, out ? out + (size_t)row * Dm : nullptr,
           outr ? outr + (size_t)row * Dm : nullptr);
}

// fused residual-add + layernorm. THREE: h += x + o, else h += o.
template<bool THREE>
__global__ void add_ln_kernel(float* __restrict__ h, const float* __restrict__ x,
                              const float* __restrict__ o,
                              const float* __restrict__ g, const float* __restrict__ b,
                              float* __restrict__ out, float* __restrict__ outr) {
    int row = blockIdx.x, tid = threadIdx.x;
    size_t base = (size_t)row * Dm;
    float4 hv = ((const float4*)(h + base))[tid];
    float4 ov = ((const float4*)(o + base))[tid];
    if (THREE) {
        float4 xv = ((const float4*)(x + base))[tid];
        hv.x += xv.x + ov.x; hv.y += xv.y + ov.y;
        hv.z += xv.z + ov.z; hv.w += xv.w + ov.w;
    } else {
        hv.x += ov.x; hv.y += ov.y; hv.z += ov.z; hv.w += ov.w;
    }
    ((float4*)(h + base))[tid] = hv;
    ln_row(hv, g, b, tid, out ? out + base : nullptr, outr ? outr + base : nullptr);
}

// ---------------- cp.async helpers ----------------
__device__ __forceinline__ void cpa16(void* dst, const void* src, bool valid) {
    unsigned d = (unsigned)__cvta_generic_to_shared(dst);
    int sz = valid ? 16 : 0;
    asm volatile("cp.async.cg.shared.global [%0], [%1], 16, %2;\n"
                 :: "r"(d), "l"(src), "r"(sz));
}
#define CP_COMMIT() asm volatile("cp.async.commit_group;\n" ::)
#define CP_WAIT1()  asm volatile("cp.async.wait_group 1;\n" ::)

// ---------------- tf32 tensor-core GEMM, 3-stage cp.async pipeline ----------
// A operands are pre-rounded by their producers (no cvt).
// B operands: RNB=true -> cvt.rna at fragment load (raw weights from gmem);
//             RNB=false -> already tf32-representable (e.g. v, A).
// NT=false: B[K,N] row-major. NT=true: B[N,K]. MT: rows = MT*32.
// ACT: 0 none, 3 gelu, 4 phase-epilogue, 5 dual-op (z=0 tanh->C, z=1 none->C2).
// CAUSAL: clamp K at row0+BM. SWAPG: row blocks in x, col blocks in y.
// RND: round stored outputs to tf32 (when they feed another GEMM as operand).
template<int ACT, bool NT, int MT, bool CAUSAL, bool SWAPG, bool RND, bool RNB>
__global__ __launch_bounds__(256, MT == 4 ? 2 : 3)
void mma_gemm(const float* __restrict__ A, const float* __restrict__ Bm,
              const float* __restrict__ bias, float* __restrict__ C,
              int M, int N, int K,
              size_t sA, size_t sB, size_t sC,
              float* __restrict__ S_out, const float* __restrict__ psc,
              const float* __restrict__ csc, int layer,
              const float* __restrict__ Bm2, const float* __restrict__ bias2,
              float* __restrict__ C2) {
    const int BM = MT * 32;
    __shared__ __align__(16) float As[3][MT * 32][20];
    __shared__ __align__(16) float Bs[NT ? 1 : 3][16][136];   // [k][n]
    __shared__ __align__(16) float Bs2[NT ? 3 : 1][128][20];  // [n][k]

    A  += (size_t)blockIdx.z * sA;
    Bm += (size_t)blockIdx.z * sB;
    C  += (size_t)blockIdx.z * sC;
    if (ACT == 5 && blockIdx.z == 1) { Bm = Bm2; bias = bias2; C = C2; }

    const int tid = threadIdx.x;
    const int lane = tid & 31;
    const int wid = tid >> 5;
    const int wm = (wid >> 2) * (MT * 16);
    const int wn = (wid & 3) * 32;
    const int tr = lane >> 2, tc = lane & 3;
    const int row0 = (SWAPG ? blockIdx.x : blockIdx.y) * BM;
    const int col0 = (SWAPG ? blockIdx.y : blockIdx.x) * 128;
    const bool wact = (col0 + wn) < N;

    float acc[MT][4][4];
    #pragma unroll
    for (int i = 0; i < MT; i++)
        #pragma unroll
        for (int j = 0; j < 4; j++)
            #pragma unroll
            for (int l = 0; l < 4; l++) acc[i][j][l] = 0.f;

    int KT = K >> 4;
    if (CAUSAL) { int kc = (row0 + BM) >> 4; KT = kc < KT ? kc : KT; }

    auto load_stage = [&](int st, int k0) {
        #pragma unroll
        for (int i = 0; i < MT / 2; i++) {
            int id = tid + i * 256;
            int r = id >> 2, cc = (id & 3) << 2;
            cpa16(&As[st][r][cc], A + (size_t)(row0 + r) * K + k0 + cc, true);
        }
        if (!NT) {
            #pragma unroll
            for (int i = 0; i < 2; i++) {
                int id = tid + i * 256;
                int r = id >> 5, c4 = (id & 31) << 2;
                bool ok = (col0 + c4) < N;
                const float* src = Bm + (size_t)(k0 + r) * N + (ok ? (col0 + c4) : 0);
                cpa16(&Bs[st][r][c4], src, ok);
            }
        } else {
            #pragma unroll
            for (int i = 0; i < 2; i++) {
                int id = tid + i * 256;
                int n = id >> 2, kc = (id & 3) << 2;
                bool ok = (col0 + n) < N;
                const float* src = Bm + (size_t)(col0 + (ok ? n : 0)) * K + k0 + kc;
                cpa16(&Bs2[st][n][kc], src, ok);
            }
        }
    };

    load_stage(0, 0);
    CP_COMMIT();
    if (KT > 1) load_stage(1, 16);
    CP_COMMIT();

    for (int kt = 0; kt < KT; kt++) {
        CP_WAIT1();
        __syncthreads();
        if (kt + 2 < KT) load_stage((kt + 2) % 3, (kt + 2) << 4);
        CP_COMMIT();
        const int st = kt % 3;
        if (wact) {
            #pragma unroll
            for (int k8 = 0; k8 < 2; k8++) {
                const int kb = k8 << 3;
                unsigned a[MT][4], b[4][2];
                #pragma unroll
                for (int mt = 0; mt < MT; mt++) {
                    const float* p = &As[st][wm + mt * 16 + tr][kb + tc];
                    a[mt][0] = __float_as_uint(p[0]);
                    a[mt][1] = __float_as_uint(p[8 * 20]);
                    a[mt][2] = __float_as_uint(p[4]);
                    a[mt][3] = __float_as_uint(p[8 * 20 + 4]);
                }
                #pragma unroll
                for (int nt = 0; nt < 4; nt++) {
                    if (!NT) {
                        const float* p = &Bs[st][kb + tc][wn + nt * 8 + tr];
                        if (RNB) {
                            b[nt][0] = rna(p[0]);
                            b[nt][1] = rna(p[4 * 136]);
                        } else {
                            b[nt][0] = __float_as_uint(p[0]);
                            b[nt][1] = __float_as_uint(p[4 * 136]);
                        }
                    } else {
                        const float* p = &Bs2[st][wn + nt * 8 + tr][kb + tc];
                        if (RNB) {
                            b[nt][0] = rna(p[0]);
                            b[nt][1] = rna(p[4]);
                        } else {
                            b[nt][0] = __float_as_uint(p[0]);
                            b[nt][1] = __float_as_uint(p[4]);
                        }
                    }
                }
                #pragma unroll
                for (int mt = 0; mt < MT; mt++)
                    #pragma unroll
                    for (int nt = 0; nt < 4; nt++)
                        asm volatile(
                            "mma.sync.aligned.m16n8k8.row.col.f32.tf32.tf32.f32 "
                            "{%0,%1,%2,%3}, {%4,%5,%6,%7}, {%8,%9}, {%0,%1,%2,%3};\n"
                            : "+f"(acc[mt][nt][0]), "+f"(acc[mt][nt][1]),
                              "+f"(acc[mt][nt][2]), "+f"(acc[mt][nt][3])
                            : "r"(a[mt][0]), "r"(a[mt][1]), "r"(a[mt][2]), "r"(a[mt][3]),
                              "r"(b[nt][0]), "r"(b[nt][1]));
            }
        }
    }

    if (!wact) return;
    // epilogue
    #pragma unroll
    for (int mt = 0; mt < MT; mt++) {
        int r0 = row0 + wm + mt * 16 + tr;
        #pragma unroll
        for (int nt = 0; nt < 4; nt++) {
            int c0 = col0 + wn + nt * 8 + 2 * tc;
            if (c0 >= N) continue;
            float bcol0 = bias ? bias[c0] : 0.f;
            float bcol1 = bias ? bias[c0 + 1] : 0.f;
            #pragma unroll
            for (int half = 0; half < 2; half++) {
                int r = r0 + half * 8;
                float v0 = acc[mt][nt][half * 2 + 0] + bcol0;
                float v1 = acc[mt][nt][half * 2 + 1] + bcol1;
                if (ACT == 3) {
                    v0 = 0.5f * v0 * (1.0f + erff(v0 * 0.70710678118654752f));
                    v1 = 0.5f * v1 * (1.0f + erff(v1 * 0.70710678118654752f));
                } else if (ACT == 5) {
                    if (blockIdx.z == 0) { v0 = tanhf(v0); v1 = tanhf(v1); }
                }
                if (ACT == 4) {
                    int l = r & (Lseq - 1);
                    float ps = psc[layer], cs = csc[layer];
                    float fl = (float)l;
                    #pragma unroll
                    for (int cc = 0; cc < 2; cc++) {
                        int c = c0 + cc;
                        float val = tanhf(cc ? v1 : v0) * 3.14159274101257324f;
                        float fr = expf((float)c * (-9.210340371976184f / 32.0f));
                        float tp = ps * (fl * fr) + cs * val;
                        float sv, cv;
                        sincosf(tp, &sv, &cv);
                        C[(size_t)r * N + c] = cv;
                        S_out[(size_t)r * N + c] = sv;
                    }
                } else {
                    if (RND) { v0 = rnaf(v0); v1 = rnaf(v1); }
                    *(float2*)(C + (size_t)r * N + c0) = make_float2(v0, v1);
                }
            }
        }
    }
}

// ---------------- causal A = (C C^T + S S^T) * inv_norm[l], tf32-rounded ----
__global__ void build_A_kernel(const float* __restrict__ C, const float* __restrict__ S,
                               float* __restrict__ A) {
    __shared__ float cl[16][33], sl[16][33], ct[16][33], st[16][33];
    int b = blockIdx.z;
    int tid = threadIdx.y * 16 + threadIdx.x;
    int l0 = blockIdx.y * 16, t0 = blockIdx.x * 16;
    const float* Cb = C + (size_t)b * Lseq * Kp;
    const float* Sb = S + (size_t)b * Lseq * Kp;
    for (int i = tid; i < 16 * 32; i += 256) {
        int r = i >> 5, c = i & 31;
        cl[r][c] = Cb[(size_t)(l0 + r) * Kp + c];
        sl[r][c] = Sb[(size_t)(l0 + r) * Kp + c];
        ct[r][c] = Cb[(size_t)(t0 + r) * Kp + c];
        st[r][c] = Sb[(size_t)(t0 + r) * Kp + c];
    }
    __syncthreads();
    int l = l0 + threadIdx.y, t = t0 + threadIdx.x;
    float acc = 0.f;
    #pragma unroll
    for (int k = 0; k < 32; k++)
        acc += cl[threadIdx.y][k] * ct[threadIdx.x][k]
             + sl[threadIdx.y][k] * st[threadIdx.x][k];
    float out = (t <= l) ? rnaf(acc * rsqrtf((float)((l + 1) * Kp))) : 0.f;
    A[((size_t)b * Lseq + l) * Lseq + t] = out;
}

// ---------------- driver ----------------
extern "C" void kernel_launch(void* const* d_in, const int* in_sizes, int n_in,
                              void* d_out, int out_size) {
    const int*   tokens  = (const int*)  d_in[0];
    const float* embed   = (const float*)d_in[1];
    const float* ln1_g   = (const float*)d_in[2];
    const float* ln1_b   = (const float*)d_in[3];
    const float* cp_w1   = (const float*)d_in[4];
    const float* cp_b1   = (const float*)d_in[5];
    const float* cp_w2   = (const float*)d_in[6];
    const float* cp_b2   = (const float*)d_in[7];
    const float* pscale  = (const float*)d_in[8];
    const float* cscale  = (const float*)d_in[9];
    const float* val_w   = (const float*)d_in[10];
    const float* val_b   = (const float*)d_in[11];
    const float* oln_g   = (const float*)d_in[12];
    const float* oln_b   = (const float*)d_in[13];
    const float* out_w   = (const float*)d_in[14];
    const float* out_b   = (const float*)d_in[15];
    const float* ln2_g   = (const float*)d_in[16];
    const float* ln2_b   = (const float*)d_in[17];
    const float* ffn_w1  = (const float*)d_in[18];
    const float* ffn_b1  = (const float*)d_in[19];
    const float* ffn_w2  = (const float*)d_in[20];
    const float* ffn_b2  = (const float*)d_in[21];
    const float* no_g    = (const float*)d_in[22];
    const float* no_b    = (const float*)d_in[23];
    const float* head_b  = (const float*)d_in[24];
    float* logits = (float*)d_out;

    float *h, *x, *xr, *t1, *Cb, *Sb, *v, *A, *ret, *rln, *o, *mid;
    cudaGetSymbolAddress((void**)&h,    g_h);
    cudaGetSymbolAddress((void**)&x,    g_x);
    cudaGetSymbolAddress((void**)&xr,   g_xr);
    cudaGetSymbolAddress((void**)&t1,   g_t1);
    cudaGetSymbolAddress((void**)&Cb,   g_C);
    cudaGetSymbolAddress((void**)&Sb,   g_S);
    cudaGetSymbolAddress((void**)&v,    g_v);
    cudaGetSymbolAddress((void**)&A,    g_A);
    cudaGetSymbolAddress((void**)&ret,  g_ret);
    cudaGetSymbolAddress((void**)&rln,  g_rln);
    cudaGetSymbolAddress((void**)&o,    g_o);
    cudaGetSymbolAddress((void**)&mid,  g_mid);

    gather_kernel<<<NTOK, 128>>>(tokens, embed, h);
    ln_kernel<<<NTOK, 128>>>(h, ln1_g, ln1_b, x, xr);

    dim3 gDual((Dm + 127) / 128, NTOK / 64, 2);
    dim3 gD((Dm  + 127) / 128, NTOK / 64);
    dim3 gK(1,                 NTOK / 64);
    dim3 gF((FFd + 127) / 128, NTOK / 64);
    dim3 gAv((Dm + 127) / 128, Lseq / 64, Bsz);

    for (int i = 0; i < NLY; i++) {
        // z=0: t1 = tanh(xr @ w1 + b1); z=1: v = xr @ vw + vb  (raw weights, RNB)
        mma_gemm<5, false, 2, false, false, true, true><<<gDual, 256>>>(
            xr, cp_w1 + (size_t)i * Dm * Dm, cp_b1 + i * Dm, t1, NTOK, Dm, Dm,
            0, 0, 0, nullptr, nullptr, nullptr, 0,
            val_w + (size_t)i * Dm * Dm, val_b + i * Dm, v);
        mma_gemm<4, false, 2, false, false, false, true><<<gK, 256>>>(
            t1, cp_w2 + (size_t)i * Dm * Kp, cp_b2 + i * Kp, Cb, NTOK, Kp, Dm,
            0, 0, 0, Sb, pscale, cscale, i, nullptr, nullptr, nullptr);
        build_A_kernel<<<dim3(Lseq / 16, Lseq / 16, Bsz), dim3(16, 16)>>>(Cb, Sb, A);
        mma_gemm<0, false, 2, true, false, false, false><<<gAv, 256>>>(
            A, v, nullptr, ret, Lseq, Dm, Lseq,
            (size_t)Lseq * Lseq, (size_t)Lseq * Dm, (size_t)Lseq * Dm,
            nullptr, nullptr, nullptr, 0, nullptr, nullptr, nullptr);
        ln_kernel<<<NTOK, 128>>>(ret, oln_g + i * Dm, oln_b + i * Dm, nullptr, rln);
        mma_gemm<0, false, 2, false, false, false, true><<<gD, 256>>>(
            rln, out_w + (size_t)i * Dm * Dm, out_b + i * Dm, o, NTOK, Dm, Dm,
            0, 0, 0, nullptr, nullptr, nullptr, 0, nullptr, nullptr, nullptr);
        add_ln_kernel<true><<<NTOK, 128>>>(h, x, o, ln2_g + i * Dm, ln2_b + i * Dm,
                                           nullptr, xr);
        mma_gemm<3, false, 2, false, false, true, true><<<gF, 256>>>(
            xr, ffn_w1 + (size_t)i * Dm * FFd, ffn_b1 + i * FFd, mid, NTOK, FFd, Dm,
            0, 0, 0, nullptr, nullptr, nullptr, 0, nullptr, nullptr, nullptr);
        mma_gemm<0, false, 2, false, false, false, true><<<gD, 256>>>(
            mid, ffn_w2 + (size_t)i * FFd * Dm, ffn_b2 + i * Dm, o, NTOK, Dm, FFd,
            0, 0, 0, nullptr, nullptr, nullptr, 0, nullptr, nullptr, nullptr);
        const float* ng = (i < NLY - 1) ? (ln1_g + (i + 1) * Dm) : no_g;
        const float* nb = (i < NLY - 1) ? (ln1_b + (i + 1) * Dm) : no_b;
        add_ln_kernel<false><<<NTOK, 128>>>(h, nullptr, o, ng, nb, x, xr);
    }

    // head: row-blocks in x (16), col-blocks in y (250) -> embed slices stay in L2
    dim3 gH(NTOK / 128, Vocab / 128);
    mma_gemm<0, true, 4, false, true, false, true><<<gH, 256>>>(
        xr, embed, head_b, logits, NTOK, Vocab, Dm,
        0, 0, 0, nullptr, nullptr, nullptr, 0, nullptr, nullptr, nullptr);
}

// round 7
// speedup vs baseline: 3.4366x; 1.0404x over previous
#include <cuda_runtime.h>
#include <math.h>

#define Bsz   2
#define Lseq  1024
#define Dm    512
#define Kp    32
#define NLY   4
#define FFd   2048
#define Vocab 32000
#define NTOK  (Bsz*Lseq)   // 2048

// ---------------- scratch (no allocs allowed) ----------------
__device__ float g_h  [NTOK*Dm];
__device__ float g_x  [NTOK*Dm];    // exact LN1 output (residual add)
__device__ float g_xr [NTOK*Dm];    // tf32-rounded GEMM input
__device__ float g_t1 [NTOK*Dm];
__device__ float g_C  [NTOK*Kp];
__device__ float g_S  [NTOK*Kp];
__device__ float g_v  [NTOK*Dm];
__device__ float g_A  [Bsz*Lseq*Lseq];
__device__ float g_ret[NTOK*Dm];
__device__ float g_rln[NTOK*Dm];
__device__ float g_o  [NTOK*Dm];
__device__ float g_mid[NTOK*FFd];

__device__ __forceinline__ unsigned rna(float x) {
    unsigned r;
    asm("cvt.rna.tf32.f32 %0, %1;\n" : "=r"(r) : "f"(x));
    return r;
}
__device__ __forceinline__ float rnaf(float x) { return __uint_as_float(rna(x)); }

// ---------------- embed gather ----------------
__global__ void gather_kernel(const int* __restrict__ tokens,
                              const float* __restrict__ embed,
                              float* __restrict__ h) {
    int row = blockIdx.x;
    int tok = tokens[row];
    const float4* src = (const float4*)(embed + (size_t)tok * Dm);
    float4* dst = (float4*)(h + (size_t)row * Dm);
    dst[threadIdx.x] = src[threadIdx.x];
}

// ---------------- layernorm core (writes exact and/or rounded) ----------------
__device__ __forceinline__ void ln_row(float4 v, const float* g, const float* b,
                                       int tid, float* out_row, float* outr_row) {
    float s = v.x + v.y + v.z + v.w;
    float q = v.x*v.x + v.y*v.y + v.z*v.z + v.w*v.w;
    #pragma unroll
    for (int off = 16; off; off >>= 1) {
        s += __shfl_xor_sync(0xffffffffu, s, off);
        q += __shfl_xor_sync(0xffffffffu, q, off);
    }
    __shared__ float ss[4], sq[4];
    int w = tid >> 5;
    if ((tid & 31) == 0) { ss[w] = s; sq[w] = q; }
    __syncthreads();
    s = ss[0] + ss[1] + ss[2] + ss[3];
    q = sq[0] + sq[1] + sq[2] + sq[3];
    float mean = s * (1.0f / Dm);
    float var  = q * (1.0f / Dm) - mean * mean;
    float r = rsqrtf(var + 1e-5f);
    float4 gv = ((const float4*)g)[tid], bv = ((const float4*)b)[tid], o;
    o.x = (v.x - mean) * r * gv.x + bv.x;
    o.y = (v.y - mean) * r * gv.y + bv.y;
    o.z = (v.z - mean) * r * gv.z + bv.z;
    o.w = (v.w - mean) * r * gv.w + bv.w;
    if (out_row)  ((float4*)out_row)[tid] = o;
    if (outr_row) {
        float4 t;
        t.x = rnaf(o.x); t.y = rnaf(o.y); t.z = rnaf(o.z); t.w = rnaf(o.w);
        ((float4*)outr_row)[tid] = t;
    }
}

__global__ void ln_kernel(const float* __restrict__ in,
                          const float* __restrict__ g,
                          const float* __restrict__ b,
                          float* __restrict__ out, float* __restrict__ outr) {
    int row = blockIdx.x, tid = threadIdx.x;
    float4 v = ((const float4*)(in + (size_t)row * Dm))[tid];
    ln_row(v, g, b, tid, out ? out + (size_t)row * Dm : nullptr,
           outr ? outr + (size_t)row * Dm : nullptr);
}

// fused residual-add + layernorm. THREE: h += x + o, else h += o.
template<bool THREE>
__global__ void add_ln_kernel(float* __restrict__ h, const float* __restrict__ x,
                              const float* __restrict__ o,
                              const float* __restrict__ g, const float* __restrict__ b,
                              float* __restrict__ out, float* __restrict__ outr) {
    int row = blockIdx.x, tid = threadIdx.x;
    size_t base = (size_t)row * Dm;
    float4 hv = ((const float4*)(h + base))[tid];
    float4 ov = ((const float4*)(o + base))[tid];
    if (THREE) {
        float4 xv = ((const float4*)(x + base))[tid];
        hv.x += xv.x + ov.x; hv.y += xv.y + ov.y;
        hv.z += xv.z + ov.z; hv.w += xv.w + ov.w;
    } else {
        hv.x += ov.x; hv.y += ov.y; hv.z += ov.z; hv.w += ov.w;
    }
    ((float4*)(h + base))[tid] = hv;
    ln_row(hv, g, b, tid, out ? out + base : nullptr, outr ? outr + base : nullptr);
}

// ---------------- cp.async helpers ----------------
__device__ __forceinline__ void cpa16(void* dst, const void* src, bool valid) {
    unsigned d = (unsigned)__cvta_generic_to_shared(dst);
    int sz = valid ? 16 : 0;
    asm volatile("cp.async.cg.shared.global [%0], [%1], 16, %2;\n"
                 :: "r"(d), "l"(src), "r"(sz));
}
#define CP_COMMIT() asm volatile("cp.async.commit_group;\n" ::)

// ---------------- tf32 tensor-core GEMM, STAGES-deep cp.async pipeline ------
// A operands pre-rounded by producers. B: RNB=true -> cvt.rna at frag load.
// NT=false: B[K,N] row-major. NT=true: B[N,K].
// Tile: BM = MT*32 rows x BN = CW*32 cols. Warps: 2 row x CW col, 64*CW threads.
// ACT: 0 none, 3 gelu, 4 phase-epilogue, 5 dual-op (z=0 tanh->C, z=1 none->C2).
// CAUSAL: clamp K at row0+BM. SWAPG: row blocks in x. RND: round outputs.
template<int ACT, bool NT, int MT, int CW, int STAGES,
         bool CAUSAL, bool SWAPG, bool RND, bool RNB>
__global__ __launch_bounds__(64 * CW, CW == 2 ? 4 : 2)
void mma_gemm(const float* __restrict__ A, const float* __restrict__ Bm,
              const float* __restrict__ bias, float* __restrict__ C,
              int M, int N, int K,
              size_t sA, size_t sB, size_t sC,
              float* __restrict__ S_out, const float* __restrict__ psc,
              const float* __restrict__ csc, int layer,
              const float* __restrict__ Bm2, const float* __restrict__ bias2,
              float* __restrict__ C2) {
    const int BM = MT * 32;
    const int BN = CW * 32;
    const int THREADS = 64 * CW;
    const int BSTRIDE = BN + 8;
    __shared__ __align__(16) float As[STAGES][MT * 32][20];
    __shared__ __align__(16) float Bs[NT ? 1 : STAGES][16][BSTRIDE];  // [k][n]
    __shared__ __align__(16) float Bs2[NT ? STAGES : 1][CW * 32][20]; // [n][k]

    A  += (size_t)blockIdx.z * sA;
    Bm += (size_t)blockIdx.z * sB;
    C  += (size_t)blockIdx.z * sC;
    if (ACT == 5 && blockIdx.z == 1) { Bm = Bm2; bias = bias2; C = C2; }

    const int tid = threadIdx.x;
    const int lane = tid & 31;
    const int wid = tid >> 5;
    const int wm = (wid / CW) * (MT * 16);
    const int wn = (wid % CW) * 32;
    const int tr = lane >> 2, tc = lane & 3;
    const int row0 = (SWAPG ? blockIdx.x : blockIdx.y) * BM;
    const int col0 = (SWAPG ? blockIdx.y : blockIdx.x) * BN;
    const bool wact = (col0 + wn) < N;

    float acc[MT][4][4];
    #pragma unroll
    for (int i = 0; i < MT; i++)
        #pragma unroll
        for (int j = 0; j < 4; j++)
            #pragma unroll
            for (int l = 0; l < 4; l++) acc[i][j][l] = 0.f;

    int KT = K >> 4;
    if (CAUSAL) { int kc = (row0 + BM) >> 4; KT = kc < KT ? kc : KT; }

    auto load_stage = [&](int st, int k0) {
        #pragma unroll
        for (int id = tid; id < BM * 4; id += THREADS) {
            int r = id >> 2, cc = (id & 3) << 2;
            cpa16(&As[st][r][cc], A + (size_t)(row0 + r) * K + k0 + cc, true);
        }
        if (!NT) {
            #pragma unroll
            for (int id = tid; id < 4 * BN; id += THREADS) {
                int r = id / (BN / 4), c4 = (id % (BN / 4)) << 2;
                bool ok = (col0 + c4) < N;
                const float* src = Bm + (size_t)(k0 + r) * N + (ok ? (col0 + c4) : 0);
                cpa16(&Bs[st][r][c4], src, ok);
            }
        } else {
            #pragma unroll
            for (int id = tid; id < 4 * BN; id += THREADS) {
                int n = id >> 2, kc = (id & 3) << 2;
                bool ok = (col0 + n) < N;
                const float* src = Bm + (size_t)(col0 + (ok ? n : 0)) * K + k0 + kc;
                cpa16(&Bs2[st][n][kc], src, ok);
            }
        }
    };

    #pragma unroll
    for (int s = 0; s < STAGES - 1; s++) {
        if (s < KT) load_stage(s, s << 4);
        CP_COMMIT();
    }

    for (int kt = 0; kt < KT; kt++) {
        asm volatile("cp.async.wait_group %0;\n" :: "n"(STAGES - 2));
        __syncthreads();
        if (kt + STAGES - 1 < KT)
            load_stage((kt + STAGES - 1) % STAGES, (kt + STAGES - 1) << 4);
        CP_COMMIT();
        const int st = kt % STAGES;
        if (wact) {
            #pragma unroll
            for (int k8 = 0; k8 < 2; k8++) {
                const int kb = k8 << 3;
                unsigned a[MT][4], b[4][2];
                #pragma unroll
                for (int mt = 0; mt < MT; mt++) {
                    const float* p = &As[st][wm + mt * 16 + tr][kb + tc];
                    a[mt][0] = __float_as_uint(p[0]);
                    a[mt][1] = __float_as_uint(p[8 * 20]);
                    a[mt][2] = __float_as_uint(p[4]);
                    a[mt][3] = __float_as_uint(p[8 * 20 + 4]);
                }
                #pragma unroll
                for (int nt = 0; nt < 4; nt++) {
                    if (!NT) {
                        const float* p = &Bs[st][kb + tc][wn + nt * 8 + tr];
                        if (RNB) {
                            b[nt][0] = rna(p[0]);
                            b[nt][1] = rna(p[4 * BSTRIDE]);
                        } else {
                            b[nt][0] = __float_as_uint(p[0]);
                            b[nt][1] = __float_as_uint(p[4 * BSTRIDE]);
                        }
                    } else {
                        const float* p = &Bs2[st][wn + nt * 8 + tr][kb + tc];
                        if (RNB) {
                            b[nt][0] = rna(p[0]);
                            b[nt][1] = rna(p[4]);
                        } else {
                            b[nt][0] = __float_as_uint(p[0]);
                            b[nt][1] = __float_as_uint(p[4]);
                        }
                    }
                }
                #pragma unroll
                for (int mt = 0; mt < MT; mt++)
                    #pragma unroll
                    for (int nt = 0; nt < 4; nt++)
                        asm volatile(
                            "mma.sync.aligned.m16n8k8.row.col.f32.tf32.tf32.f32 "
                            "{%0,%1,%2,%3}, {%4,%5,%6,%7}, {%8,%9}, {%0,%1,%2,%3};\n"
                            : "+f"(acc[mt][nt][0]), "+f"(acc[mt][nt][1]),
                              "+f"(acc[mt][nt][2]), "+f"(acc[mt][nt][3])
                            : "r"(a[mt][0]), "r"(a[mt][1]), "r"(a[mt][2]), "r"(a[mt][3]),
                              "r"(b[nt][0]), "r"(b[nt][1]));
            }
        }
    }

    if (!wact) return;
    // epilogue
    #pragma unroll
    for (int mt = 0; mt < MT; mt++) {
        int r0 = row0 + wm + mt * 16 + tr;
        #pragma unroll
        for (int nt = 0; nt < 4; nt++) {
            int c0 = col0 + wn + nt * 8 + 2 * tc;
            if (c0 >= N) continue;
            float bcol0 = bias ? bias[c0] : 0.f;
            float bcol1 = bias ? bias[c0 + 1] : 0.f;
            #pragma unroll
            for (int half = 0; half < 2; half++) {
                int r = r0 + half * 8;
                float v0 = acc[mt][nt][half * 2 + 0] + bcol0;
                float v1 = acc[mt][nt][half * 2 + 1] + bcol1;
                if (ACT == 3) {
                    v0 = 0.5f * v0 * (1.0f + erff(v0 * 0.70710678118654752f));
                    v1 = 0.5f * v1 * (1.0f + erff(v1 * 0.70710678118654752f));
                } else if (ACT == 5) {
                    if (blockIdx.z == 0) { v0 = tanhf(v0); v1 = tanhf(v1); }
                }
                if (ACT == 4) {
                    int l = r & (Lseq - 1);
                    float ps = psc[layer], cs = csc[layer];
                    float fl = (float)l;
                    #pragma unroll
                    for (int cc = 0; cc < 2; cc++) {
                        int c = c0 + cc;
                        float val = tanhf(cc ? v1 : v0) * 3.14159274101257324f;
                        float fr = expf((float)c * (-9.210340371976184f / 32.0f));
                        float tp = ps * (fl * fr) + cs * val;
                        float sv, cv;
                        sincosf(tp, &sv, &cv);
                        C[(size_t)r * N + c] = cv;
                        S_out[(size_t)r * N + c] = sv;
                    }
                } else {
                    if (RND) { v0 = rnaf(v0); v1 = rnaf(v1); }
                    *(float2*)(C + (size_t)r * N + c0) = make_float2(v0, v1);
                }
            }
        }
    }
}

// ---------------- causal A = (C C^T + S S^T) * inv_norm[l], tf32-rounded ----
__global__ void build_A_kernel(const float* __restrict__ C, const float* __restrict__ S,
                               float* __restrict__ A) {
    __shared__ float cl[16][33], sl[16][33], ct[16][33], st[16][33];
    int b = blockIdx.z;
    int tid = threadIdx.y * 16 + threadIdx.x;
    int l0 = blockIdx.y * 16, t0 = blockIdx.x * 16;
    const float* Cb = C + (size_t)b * Lseq * Kp;
    const float* Sb = S + (size_t)b * Lseq * Kp;
    for (int i = tid; i < 16 * 32; i += 256) {
        int r = i >> 5, c = i & 31;
        cl[r][c] = Cb[(size_t)(l0 + r) * Kp + c];
        sl[r][c] = Sb[(size_t)(l0 + r) * Kp + c];
        ct[r][c] = Cb[(size_t)(t0 + r) * Kp + c];
        st[r][c] = Sb[(size_t)(t0 + r) * Kp + c];
    }
    __syncthreads();
    int l = l0 + threadIdx.y, t = t0 + threadIdx.x;
    float acc = 0.f;
    #pragma unroll
    for (int k = 0; k < 32; k++)
        acc += cl[threadIdx.y][k] * ct[threadIdx.x][k]
             + sl[threadIdx.y][k] * st[threadIdx.x][k];
    float out = (t <= l) ? rnaf(acc * rsqrtf((float)((l + 1) * Kp))) : 0.f;
    A[((size_t)b * Lseq + l) * Lseq + t] = out;
}

// ---------------- driver ----------------
extern "C" void kernel_launch(void* const* d_in, const int* in_sizes, int n_in,
                              void* d_out, int out_size) {
    const int*   tokens  = (const int*)  d_in[0];
    const float* embed   = (const float*)d_in[1];
    const float* ln1_g   = (const float*)d_in[2];
    const float* ln1_b   = (const float*)d_in[3];
    const float* cp_w1   = (const float*)d_in[4];
    const float* cp_b1   = (const float*)d_in[5];
    const float* cp_w2   = (const float*)d_in[6];
    const float* cp_b2   = (const float*)d_in[7];
    const float* pscale  = (const float*)d_in[8];
    const float* cscale  = (const float*)d_in[9];
    const float* val_w   = (const float*)d_in[10];
    const float* val_b   = (const float*)d_in[11];
    const float* oln_g   = (const float*)d_in[12];
    const float* oln_b   = (const float*)d_in[13];
    const float* out_w   = (const float*)d_in[14];
    const float* out_b   = (const float*)d_in[15];
    const float* ln2_g   = (const float*)d_in[16];
    const float* ln2_b   = (const float*)d_in[17];
    const float* ffn_w1  = (const float*)d_in[18];
    const float* ffn_b1  = (const float*)d_in[19];
    const float* ffn_w2  = (const float*)d_in[20];
    const float* ffn_b2  = (const float*)d_in[21];
    const float* no_g    = (const float*)d_in[22];
    const float* no_b    = (const float*)d_in[23];
    const float* head_b  = (const float*)d_in[24];
    float* logits = (float*)d_out;

    float *h, *x, *xr, *t1, *Cb, *Sb, *v, *A, *ret, *rln, *o, *mid;
    cudaGetSymbolAddress((void**)&h,    g_h);
    cudaGetSymbolAddress((void**)&x,    g_x);
    cudaGetSymbolAddress((void**)&xr,   g_xr);
    cudaGetSymbolAddress((void**)&t1,   g_t1);
    cudaGetSymbolAddress((void**)&Cb,   g_C);
    cudaGetSymbolAddress((void**)&Sb,   g_S);
    cudaGetSymbolAddress((void**)&v,    g_v);
    cudaGetSymbolAddress((void**)&A,    g_A);
    cudaGetSymbolAddress((void**)&ret,  g_ret);
    cudaGetSymbolAddress((void**)&rln,  g_rln);
    cudaGetSymbolAddress((void**)&o,    g_o);
    cudaGetSymbolAddress((void**)&mid,  g_mid);

    gather_kernel<<<NTOK, 128>>>(tokens, embed, h);
    ln_kernel<<<NTOK, 128>>>(h, ln1_g, ln1_b, x, xr);

    // layer GEMMs: 64x64 tiles, 128 threads, 4-stage pipeline
    dim3 gDual(Dm / 64, NTOK / 64, 2);         // 8 x 32 x 2
    dim3 gD(Dm / 64,  NTOK / 64);              // 8 x 32
    dim3 gK(1,        NTOK / 64);              // N=32 -> 1 col block
    dim3 gF(FFd / 64, NTOK / 64);              // 32 x 32
    dim3 gAv(Dm / 64, Lseq / 64, Bsz);         // 8 x 16 x 2

    for (int i = 0; i < NLY; i++) {
        // z=0: t1 = tanh(xr @ w1 + b1); z=1: v = xr @ vw + vb  (raw weights, RNB)
        mma_gemm<5, false, 2, 2, 4, false, false, true, true><<<gDual, 128>>>(
            xr, cp_w1 + (size_t)i * Dm * Dm, cp_b1 + i * Dm, t1, NTOK, Dm, Dm,
            0, 0, 0, nullptr, nullptr, nullptr, 0,
            val_w + (size_t)i * Dm * Dm, val_b + i * Dm, v);
        mma_gemm<4, false, 2, 2, 4, false, false, false, true><<<gK, 128>>>(
            t1, cp_w2 + (size_t)i * Dm * Kp, cp_b2 + i * Kp, Cb, NTOK, Kp, Dm,
            0, 0, 0, Sb, pscale, cscale, i, nullptr, nullptr, nullptr);
        build_A_kernel<<<dim3(Lseq / 16, Lseq / 16, Bsz), dim3(16, 16)>>>(Cb, Sb, A);
        mma_gemm<0, false, 2, 2, 4, true, false, false, false><<<gAv, 128>>>(
            A, v, nullptr, ret, Lseq, Dm, Lseq,
            (size_t)Lseq * Lseq, (size_t)Lseq * Dm, (size_t)Lseq * Dm,
            nullptr, nullptr, nullptr, 0, nullptr, nullptr, nullptr);
        ln_kernel<<<NTOK, 128>>>(ret, oln_g + i * Dm, oln_b + i * Dm, nullptr, rln);
        mma_gemm<0, false, 2, 2, 4, false, false, false, true><<<gD, 128>>>(
            rln, out_w + (size_t)i * Dm * Dm, out_b + i * Dm, o, NTOK, Dm, Dm,
            0, 0, 0, nullptr, nullptr, nullptr, 0, nullptr, nullptr, nullptr);
        add_ln_kernel<true><<<NTOK, 128>>>(h, x, o, ln2_g + i * Dm, ln2_b + i * Dm,
                                           nullptr, xr);
        mma_gemm<3, false, 2, 2, 4, false, false, true, true><<<gF, 128>>>(
            xr, ffn_w1 + (size_t)i * Dm * FFd, ffn_b1 + i * FFd, mid, NTOK, FFd, Dm,
            0, 0, 0, nullptr, nullptr, nullptr, 0, nullptr, nullptr, nullptr);
        mma_gemm<0, false, 2, 2, 4, false, false, false, true><<<gD, 128>>>(
            mid, ffn_w2 + (size_t)i * FFd * Dm, ffn_b2 + i * Dm, o, NTOK, Dm, FFd,
            0, 0, 0, nullptr, nullptr, nullptr, 0, nullptr, nullptr, nullptr);
        const float* ng = (i < NLY - 1) ? (ln1_g + (i + 1) * Dm) : no_g;
        const float* nb = (i < NLY - 1) ? (ln1_b + (i + 1) * Dm) : no_b;
        add_ln_kernel<false><<<NTOK, 128>>>(h, nullptr, o, ng, nb, x, xr);
    }

    // head: 128x128 tiles, row-blocks in x -> embed slices stay in L2
    dim3 gH(NTOK / 128, Vocab / 128);
    mma_gemm<0, true, 4, 4, 3, false, true, false, true><<<gH, 256>>>(
        xr, embed, head_b, logits, NTOK, Vocab, Dm,
        0, 0, 0, nullptr, nullptr, nullptr, 0, nullptr, nullptr, nullptr);
}

// round 8
// speedup vs baseline: 3.5987x; 1.0472x over previous
#include <cuda_runtime.h>
#include <math.h>

#define Bsz   2
#define Lseq  1024
#define Dm    512
#define Kp    32
#define NLY   4
#define FFd   2048
#define Vocab 32000
#define NTOK  (Bsz*Lseq)   // 2048

// ---------------- scratch (no allocs allowed) ----------------
__device__ float g_h  [NTOK*Dm];
__device__ float g_x  [NTOK*Dm];    // exact LN1 output (residual add)
__device__ float g_xr [NTOK*Dm];    // tf32-rounded GEMM input
__device__ float g_t1 [NTOK*Dm];
__device__ float g_C  [NTOK*Kp];
__device__ float g_S  [NTOK*Kp];
__device__ float g_v  [NTOK*Dm];
__device__ float g_A  [Bsz*Lseq*Lseq];
__device__ float g_ret[NTOK*Dm];
__device__ float g_rln[NTOK*Dm];
__device__ float g_o  [NTOK*Dm];
__device__ float g_mid[NTOK*FFd];

__device__ __forceinline__ unsigned rna(float x) {
    unsigned r;
    asm("cvt.rna.tf32.f32 %0, %1;\n" : "=r"(r) : "f"(x));
    return r;
}
__device__ __forceinline__ float rnaf(float x) { return __uint_as_float(rna(x)); }

// ---------------- embed gather ----------------
__global__ void gather_kernel(const int* __restrict__ tokens,
                              const float* __restrict__ embed,
                              float* __restrict__ h) {
    int row = blockIdx.x;
    int tok = tokens[row];
    const float4* src = (const float4*)(embed + (size_t)tok * Dm);
    float4* dst = (float4*)(h + (size_t)row * Dm);
    dst[threadIdx.x] = src[threadIdx.x];
}

// ---------------- layernorm core (writes exact and/or rounded) ----------------
__device__ __forceinline__ void ln_row(float4 v, const float* g, const float* b,
                                       int tid, float* out_row, float* outr_row) {
    float s = v.x + v.y + v.z + v.w;
    float q = v.x*v.x + v.y*v.y + v.z*v.z + v.w*v.w;
    #pragma unroll
    for (int off = 16; off; off >>= 1) {
        s += __shfl_xor_sync(0xffffffffu, s, off);
        q += __shfl_xor_sync(0xffffffffu, q, off);
    }
    __shared__ float ss[4], sq[4];
    int w = tid >> 5;
    if ((tid & 31) == 0) { ss[w] = s; sq[w] = q; }
    __syncthreads();
    s = ss[0] + ss[1] + ss[2] + ss[3];
    q = sq[0] + sq[1] + sq[2] + sq[3];
    float mean = s * (1.0f / Dm);
    float var  = q * (1.0f / Dm) - mean * mean;
    float r = rsqrtf(var + 1e-5f);
    float4 gv = ((const float4*)g)[tid], bv = ((const float4*)b)[tid], o;
    o.x = (v.x - mean) * r * gv.x + bv.x;
    o.y = (v.y - mean) * r * gv.y + bv.y;
    o.z = (v.z - mean) * r * gv.z + bv.z;
    o.w = (v.w - mean) * r * gv.w + bv.w;
    if (out_row)  ((float4*)out_row)[tid] = o;
    if (outr_row) {
        float4 t;
        t.x = rnaf(o.x); t.y = rnaf(o.y); t.z = rnaf(o.z); t.w = rnaf(o.w);
        ((float4*)outr_row)[tid] = t;
    }
}

__global__ void ln_kernel(const float* __restrict__ in,
                          const float* __restrict__ g,
                          const float* __restrict__ b,
                          float* __restrict__ out, float* __restrict__ outr) {
    int row = blockIdx.x, tid = threadIdx.x;
    float4 v = ((const float4*)(in + (size_t)row * Dm))[tid];
    ln_row(v, g, b, tid, out ? out + (size_t)row * Dm : nullptr,
           outr ? outr + (size_t)row * Dm : nullptr);
}

// fused residual-add + layernorm. THREE: h += x + o, else h += o.
template<bool THREE>
__global__ void add_ln_kernel(float* __restrict__ h, const float* __restrict__ x,
                              const float* __restrict__ o,
                              const float* __restrict__ g, const float* __restrict__ b,
                              float* __restrict__ out, float* __restrict__ outr) {
    int row = blockIdx.x, tid = threadIdx.x;
    size_t base = (size_t)row * Dm;
    float4 hv = ((const float4*)(h + base))[tid];
    float4 ov = ((const float4*)(o + base))[tid];
    if (THREE) {
        float4 xv = ((const float4*)(x + base))[tid];
        hv.x += xv.x + ov.x; hv.y += xv.y + ov.y;
        hv.z += xv.z + ov.z; hv.w += xv.w + ov.w;
    } else {
        hv.x += ov.x; hv.y += ov.y; hv.z += ov.z; hv.w += ov.w;
    }
    ((float4*)(h + base))[tid] = hv;
    ln_row(hv, g, b, tid, out ? out + base : nullptr, outr ? outr + base : nullptr);
}

// ---------------- cp.async helpers ----------------
__device__ __forceinline__ void cpa16(void* dst, const void* src, bool valid) {
    unsigned d = (unsigned)__cvta_generic_to_shared(dst);
    int sz = valid ? 16 : 0;
    asm volatile("cp.async.cg.shared.global [%0], [%1], 16, %2;\n"
                 :: "r"(d), "l"(src), "r"(sz));
}
#define CP_COMMIT() asm volatile("cp.async.commit_group;\n" ::)

// ---------------- tf32 tensor-core GEMM, BK=32, STAGES-deep pipeline --------
// Dynamic smem. A operands pre-rounded by producers; B: RNB -> cvt.rna at load.
// NT=false: B[K,N] row-major. NT=true: B[N,K].
// Tile: BM = MT*32 x BN = CW*32. Warps: 2 row x CW col, 64*CW threads.
// ACT: 0 none, 3 gelu, 4 phase-epilogue, 5 dual-op (z=0 tanh->C, z=1 none->C2).
// CAUSAL: clamp K at row0+BM. SWAPG: row blocks in x. RND: round outputs.
template<int ACT, bool NT, int MT, int CW, int STAGES,
         bool CAUSAL, bool SWAPG, bool RND, bool RNB>
__global__ __launch_bounds__(64 * CW, CW == 2 ? 3 : 2)
void mma_gemm(const float* __restrict__ A, const float* __restrict__ Bm,
              const float* __restrict__ bias, float* __restrict__ C,
              int M, int N, int K,
              size_t sA, size_t sB, size_t sC,
              float* __restrict__ S_out, const float* __restrict__ psc,
              const float* __restrict__ csc, int layer,
              const float* __restrict__ Bm2, const float* __restrict__ bias2,
              float* __restrict__ C2) {
    const int BM = MT * 32;
    const int BN = CW * 32;
    const int THREADS = 64 * CW;
    const int ASTRIDE = 36;              // 32 k + 4 pad
    const int BSTRIDE = BN + 8;          // [k][n] layout pad
    extern __shared__ float dsm[];
    float* As = dsm;                                  // [STAGES][BM][36]
    float* Bs = dsm + (size_t)STAGES * BM * ASTRIDE;  // !NT: [STAGES][32][BN+8]
                                                      //  NT: [STAGES][BN][36]
    A  += (size_t)blockIdx.z * sA;
    Bm += (size_t)blockIdx.z * sB;
    C  += (size_t)blockIdx.z * sC;
    if (ACT == 5 && blockIdx.z == 1) { Bm = Bm2; bias = bias2; C = C2; }

    const int tid = threadIdx.x;
    const int lane = tid & 31;
    const int wid = tid >> 5;
    const int wm = (wid / CW) * (MT * 16);
    const int wn = (wid % CW) * 32;
    const int tr = lane >> 2, tc = lane & 3;
    const int row0 = (SWAPG ? blockIdx.x : blockIdx.y) * BM;
    const int col0 = (SWAPG ? blockIdx.y : blockIdx.x) * BN;
    const bool wact = (col0 + wn) < N;

    float acc[MT][4][4];
    #pragma unroll
    for (int i = 0; i < MT; i++)
        #pragma unroll
        for (int j = 0; j < 4; j++)
            #pragma unroll
            for (int l = 0; l < 4; l++) acc[i][j][l] = 0.f;

    int KT = K >> 5;                       // 32-wide k tiles
    if (CAUSAL) { int kc = (row0 + BM) >> 5; KT = kc < KT ? kc : KT; }

    auto load_stage = [&](int st, int k0) {
        for (int id = tid; id < BM * 8; id += THREADS) {
            int r = id >> 3, cc = (id & 7) << 2;
            cpa16(As + ((size_t)st * BM + r) * ASTRIDE + cc,
                  A + (size_t)(row0 + r) * K + k0 + cc, true);
        }
        if (!NT) {
            const int BN4 = BN / 4;
            for (int id = tid; id < 8 * BN; id += THREADS) {
                int r = id / BN4, c4 = (id % BN4) << 2;
                bool ok = (col0 + c4) < N;
                const float* src = Bm + (size_t)(k0 + r) * N + (ok ? (col0 + c4) : 0);
                cpa16(Bs + ((size_t)st * 32 + r) * BSTRIDE + c4, src, ok);
            }
        } else {
            for (int id = tid; id < BN * 8; id += THREADS) {
                int n = id >> 3, kc = (id & 7) << 2;
                bool ok = (col0 + n) < N;
                const float* src = Bm + (size_t)(col0 + (ok ? n : 0)) * K + k0 + kc;
                cpa16(Bs + ((size_t)st * BN + n) * ASTRIDE + kc, src, ok);
            }
        }
    };

    #pragma unroll
    for (int s = 0; s < STAGES - 1; s++) {
        if (s < KT) load_stage(s, s << 5);
        CP_COMMIT();
    }

    for (int kt = 0; kt < KT; kt++) {
        asm volatile("cp.async.wait_group %0;\n" :: "n"(STAGES - 2));
        __syncthreads();
        if (kt + STAGES - 1 < KT)
            load_stage((kt + STAGES - 1) % STAGES, (kt + STAGES - 1) << 5);
        CP_COMMIT();
        const int st = kt % STAGES;
        if (wact) {
            #pragma unroll
            for (int k8 = 0; k8 < 4; k8++) {
                const int kb = k8 << 3;
                unsigned a[MT][4], b[4][2];
                #pragma unroll
                for (int mt = 0; mt < MT; mt++) {
                    const float* p = As + ((size_t)st * BM + wm + mt * 16 + tr) * ASTRIDE
                                     + kb + tc;
                    a[mt][0] = __float_as_uint(p[0]);
                    a[mt][1] = __float_as_uint(p[8 * ASTRIDE]);
                    a[mt][2] = __float_as_uint(p[4]);
                    a[mt][3] = __float_as_uint(p[8 * ASTRIDE + 4]);
                }
                #pragma unroll
                for (int nt = 0; nt < 4; nt++) {
                    if (!NT) {
                        const float* p = Bs + ((size_t)st * 32 + kb + tc) * BSTRIDE
                                         + wn + nt * 8 + tr;
                        if (RNB) {
                            b[nt][0] = rna(p[0]);
                            b[nt][1] = rna(p[4 * BSTRIDE]);
                        } else {
                            b[nt][0] = __float_as_uint(p[0]);
                            b[nt][1] = __float_as_uint(p[4 * BSTRIDE]);
                        }
                    } else {
                        const float* p = Bs + ((size_t)st * BN + wn + nt * 8 + tr) * ASTRIDE
                                         + kb + tc;
                        if (RNB) {
                            b[nt][0] = rna(p[0]);
                            b[nt][1] = rna(p[4]);
                        } else {
                            b[nt][0] = __float_as_uint(p[0]);
                            b[nt][1] = __float_as_uint(p[4]);
                        }
                    }
                }
                #pragma unroll
                for (int mt = 0; mt < MT; mt++)
                    #pragma unroll
                    for (int nt = 0; nt < 4; nt++)
                        asm volatile(
                            "mma.sync.aligned.m16n8k8.row.col.f32.tf32.tf32.f32 "
                            "{%0,%1,%2,%3}, {%4,%5,%6,%7}, {%8,%9}, {%0,%1,%2,%3};\n"
                            : "+f"(acc[mt][nt][0]), "+f"(acc[mt][nt][1]),
                              "+f"(acc[mt][nt][2]), "+f"(acc[mt][nt][3])
                            : "r"(a[mt][0]), "r"(a[mt][1]), "r"(a[mt][2]), "r"(a[mt][3]),
                              "r"(b[nt][0]), "r"(b[nt][1]));
            }
        }
    }

    if (!wact) return;
    // epilogue
    #pragma unroll
    for (int mt = 0; mt < MT; mt++) {
        int r0 = row0 + wm + mt * 16 + tr;
        #pragma unroll
        for (int nt = 0; nt < 4; nt++) {
            int c0 = col0 + wn + nt * 8 + 2 * tc;
            if (c0 >= N) continue;
            float bcol0 = bias ? bias[c0] : 0.f;
            float bcol1 = bias ? bias[c0 + 1] : 0.f;
            #pragma unroll
            for (int half = 0; half < 2; half++) {
                int r = r0 + half * 8;
                float v0 = acc[mt][nt][half * 2 + 0] + bcol0;
                float v1 = acc[mt][nt][half * 2 + 1] + bcol1;
                if (ACT == 3) {
                    v0 = 0.5f * v0 * (1.0f + erff(v0 * 0.70710678118654752f));
                    v1 = 0.5f * v1 * (1.0f + erff(v1 * 0.70710678118654752f));
                } else if (ACT == 5) {
                    if (blockIdx.z == 0) { v0 = tanhf(v0); v1 = tanhf(v1); }
                }
                if (ACT == 4) {
                    int l = r & (Lseq - 1);
                    float ps = psc[layer], cs = csc[layer];
                    float fl = (float)l;
                    #pragma unroll
                    for (int cc = 0; cc < 2; cc++) {
                        int c = c0 + cc;
                        float val = tanhf(cc ? v1 : v0) * 3.14159274101257324f;
                        float fr = expf((float)c * (-9.210340371976184f / 32.0f));
                        float tp = ps * (fl * fr) + cs * val;
                        float sv, cv;
                        sincosf(tp, &sv, &cv);
                        C[(size_t)r * N + c] = cv;
                        S_out[(size_t)r * N + c] = sv;
                    }
                } else {
                    if (RND) { v0 = rnaf(v0); v1 = rnaf(v1); }
                    *(float2*)(C + (size_t)r * N + c0) = make_float2(v0, v1);
                }
            }
        }
    }
}

// ---------------- causal A = (C C^T + S S^T) * inv_norm[l], tf32-rounded ----
__global__ void build_A_kernel(const float* __restrict__ C, const float* __restrict__ S,
                               float* __restrict__ A) {
    __shared__ float cl[16][33], sl[16][33], ct[16][33], st[16][33];
    int b = blockIdx.z;
    int tid = threadIdx.y * 16 + threadIdx.x;
    int l0 = blockIdx.y * 16, t0 = blockIdx.x * 16;
    const float* Cb = C + (size_t)b * Lseq * Kp;
    const float* Sb = S + (size_t)b * Lseq * Kp;
    for (int i = tid; i < 16 * 32; i += 256) {
        int r = i >> 5, c = i & 31;
        cl[r][c] = Cb[(size_t)(l0 + r) * Kp + c];
        sl[r][c] = Sb[(size_t)(l0 + r) * Kp + c];
        ct[r][c] = Cb[(size_t)(t0 + r) * Kp + c];
        st[r][c] = Sb[(size_t)(t0 + r) * Kp + c];
    }
    __syncthreads();
    int l = l0 + threadIdx.y, t = t0 + threadIdx.x;
    float acc = 0.f;
    #pragma unroll
    for (int k = 0; k < 32; k++)
        acc += cl[threadIdx.y][k] * ct[threadIdx.x][k]
             + sl[threadIdx.y][k] * st[threadIdx.x][k];
    float out = (t <= l) ? rnaf(acc * rsqrtf((float)((l + 1) * Kp))) : 0.f;
    A[((size_t)b * Lseq + l) * Lseq + t] = out;
}

// ---------------- driver ----------------
extern "C" void kernel_launch(void* const* d_in, const int* in_sizes, int n_in,
                              void* d_out, int out_size) {
    const int*   tokens  = (const int*)  d_in[0];
    const float* embed   = (const float*)d_in[1];
    const float* ln1_g   = (const float*)d_in[2];
    const float* ln1_b   = (const float*)d_in[3];
    const float* cp_w1   = (const float*)d_in[4];
    const float* cp_b1   = (const float*)d_in[5];
    const float* cp_w2   = (const float*)d_in[6];
    const float* cp_b2   = (const float*)d_in[7];
    const float* pscale  = (const float*)d_in[8];
    const float* cscale  = (const float*)d_in[9];
    const float* val_w   = (const float*)d_in[10];
    const float* val_b   = (const float*)d_in[11];
    const float* oln_g   = (const float*)d_in[12];
    const float* oln_b   = (const float*)d_in[13];
    const float* out_w   = (const float*)d_in[14];
    const float* out_b   = (const float*)d_in[15];
    const float* ln2_g   = (const float*)d_in[16];
    const float* ln2_b   = (const float*)d_in[17];
    const float* ffn_w1  = (const float*)d_in[18];
    const float* ffn_b1  = (const float*)d_in[19];
    const float* ffn_w2  = (const float*)d_in[20];
    const float* ffn_b2  = (const float*)d_in[21];
    const float* no_g    = (const float*)d_in[22];
    const float* no_b    = (const float*)d_in[23];
    const float* head_b  = (const float*)d_in[24];
    float* logits = (float*)d_out;

    float *h, *x, *xr, *t1, *Cb, *Sb, *v, *A, *ret, *rln, *o, *mid;
    cudaGetSymbolAddress((void**)&h,    g_h);
    cudaGetSymbolAddress((void**)&x,    g_x);
    cudaGetSymbolAddress((void**)&xr,   g_xr);
    cudaGetSymbolAddress((void**)&t1,   g_t1);
    cudaGetSymbolAddress((void**)&Cb,   g_C);
    cudaGetSymbolAddress((void**)&Sb,   g_S);
    cudaGetSymbolAddress((void**)&v,    g_v);
    cudaGetSymbolAddress((void**)&A,    g_A);
    cudaGetSymbolAddress((void**)&ret,  g_ret);
    cudaGetSymbolAddress((void**)&rln,  g_rln);
    cudaGetSymbolAddress((void**)&o,    g_o);
    cudaGetSymbolAddress((void**)&mid,  g_mid);

    // dynamic smem sizes
    const int SM_L  = 4 * (64 * 36 + 32 * 72) * 4;       // layer: STAGES=4, !NT -> 73728
    const int SM_LT = 4 * (64 * 36 + 64 * 36) * 4;       // layer NT (unused) guard
    const int SM_H  = 3 * (128 * 36 + 128 * 36) * 4;     // head: STAGES=3, NT -> 110592
    (void)SM_LT;

    // kernel handles (instantiations)
    auto kDual = mma_gemm<5, false, 2, 2, 4, false, false, true,  true>;
    auto kPhs  = mma_gemm<4, false, 2, 2, 4, false, false, false, true>;
    auto kAv   = mma_gemm<0, false, 2, 2, 4, true,  false, false, false>;
    auto kPlain= mma_gemm<0, false, 2, 2, 4, false, false, false, true>;
    auto kGelu = mma_gemm<3, false, 2, 2, 4, false, false, true,  true>;
    auto kHead = mma_gemm<0, true,  4, 4, 3, false, true,  false, true>;

    cudaFuncSetAttribute(kDual,  cudaFuncAttributeMaxDynamicSharedMemorySize, SM_L);
    cudaFuncSetAttribute(kPhs,   cudaFuncAttributeMaxDynamicSharedMemorySize, SM_L);
    cudaFuncSetAttribute(kAv,    cudaFuncAttributeMaxDynamicSharedMemorySize, SM_L);
    cudaFuncSetAttribute(kPlain, cudaFuncAttributeMaxDynamicSharedMemorySize, SM_L);
    cudaFuncSetAttribute(kGelu,  cudaFuncAttributeMaxDynamicSharedMemorySize, SM_L);
    cudaFuncSetAttribute(kHead,  cudaFuncAttributeMaxDynamicSharedMemorySize, SM_H);

    gather_kernel<<<NTOK, 128>>>(tokens, embed, h);
    ln_kernel<<<NTOK, 128>>>(h, ln1_g, ln1_b, x, xr);

    dim3 gDual(Dm / 64, NTOK / 64, 2);
    dim3 gD(Dm / 64,  NTOK / 64);
    dim3 gK(1,        NTOK / 64);
    dim3 gF(FFd / 64, NTOK / 64);
    dim3 gAv(Dm / 64, Lseq / 64, Bsz);

    for (int i = 0; i < NLY; i++) {
        kDual<<<gDual, 128, SM_L>>>(
            xr, cp_w1 + (size_t)i * Dm * Dm, cp_b1 + i * Dm, t1, NTOK, Dm, Dm,
            0, 0, 0, nullptr, nullptr, nullptr, 0,
            val_w + (size_t)i * Dm * Dm, val_b + i * Dm, v);
        kPhs<<<gK, 128, SM_L>>>(
            t1, cp_w2 + (size_t)i * Dm * Kp, cp_b2 + i * Kp, Cb, NTOK, Kp, Dm,
            0, 0, 0, Sb, pscale, cscale, i, nullptr, nullptr, nullptr);
        build_A_kernel<<<dim3(Lseq / 16, Lseq / 16, Bsz), dim3(16, 16)>>>(Cb, Sb, A);
        kAv<<<gAv, 128, SM_L>>>(
            A, v, nullptr, ret, Lseq, Dm, Lseq,
            (size_t)Lseq * Lseq, (size_t)Lseq * Dm, (size_t)Lseq * Dm,
            nullptr, nullptr, nullptr, 0, nullptr, nullptr, nullptr);
        ln_kernel<<<NTOK, 128>>>(ret, oln_g + i * Dm, oln_b + i * Dm, nullptr, rln);
        kPlain<<<gD, 128, SM_L>>>(
            rln, out_w + (size_t)i * Dm * Dm, out_b + i * Dm, o, NTOK, Dm, Dm,
            0, 0, 0, nullptr, nullptr, nullptr, 0, nullptr, nullptr, nullptr);
        add_ln_kernel<true><<<NTOK, 128>>>(h, x, o, ln2_g + i * Dm, ln2_b + i * Dm,
                                           nullptr, xr);
        kGelu<<<gF, 128, SM_L>>>(
            xr, ffn_w1 + (size_t)i * Dm * FFd, ffn_b1 + i * FFd, mid, NTOK, FFd, Dm,
            0, 0, 0, nullptr, nullptr, nullptr, 0, nullptr, nullptr, nullptr);
        kPlain<<<gD, 128, SM_L>>>(
            mid, ffn_w2 + (size_t)i * FFd * Dm, ffn_b2 + i * Dm, o, NTOK, Dm, FFd,
            0, 0, 0, nullptr, nullptr, nullptr, 0, nullptr, nullptr, nullptr);
        const float* ng = (i < NLY - 1) ? (ln1_g + (i + 1) * Dm) : no_g;
        const float* nb = (i < NLY - 1) ? (ln1_b + (i + 1) * Dm) : no_b;
        add_ln_kernel<false><<<NTOK, 128>>>(h, nullptr, o, ng, nb, x, xr);
    }

    // head: 128x128 tiles, row-blocks in x -> embed slices stay in L2
    dim3 gH(NTOK / 128, Vocab / 128);
    kHead<<<gH, 256, SM_H>>>(
        xr, embed, head_b, logits, NTOK, Vocab, Dm,
        0, 0, 0, nullptr, nullptr, nullptr, 0, nullptr, nullptr, nullptr);
}

// round 10
// speedup vs baseline: 3.7868x; 1.0523x over previous
#include <cuda_runtime.h>
#include <math.h>

#define Bsz   2
#define Lseq  1024
#define Dm    512
#define Kp    32
#define NLY   4
#define FFd   2048
#define Vocab 32000
#define NTOK  (Bsz*Lseq)   // 2048

// ---------------- scratch (no allocs allowed) ----------------
__device__ float g_h  [NTOK*Dm];
__device__ float g_x  [NTOK*Dm];    // exact LN1 output (residual add)
__device__ float g_xr [NTOK*Dm];    // tf32-rounded GEMM input
__device__ float g_t1 [NTOK*Dm];
__device__ float g_cpr[NTOK*Kp];    // raw cp-projection (pre-tanh)
__device__ float g_C  [NTOK*Kp];
__device__ float g_S  [NTOK*Kp];
__device__ float g_v  [NTOK*Dm];
__device__ float g_A  [Bsz*Lseq*Lseq];
__device__ float g_ret[NTOK*Dm];
__device__ float g_rln[NTOK*Dm];
__device__ float g_o  [NTOK*Dm];
__device__ float g_mid[NTOK*FFd];

__device__ __forceinline__ unsigned rna(float x) {
    unsigned r;
    asm("cvt.rna.tf32.f32 %0, %1;\n" : "=r"(r) : "f"(x));
    return r;
}
__device__ __forceinline__ float rnaf(float x) { return __uint_as_float(rna(x)); }

// ---------------- embed gather ----------------
__global__ void gather_kernel(const int* __restrict__ tokens,
                              const float* __restrict__ embed,
                              float* __restrict__ h) {
    int row = blockIdx.x;
    int tok = tokens[row];
    const float4* src = (const float4*)(embed + (size_t)tok * Dm);
    float4* dst = (float4*)(h + (size_t)row * Dm);
    dst[threadIdx.x] = src[threadIdx.x];
}

// ---------------- layernorm core (writes exact and/or rounded) ----------------
__device__ __forceinline__ void ln_row(float4 v, const float* g, const float* b,
                                       int tid, float* out_row, float* outr_row) {
    float s = v.x + v.y + v.z + v.w;
    float q = v.x*v.x + v.y*v.y + v.z*v.z + v.w*v.w;
    #pragma unroll
    for (int off = 16; off; off >>= 1) {
        s += __shfl_xor_sync(0xffffffffu, s, off);
        q += __shfl_xor_sync(0xffffffffu, q, off);
    }
    __shared__ float ss[4], sq[4];
    int w = tid >> 5;
    if ((tid & 31) == 0) { ss[w] = s; sq[w] = q; }
    __syncthreads();
    s = ss[0] + ss[1] + ss[2] + ss[3];
    q = sq[0] + sq[1] + sq[2] + sq[3];
    float mean = s * (1.0f / Dm);
    float var  = q * (1.0f / Dm) - mean * mean;
    float r = rsqrtf(var + 1e-5f);
    float4 gv = ((const float4*)g)[tid], bv = ((const float4*)b)[tid], o;
    o.x = (v.x - mean) * r * gv.x + bv.x;
    o.y = (v.y - mean) * r * gv.y + bv.y;
    o.z = (v.z - mean) * r * gv.z + bv.z;
    o.w = (v.w - mean) * r * gv.w + bv.w;
    if (out_row)  ((float4*)out_row)[tid] = o;
    if (outr_row) {
        float4 t;
        t.x = rnaf(o.x); t.y = rnaf(o.y); t.z = rnaf(o.z); t.w = rnaf(o.w);
        ((float4*)outr_row)[tid] = t;
    }
}

__global__ void ln_kernel(const float* __restrict__ in,
                          const float* __restrict__ g,
                          const float* __restrict__ b,
                          float* __restrict__ out, float* __restrict__ outr) {
    int row = blockIdx.x, tid = threadIdx.x;
    float4 v = ((const float4*)(in + (size_t)row * Dm))[tid];
    ln_row(v, g, b, tid, out ? out + (size_t)row * Dm : nullptr,
           outr ? outr + (size_t)row * Dm : nullptr);
}

// fused residual-add + layernorm. THREE: h += x + o, else h += o.
template<bool THREE>
__global__ void add_ln_kernel(float* __restrict__ h, const float* __restrict__ x,
                              const float* __restrict__ o,
                              const float* __restrict__ g, const float* __restrict__ b,
                              float* __restrict__ out, float* __restrict__ outr) {
    int row = blockIdx.x, tid = threadIdx.x;
    size_t base = (size_t)row * Dm;
    float4 hv = ((const float4*)(h + base))[tid];
    float4 ov = ((const float4*)(o + base))[tid];
    if (THREE) {
        float4 xv = ((const float4*)(x + base))[tid];
        hv.x += xv.x + ov.x; hv.y += xv.y + ov.y;
        hv.z += xv.z + ov.z; hv.w += xv.w + ov.w;
    } else {
        hv.x += ov.x; hv.y += ov.y; hv.z += ov.z; hv.w += ov.w;
    }
    ((float4*)(h + base))[tid] = hv;
    ln_row(hv, g, b, tid, out ? out + base : nullptr, outr ? outr + base : nullptr);
}

// ---------------- phase: full-chip elementwise tanh/exp/sincos --------------
__global__ void phase_kernel(const float* __restrict__ raw,
                             const float* __restrict__ psc,
                             const float* __restrict__ csc, int layer,
                             float* __restrict__ C, float* __restrict__ S) {
    int idx = blockIdx.x * 256 + threadIdx.x;
    if (idx >= NTOK * Kp) return;
    int k = idx & (Kp - 1);
    int l = (idx >> 5) & (Lseq - 1);
    float val = tanhf(raw[idx]) * 3.14159274101257324f;
    float fr = expf((float)k * (-9.210340371976184f / 32.0f));
    float tp = psc[layer] * ((float)l * fr) + csc[layer] * val;
    float sv, cv;
    sincosf(tp, &sv, &cv);
    C[idx] = cv;
    S[idx] = sv;
}

// ---------------- cp.async helpers ----------------
__device__ __forceinline__ void cpa16(void* dst, const void* src, bool valid) {
    unsigned d = (unsigned)__cvta_generic_to_shared(dst);
    int sz = valid ? 16 : 0;
    asm volatile("cp.async.cg.shared.global [%0], [%1], 16, %2;\n"
                 :: "r"(d), "l"(src), "r"(sz));
}
#define CP_COMMIT() asm volatile("cp.async.commit_group;\n" ::)

// ---------------- tf32 tensor-core GEMM, BK=32, intra-CTA split-K -----------
// KS=2: two independent 128-thread pipelines (named barriers) each do half of
// K, partial sums reduced through smem; doubles resident warps per SMSP.
// Dynamic smem. A operands pre-rounded; B: RNB -> cvt.rna at fragment load.
// NT=false: B[K,N]. NT=true: B[N,K]. Group tile: BM=MT*32 x BN=CW*32.
// ACT: 0 none, 3 gelu, 5 dual-op (z=0 tanh->C, z=1 none->C2).
// CAUSAL: clamp K at row0+BM. SWAPG: row blocks in x. RND: round outputs.
template<int ACT, bool NT, int MT, int CW, int STAGES, int KS,
         bool CAUSAL, bool SWAPG, bool RND, bool RNB>
__global__ __launch_bounds__(64 * CW * KS, 2)
void mma_gemm(const float* __restrict__ A, const float* __restrict__ Bm,
              const float* __restrict__ bias, float* __restrict__ C,
              int M, int N, int K,
              size_t sA, size_t sB, size_t sC,
              const float* __restrict__ Bm2, const float* __restrict__ bias2,
              float* __restrict__ C2) {
    const int BM = MT * 32;
    const int BN = CW * 32;
    const int TG = 64 * CW;              // threads per pipeline group
    const int ASTRIDE = 36;              // 32 k + 4 pad
    const int BSTRIDE = BN + 8;
    const int AFLOATS = STAGES * BM * ASTRIDE;
    const int BFLOATS = STAGES * (NT ? BN * ASTRIDE : 32 * BSTRIDE);
    const int SGROUP = AFLOATS + BFLOATS;
    extern __shared__ float dsm[];

    A  += (size_t)blockIdx.z * sA;
    Bm += (size_t)blockIdx.z * sB;
    C  += (size_t)blockIdx.z * sC;
    if (ACT == 5 && blockIdx.z == 1) { Bm = Bm2; bias = bias2; C = C2; }

    const int tid = threadIdx.x;
    const int g   = (KS == 2) ? (tid / TG) : 0;
    const int tg  = tid % TG;
    const int lane = tg & 31;
    const int wlocal = tg >> 5;
    const int wm = (wlocal / CW) * (MT * 16);
    const int wn = (wlocal % CW) * 32;
    const int tr = lane >> 2, tc = lane & 3;
    const int row0 = (SWAPG ? blockIdx.x : blockIdx.y) * BM;
    const int col0 = (SWAPG ? blockIdx.y : blockIdx.x) * BN;
    const bool wact = (col0 + wn) < N;

    float* As = dsm + g * SGROUP;
    float* Bs = As + AFLOATS;

    float acc[MT][4][4];
    #pragma unroll
    for (int i = 0; i < MT; i++)
        #pragma unroll
        for (int j = 0; j < 4; j++)
            #pragma unroll
            for (int l = 0; l < 4; l++) acc[i][j][l] = 0.f;

    int KT = K >> 5;
    if (CAUSAL) { int kc = (row0 + BM) >> 5; KT = kc < KT ? kc : KT; }
    int Kb = 0, KTn = KT;
    if (KS == 2) {
        int half = (KT + 1) >> 1;
        Kb  = g ? half : 0;
        KTn = g ? (KT - half) : half;
    }

    auto load_stage = [&](int st, int k0) {
        for (int id = tg; id < BM * 8; id += TG) {
            int r = id >> 3, cc = (id & 7) << 2;
            cpa16(As + ((size_t)st * BM + r) * ASTRIDE + cc,
                  A + (size_t)(row0 + r) * K + k0 + cc, true);
        }
        if (!NT) {
            const int BN4 = BN / 4;
            for (int id = tg; id < 8 * BN; id += TG) {
                int r = id / BN4, c4 = (id % BN4) << 2;
                bool ok = (col0 + c4) < N;
                const float* src = Bm + (size_t)(k0 + r) * N + (ok ? (col0 + c4) : 0);
                cpa16(Bs + ((size_t)st * 32 + r) * BSTRIDE + c4, src, ok);
            }
        } else {
            for (int id = tg; id < BN * 8; id += TG) {
                int n = id >> 3, kc = (id & 7) << 2;
                bool ok = (col0 + n) < N;
                const float* src = Bm + (size_t)(col0 + (ok ? n : 0)) * K + k0 + kc;
                cpa16(Bs + ((size_t)st * BN + n) * ASTRIDE + kc, src, ok);
            }
        }
    };
    auto groupbar = [&]() {
        if (KS == 1) __syncthreads();
        else asm volatile("bar.sync %0, %1;\n" :: "r"(g + 1), "r"(TG) : "memory");
    };

    #pragma unroll
    for (int s = 0; s < STAGES - 1; s++) {
        if (s < KTn) load_stage(s, (Kb + s) << 5);
        CP_COMMIT();
    }

    for (int kt = 0; kt < KTn; kt++) {
        asm volatile("cp.async.wait_group %0;\n" :: "n"(STAGES - 2));
        groupbar();
        if (kt + STAGES - 1 < KTn)
            load_stage((kt + STAGES - 1) % STAGES, (Kb + kt + STAGES - 1) << 5);
        CP_COMMIT();
        const int st = kt % STAGES;
        if (wact) {
            #pragma unroll
            for (int k8 = 0; k8 < 4; k8++) {
                const int kb = k8 << 3;
                unsigned a[MT][4], b[4][2];
                #pragma unroll
                for (int mt = 0; mt < MT; mt++) {
                    const float* p = As + ((size_t)st * BM + wm + mt * 16 + tr) * ASTRIDE
                                     + kb + tc;
                    a[mt][0] = __float_as_uint(p[0]);
                    a[mt][1] = __float_as_uint(p[8 * ASTRIDE]);
                    a[mt][2] = __float_as_uint(p[4]);
                    a[mt][3] = __float_as_uint(p[8 * ASTRIDE + 4]);
                }
                #pragma unroll
                for (int nt = 0; nt < 4; nt++) {
                    if (!NT) {
                        const float* p = Bs + ((size_t)st * 32 + kb + tc) * BSTRIDE
                                         + wn + nt * 8 + tr;
                        if (RNB) {
                            b[nt][0] = rna(p[0]);
                            b[nt][1] = rna(p[4 * BSTRIDE]);
                        } else {
                            b[nt][0] = __float_as_uint(p[0]);
                            b[nt][1] = __float_as_uint(p[4 * BSTRIDE]);
                        }
                    } else {
                        const float* p = Bs + ((size_t)st * BN + wn + nt * 8 + tr) * ASTRIDE
                                         + kb + tc;
                        if (RNB) {
                            b[nt][0] = rna(p[0]);
                            b[nt][1] = rna(p[4]);
                        } else {
                            b[nt][0] = __float_as_uint(p[0]);
                            b[nt][1] = __float_as_uint(p[4]);
                        }
                    }
                }
                #pragma unroll
                for (int mt = 0; mt < MT; mt++)
                    #pragma unroll
                    for (int nt = 0; nt < 4; nt++)
                        asm volatile(
                            "mma.sync.aligned.m16n8k8.row.col.f32.tf32.tf32.f32 "
                            "{%0,%1,%2,%3}, {%4,%5,%6,%7}, {%8,%9}, {%0,%1,%2,%3};\n"
                            : "+f"(acc[mt][nt][0]), "+f"(acc[mt][nt][1]),
                              "+f"(acc[mt][nt][2]), "+f"(acc[mt][nt][3])
                            : "r"(a[mt][0]), "r"(a[mt][1]), "r"(a[mt][2]), "r"(a[mt][3]),
                              "r"(b[nt][0]), "r"(b[nt][1]));
            }
        }
    }

    if (KS == 2) {
        // RACE FIX: drain ALL pending cp.async (tail prefetches) in BOTH groups
        // before reusing group1's As region as the reduction buffer.
        asm volatile("cp.async.wait_group 0;\n" ::);
        __syncthreads();
        float* red = dsm + SGROUP;    // group1's As region (now quiescent)
        if (g == 1) {
            int idx = 0;
            #pragma unroll
            for (int mt = 0; mt < MT; mt++)
                #pragma unroll
                for (int nt = 0; nt < 4; nt++)
                    #pragma unroll
                    for (int l = 0; l < 4; l++)
                        red[(idx++) * TG + tg] = acc[mt][nt][l];
        }
        __syncthreads();
        if (g == 0) {
            int idx = 0;
            #pragma unroll
            for (int mt = 0; mt < MT; mt++)
                #pragma unroll
                for (int nt = 0; nt < 4; nt++)
                    #pragma unroll
                    for (int l = 0; l < 4; l++)
                        acc[mt][nt][l] += red[(idx++) * TG + tg];
        }
    }

    if (g != 0 || !wact) return;
    // epilogue (group 0 only)
    #pragma unroll
    for (int mt = 0; mt < MT; mt++) {
        int r0 = row0 + wm + mt * 16 + tr;
        #pragma unroll
        for (int nt = 0; nt < 4; nt++) {
            int c0 = col0 + wn + nt * 8 + 2 * tc;
            if (c0 >= N) continue;
            float bcol0 = bias ? bias[c0] : 0.f;
            float bcol1 = bias ? bias[c0 + 1] : 0.f;
            #pragma unroll
            for (int half = 0; half < 2; half++) {
                int r = r0 + half * 8;
                float v0 = acc[mt][nt][half * 2 + 0] + bcol0;
                float v1 = acc[mt][nt][half * 2 + 1] + bcol1;
                if (ACT == 3) {
                    v0 = 0.5f * v0 * (1.0f + erff(v0 * 0.70710678118654752f));
                    v1 = 0.5f * v1 * (1.0f + erff(v1 * 0.70710678118654752f));
                } else if (ACT == 5) {
                    if (blockIdx.z == 0) { v0 = tanhf(v0); v1 = tanhf(v1); }
                }
                if (RND) { v0 = rnaf(v0); v1 = rnaf(v1); }
                *(float2*)(C + (size_t)r * N + c0) = make_float2(v0, v1);
            }
        }
    }
}

// ---------------- causal A = (C C^T + S S^T) * inv_norm[l], tf32-rounded ----
__global__ void build_A_kernel(const float* __restrict__ C, const float* __restrict__ S,
                               float* __restrict__ A) {
    __shared__ float cl[16][33], sl[16][33], ct[16][33], st[16][33];
    int b = blockIdx.z;
    int tid = threadIdx.y * 16 + threadIdx.x;
    int l0 = blockIdx.y * 16, t0 = blockIdx.x * 16;
    const float* Cb = C + (size_t)b * Lseq * Kp;
    const float* Sb = S + (size_t)b * Lseq * Kp;
    for (int i = tid; i < 16 * 32; i += 256) {
        int r = i >> 5, c = i & 31;
        cl[r][c] = Cb[(size_t)(l0 + r) * Kp + c];
        sl[r][c] = Sb[(size_t)(l0 + r) * Kp + c];
        ct[r][c] = Cb[(size_t)(t0 + r) * Kp + c];
        st[r][c] = Sb[(size_t)(t0 + r) * Kp + c];
    }
    __syncthreads();
    int l = l0 + threadIdx.y, t = t0 + threadIdx.x;
    float acc = 0.f;
    #pragma unroll
    for (int k = 0; k < 32; k++)
        acc += cl[threadIdx.y][k] * ct[threadIdx.x][k]
             + sl[threadIdx.y][k] * st[threadIdx.x][k];
    float out = (t <= l) ? rnaf(acc * rsqrtf((float)((l + 1) * Kp))) : 0.f;
    A[((size_t)b * Lseq + l) * Lseq + t] = out;
}

// ---------------- driver ----------------
extern "C" void kernel_launch(void* const* d_in, const int* in_sizes, int n_in,
                              void* d_out, int out_size) {
    const int*   tokens  = (const int*)  d_in[0];
    const float* embed   = (const float*)d_in[1];
    const float* ln1_g   = (const float*)d_in[2];
    const float* ln1_b   = (const float*)d_in[3];
    const float* cp_w1   = (const float*)d_in[4];
    const float* cp_b1   = (const float*)d_in[5];
    const float* cp_w2   = (const float*)d_in[6];
    const float* cp_b2   = (const float*)d_in[7];
    const float* pscale  = (const float*)d_in[8];
    const float* cscale  = (const float*)d_in[9];
    const float* val_w   = (const float*)d_in[10];
    const float* val_b   = (const float*)d_in[11];
    const float* oln_g   = (const float*)d_in[12];
    const float* oln_b   = (const float*)d_in[13];
    const float* out_w   = (const float*)d_in[14];
    const float* out_b   = (const float*)d_in[15];
    const float* ln2_g   = (const float*)d_in[16];
    const float* ln2_b   = (const float*)d_in[17];
    const float* ffn_w1  = (const float*)d_in[18];
    const float* ffn_b1  = (const float*)d_in[19];
    const float* ffn_w2  = (const float*)d_in[20];
    const float* ffn_b2  = (const float*)d_in[21];
    const float* no_g    = (const float*)d_in[22];
    const float* no_b    = (const float*)d_in[23];
    const float* head_b  = (const float*)d_in[24];
    float* logits = (float*)d_out;

    float *h, *x, *xr, *t1, *cpr, *Cb, *Sb, *v, *A, *ret, *rln, *o, *mid;
    cudaGetSymbolAddress((void**)&h,    g_h);
    cudaGetSymbolAddress((void**)&x,    g_x);
    cudaGetSymbolAddress((void**)&xr,   g_xr);
    cudaGetSymbolAddress((void**)&t1,   g_t1);
    cudaGetSymbolAddress((void**)&cpr,  g_cpr);
    cudaGetSymbolAddress((void**)&Cb,   g_C);
    cudaGetSymbolAddress((void**)&Sb,   g_S);
    cudaGetSymbolAddress((void**)&v,    g_v);
    cudaGetSymbolAddress((void**)&A,    g_A);
    cudaGetSymbolAddress((void**)&ret,  g_ret);
    cudaGetSymbolAddress((void**)&rln,  g_rln);
    cudaGetSymbolAddress((void**)&o,    g_o);
    cudaGetSymbolAddress((void**)&mid,  g_mid);

    // dynamic smem: KS * STAGES * (A + B) tiles
    const int SM_L = 2 * 3 * (64 * 36 + 32 * 72) * 4;   // 110592
    const int SM_H = 1 * 3 * (128 * 36 + 128 * 36) * 4; // 110592

    // <ACT, NT, MT, CW, STAGES, KS, CAUSAL, SWAPG, RND, RNB>
    auto kDual = mma_gemm<5, false, 2, 2, 3, 2, false, false, true,  true>;
    auto kCp   = mma_gemm<0, false, 2, 2, 3, 2, false, false, false, true>;
    auto kAv   = mma_gemm<0, false, 2, 2, 3, 2, true,  false, false, false>;
    auto kPlain= mma_gemm<0, false, 2, 2, 3, 2, false, false, false, true>;
    auto kGelu = mma_gemm<3, false, 2, 2, 3, 2, false, false, true,  true>;
    auto kHead = mma_gemm<0, true,  4, 4, 3, 1, false, true,  false, true>;

    cudaFuncSetAttribute(kDual,  cudaFuncAttributeMaxDynamicSharedMemorySize, SM_L);
    cudaFuncSetAttribute(kCp,    cudaFuncAttributeMaxDynamicSharedMemorySize, SM_L);
    cudaFuncSetAttribute(kAv,    cudaFuncAttributeMaxDynamicSharedMemorySize, SM_L);
    cudaFuncSetAttribute(kPlain, cudaFuncAttributeMaxDynamicSharedMemorySize, SM_L);
    cudaFuncSetAttribute(kGelu,  cudaFuncAttributeMaxDynamicSharedMemorySize, SM_L);
    cudaFuncSetAttribute(kHead,  cudaFuncAttributeMaxDynamicSharedMemorySize, SM_H);

    gather_kernel<<<NTOK, 128>>>(tokens, embed, h);
    ln_kernel<<<NTOK, 128>>>(h, ln1_g, ln1_b, x, xr);

    dim3 gDual(Dm / 64, NTOK / 64, 2);
    dim3 gD(Dm / 64,  NTOK / 64);
    dim3 gK(1,        NTOK / 64);
    dim3 gF(FFd / 64, NTOK / 64);
    dim3 gAv(Dm / 64, Lseq / 64, Bsz);

    for (int i = 0; i < NLY; i++) {
        kDual<<<gDual, 256, SM_L>>>(
            xr, cp_w1 + (size_t)i * Dm * Dm, cp_b1 + i * Dm, t1, NTOK, Dm, Dm,
            0, 0, 0, val_w + (size_t)i * Dm * Dm, val_b + i * Dm, v);
        kCp<<<gK, 256, SM_L>>>(
            t1, cp_w2 + (size_t)i * Dm * Kp, cp_b2 + i * Kp, cpr, NTOK, Kp, Dm,
            0, 0, 0, nullptr, nullptr, nullptr);
        phase_kernel<<<(NTOK * Kp) / 256, 256>>>(cpr, pscale, cscale, i, Cb, Sb);
        build_A_kernel<<<dim3(Lseq / 16, Lseq / 16, Bsz), dim3(16, 16)>>>(Cb, Sb, A);
        kAv<<<gAv, 256, SM_L>>>(
            A, v, nullptr, ret, Lseq, Dm, Lseq,
            (size_t)Lseq * Lseq, (size_t)Lseq * Dm, (size_t)Lseq * Dm,
            nullptr, nullptr, nullptr);
        ln_kernel<<<NTOK, 128>>>(ret, oln_g + i * Dm, oln_b + i * Dm, nullptr, rln);
        kPlain<<<gD, 256, SM_L>>>(
            rln, out_w + (size_t)i * Dm * Dm, out_b + i * Dm, o, NTOK, Dm, Dm,
            0, 0, 0, nullptr, nullptr, nullptr);
        add_ln_kernel<true><<<NTOK, 128>>>(h, x, o, ln2_g + i * Dm, ln2_b + i * Dm,
                                           nullptr, xr);
        kGelu<<<gF, 256, SM_L>>>(
            xr, ffn_w1 + (size_t)i * Dm * FFd, ffn_b1 + i * FFd, mid, NTOK, FFd, Dm,
            0, 0, 0, nullptr, nullptr, nullptr);
        kPlain<<<gD, 256, SM_L>>>(
            mid, ffn_w2 + (size_t)i * FFd * Dm, ffn_b2 + i * Dm, o, NTOK, Dm, FFd,
            0, 0, 0, nullptr, nullptr, nullptr);
        const float* ng = (i < NLY - 1) ? (ln1_g + (i + 1) * Dm) : no_g;
        const float* nb = (i < NLY - 1) ? (ln1_b + (i + 1) * Dm) : no_b;
        add_ln_kernel<false><<<NTOK, 128>>>(h, nullptr, o, ng, nb, x, xr);
    }

    // head: 128x128 tiles, row-blocks in x -> embed slices stay in L2
    dim3 gH(NTOK / 128, Vocab / 128);
    kHead<<<gH, 256, SM_H>>>(
        xr, embed, head_b, logits, NTOK, Vocab, Dm,
        0, 0, 0, nullptr, nullptr, nullptr);
}

// round 12
// speedup vs baseline: 3.8360x; 1.0130x over previous
#include <cuda_runtime.h>
#include <math.h>

#define Bsz   2
#define Lseq  1024
#define Dm    512
#define Kp    32
#define NLY   4
#define FFd   2048
#define Vocab 32000
#define NTOK  (Bsz*Lseq)   // 2048

// ---------------- scratch (no allocs allowed) ----------------
__device__ float g_h  [NTOK*Dm];
__device__ float g_x  [NTOK*Dm];    // exact LN1 output (residual add)
__device__ float g_xr [NTOK*Dm];    // tf32-rounded GEMM input
__device__ float g_t1 [NTOK*Dm];
__device__ float g_cpr[NTOK*Kp];    // raw cp-projection (pre-tanh)
__device__ float g_C  [NTOK*Kp];
__device__ float g_S  [NTOK*Kp];
__device__ float g_v  [NTOK*Dm];
__device__ float g_A  [Bsz*Lseq*Lseq];
__device__ float g_ret[NTOK*Dm];
__device__ float g_rln[NTOK*Dm];
__device__ float g_o  [NTOK*Dm];
__device__ float g_mid[NTOK*FFd];

__device__ __forceinline__ unsigned rna(float x) {
    unsigned r;
    asm("cvt.rna.tf32.f32 %0, %1;\n" : "=r"(r) : "f"(x));
    return r;
}
__device__ __forceinline__ float rnaf(float x) { return __uint_as_float(rna(x)); }

// ---------------- embed gather ----------------
__global__ void gather_kernel(const int* __restrict__ tokens,
                              const float* __restrict__ embed,
                              float* __restrict__ h) {
    int row = blockIdx.x;
    int tok = tokens[row];
    const float4* src = (const float4*)(embed + (size_t)tok * Dm);
    float4* dst = (float4*)(h + (size_t)row * Dm);
    dst[threadIdx.x] = src[threadIdx.x];
}

// ---------------- layernorm core (writes exact and/or rounded) ----------------
__device__ __forceinline__ void ln_row(float4 v, const float* g, const float* b,
                                       int tid, float* out_row, float* outr_row) {
    float s = v.x + v.y + v.z + v.w;
    float q = v.x*v.x + v.y*v.y + v.z*v.z + v.w*v.w;
    #pragma unroll
    for (int off = 16; off; off >>= 1) {
        s += __shfl_xor_sync(0xffffffffu, s, off);
        q += __shfl_xor_sync(0xffffffffu, q, off);
    }
    __shared__ float ss[4], sq[4];
    int w = tid >> 5;
    if ((tid & 31) == 0) { ss[w] = s; sq[w] = q; }
    __syncthreads();
    s = ss[0] + ss[1] + ss[2] + ss[3];
    q = sq[0] + sq[1] + sq[2] + sq[3];
    float mean = s * (1.0f / Dm);
    float var  = q * (1.0f / Dm) - mean * mean;
    float r = rsqrtf(var + 1e-5f);
    float4 gv = ((const float4*)g)[tid], bv = ((const float4*)b)[tid], o;
    o.x = (v.x - mean) * r * gv.x + bv.x;
    o.y = (v.y - mean) * r * gv.y + bv.y;
    o.z = (v.z - mean) * r * gv.z + bv.z;
    o.w = (v.w - mean) * r * gv.w + bv.w;
    if (out_row)  ((float4*)out_row)[tid] = o;
    if (outr_row) {
        float4 t;
        t.x = rnaf(o.x); t.y = rnaf(o.y); t.z = rnaf(o.z); t.w = rnaf(o.w);
        ((float4*)outr_row)[tid] = t;
    }
}

__global__ void ln_kernel(const float* __restrict__ in,
                          const float* __restrict__ g,
                          const float* __restrict__ b,
                          float* __restrict__ out, float* __restrict__ outr) {
    int row = blockIdx.x, tid = threadIdx.x;
    float4 v = ((const float4*)(in + (size_t)row * Dm))[tid];
    ln_row(v, g, b, tid, out ? out + (size_t)row * Dm : nullptr,
           outr ? outr + (size_t)row * Dm : nullptr);
}

// fused residual-add + layernorm. THREE: h += x + o, else h += o.
template<bool THREE>
__global__ void add_ln_kernel(float* __restrict__ h, const float* __restrict__ x,
                              const float* __restrict__ o,
                              const float* __restrict__ g, const float* __restrict__ b,
                              float* __restrict__ out, float* __restrict__ outr) {
    int row = blockIdx.x, tid = threadIdx.x;
    size_t base = (size_t)row * Dm;
    float4 hv = ((const float4*)(h + base))[tid];
    float4 ov = ((const float4*)(o + base))[tid];
    if (THREE) {
        float4 xv = ((const float4*)(x + base))[tid];
        hv.x += xv.x + ov.x; hv.y += xv.y + ov.y;
        hv.z += xv.z + ov.z; hv.w += xv.w + ov.w;
    } else {
        hv.x += ov.x; hv.y += ov.y; hv.z += ov.z; hv.w += ov.w;
    }
    ((float4*)(h + base))[tid] = hv;
    ln_row(hv, g, b, tid, out ? out + base : nullptr, outr ? outr + base : nullptr);
}

// ---------------- phase: full-chip elementwise tanh/exp/sincos --------------
__global__ void phase_kernel(const float* __restrict__ raw,
                             const float* __restrict__ psc,
                             const float* __restrict__ csc, int layer,
                             float* __restrict__ C, float* __restrict__ S) {
    int idx = blockIdx.x * 256 + threadIdx.x;
    if (idx >= NTOK * Kp) return;
    int k = idx & (Kp - 1);
    int l = (idx >> 5) & (Lseq - 1);
    float val = tanhf(raw[idx]) * 3.14159274101257324f;
    float fr = expf((float)k * (-9.210340371976184f / 32.0f));
    float tp = psc[layer] * ((float)l * fr) + csc[layer] * val;
    float sv, cv;
    sincosf(tp, &sv, &cv);
    C[idx] = cv;
    S[idx] = sv;
}

// ---------------- cp.async helpers ----------------
__device__ __forceinline__ void cpa16(void* dst, const void* src, bool valid) {
    unsigned d = (unsigned)__cvta_generic_to_shared(dst);
    int sz = valid ? 16 : 0;
    asm volatile("cp.async.cg.shared.global [%0], [%1], 16, %2;\n"
                 :: "r"(d), "l"(src), "r"(sz));
}
#define CP_COMMIT() asm volatile("cp.async.commit_group;\n" ::)

// ---------------- tf32 tensor-core GEMM, BK=32, intra-CTA split-K -----------
// KS=2: two independent 128-thread pipelines (named barriers) each do half of
// K, partial sums reduced through smem; doubles resident warps per SMSP.
// Dynamic smem. A operands pre-rounded; B: RNB -> cvt.rna at fragment load.
// NT=false: B[K,N]. NT=true: B[N,K]. Group tile: BM=MT*32 x BN=CW*32.
// ACT: 0 none, 3 gelu, 5 dual-op (z=0 tanh->C, z=1 none->C2).
// CAUSAL: clamp K at row0+BM. SWAPG: row blocks in x. RND: round outputs.
template<int ACT, bool NT, int MT, int CW, int STAGES, int KS,
         bool CAUSAL, bool SWAPG, bool RND, bool RNB>
__global__ __launch_bounds__(64 * CW * KS, 2)
void mma_gemm(const float* __restrict__ A, const float* __restrict__ Bm,
              const float* __restrict__ bias, float* __restrict__ C,
              int M, int N, int K,
              size_t sA, size_t sB, size_t sC,
              const float* __restrict__ Bm2, const float* __restrict__ bias2,
              float* __restrict__ C2) {
    const int BM = MT * 32;
    const int BN = CW * 32;
    const int TG = 64 * CW;              // threads per pipeline group
    const int ASTRIDE = 36;              // 32 k + 4 pad
    const int BSTRIDE = BN + 8;
    const int AFLOATS = STAGES * BM * ASTRIDE;
    const int BFLOATS = STAGES * (NT ? BN * ASTRIDE : 32 * BSTRIDE);
    const int SGROUP = AFLOATS + BFLOATS;
    extern __shared__ float dsm[];

    A  += (size_t)blockIdx.z * sA;
    Bm += (size_t)blockIdx.z * sB;
    C  += (size_t)blockIdx.z * sC;
    if (ACT == 5 && blockIdx.z == 1) { Bm = Bm2; bias = bias2; C = C2; }

    const int tid = threadIdx.x;
    const int g   = (KS == 2) ? (tid / TG) : 0;
    const int tg  = tid % TG;
    const int lane = tg & 31;
    const int wlocal = tg >> 5;
    const int wm = (wlocal / CW) * (MT * 16);
    const int wn = (wlocal % CW) * 32;
    const int tr = lane >> 2, tc = lane & 3;
    const int row0 = (SWAPG ? blockIdx.x : blockIdx.y) * BM;
    const int col0 = (SWAPG ? blockIdx.y : blockIdx.x) * BN;
    const bool wact = (col0 + wn) < N;

    float* As = dsm + g * SGROUP;
    float* Bs = As + AFLOATS;

    float acc[MT][4][4];
    #pragma unroll
    for (int i = 0; i < MT; i++)
        #pragma unroll
        for (int j = 0; j < 4; j++)
            #pragma unroll
            for (int l = 0; l < 4; l++) acc[i][j][l] = 0.f;

    int KT = K >> 5;
    if (CAUSAL) { int kc = (row0 + BM) >> 5; KT = kc < KT ? kc : KT; }
    int Kb = 0, KTn = KT;
    if (KS == 2) {
        int half = (KT + 1) >> 1;
        Kb  = g ? half : 0;
        KTn = g ? (KT - half) : half;
    }

    auto load_stage = [&](int st, int k0) {
        for (int id = tg; id < BM * 8; id += TG) {
            int r = id >> 3, cc = (id & 7) << 2;
            cpa16(As + ((size_t)st * BM + r) * ASTRIDE + cc,
                  A + (size_t)(row0 + r) * K + k0 + cc, true);
        }
        if (!NT) {
            const int BN4 = BN / 4;
            for (int id = tg; id < 8 * BN; id += TG) {
                int r = id / BN4, c4 = (id % BN4) << 2;
                bool ok = (col0 + c4) < N;
                const float* src = Bm + (size_t)(k0 + r) * N + (ok ? (col0 + c4) : 0);
                cpa16(Bs + ((size_t)st * 32 + r) * BSTRIDE + c4, src, ok);
            }
        } else {
            for (int id = tg; id < BN * 8; id += TG) {
                int n = id >> 3, kc = (id & 7) << 2;
                bool ok = (col0 + n) < N;
                const float* src = Bm + (size_t)(col0 + (ok ? n : 0)) * K + k0 + kc;
                cpa16(Bs + ((size_t)st * BN + n) * ASTRIDE + kc, src, ok);
            }
        }
    };
    auto groupbar = [&]() {
        if (KS == 1) __syncthreads();
        else asm volatile("bar.sync %0, %1;\n" :: "r"(g + 1), "r"(TG) : "memory");
    };

    #pragma unroll
    for (int s = 0; s < STAGES - 1; s++) {
        if (s < KTn) load_stage(s, (Kb + s) << 5);
        CP_COMMIT();
    }

    for (int kt = 0; kt < KTn; kt++) {
        asm volatile("cp.async.wait_group %0;\n" :: "n"(STAGES - 2));
        groupbar();
        if (kt + STAGES - 1 < KTn)
            load_stage((kt + STAGES - 1) % STAGES, (Kb + kt + STAGES - 1) << 5);
        CP_COMMIT();
        const int st = kt % STAGES;
        if (wact) {
            #pragma unroll
            for (int k8 = 0; k8 < 4; k8++) {
                const int kb = k8 << 3;
                unsigned a[MT][4], b[4][2];
                #pragma unroll
                for (int mt = 0; mt < MT; mt++) {
                    const float* p = As + ((size_t)st * BM + wm + mt * 16 + tr) * ASTRIDE
                                     + kb + tc;
                    a[mt][0] = __float_as_uint(p[0]);
                    a[mt][1] = __float_as_uint(p[8 * ASTRIDE]);
                    a[mt][2] = __float_as_uint(p[4]);
                    a[mt][3] = __float_as_uint(p[8 * ASTRIDE + 4]);
                }
                #pragma unroll
                for (int nt = 0; nt < 4; nt++) {
                    if (!NT) {
                        const float* p = Bs + ((size_t)st * 32 + kb + tc) * BSTRIDE
                                         + wn + nt * 8 + tr;
                        if (RNB) {
                            b[nt][0] = rna(p[0]);
                            b[nt][1] = rna(p[4 * BSTRIDE]);
                        } else {
                            b[nt][0] = __float_as_uint(p[0]);
                            b[nt][1] = __float_as_uint(p[4 * BSTRIDE]);
                        }
                    } else {
                        const float* p = Bs + ((size_t)st * BN + wn + nt * 8 + tr) * ASTRIDE
                                         + kb + tc;
                        if (RNB) {
                            b[nt][0] = rna(p[0]);
                            b[nt][1] = rna(p[4]);
                        } else {
                            b[nt][0] = __float_as_uint(p[0]);
                            b[nt][1] = __float_as_uint(p[4]);
                        }
                    }
                }
                #pragma unroll
                for (int mt = 0; mt < MT; mt++)
                    #pragma unroll
                    for (int nt = 0; nt < 4; nt++)
                        asm volatile(
                            "mma.sync.aligned.m16n8k8.row.col.f32.tf32.tf32.f32 "
                            "{%0,%1,%2,%3}, {%4,%5,%6,%7}, {%8,%9}, {%0,%1,%2,%3};\n"
                            : "+f"(acc[mt][nt][0]), "+f"(acc[mt][nt][1]),
                              "+f"(acc[mt][nt][2]), "+f"(acc[mt][nt][3])
                            : "r"(a[mt][0]), "r"(a[mt][1]), "r"(a[mt][2]), "r"(a[mt][3]),
                              "r"(b[nt][0]), "r"(b[nt][1]));
            }
        }
    }

    if (KS == 2) {
        // drain ALL pending cp.async (tail prefetches) in BOTH groups before
        // reusing group1's As region as the reduction buffer.
        asm volatile("cp.async.wait_group 0;\n" ::);
        __syncthreads();
        float* red = dsm + SGROUP;    // group1's As region (now quiescent)
        if (g == 1) {
            int idx = 0;
            #pragma unroll
            for (int mt = 0; mt < MT; mt++)
                #pragma unroll
                for (int nt = 0; nt < 4; nt++)
                    #pragma unroll
                    for (int l = 0; l < 4; l++)
                        red[(idx++) * TG + tg] = acc[mt][nt][l];
        }
        __syncthreads();
        if (g == 0) {
            int idx = 0;
            #pragma unroll
            for (int mt = 0; mt < MT; mt++)
                #pragma unroll
                for (int nt = 0; nt < 4; nt++)
                    #pragma unroll
                    for (int l = 0; l < 4; l++)
                        acc[mt][nt][l] += red[(idx++) * TG + tg];
        }
    }

    if (g != 0 || !wact) return;
    // epilogue (group 0 only)
    #pragma unroll
    for (int mt = 0; mt < MT; mt++) {
        int r0 = row0 + wm + mt * 16 + tr;
        #pragma unroll
        for (int nt = 0; nt < 4; nt++) {
            int c0 = col0 + wn + nt * 8 + 2 * tc;
            if (c0 >= N) continue;
            float bcol0 = bias ? bias[c0] : 0.f;
            float bcol1 = bias ? bias[c0 + 1] : 0.f;
            #pragma unroll
            for (int half = 0; half < 2; half++) {
                int r = r0 + half * 8;
                float v0 = acc[mt][nt][half * 2 + 0] + bcol0;
                float v1 = acc[mt][nt][half * 2 + 1] + bcol1;
                if (ACT == 3) {
                    v0 = 0.5f * v0 * (1.0f + erff(v0 * 0.70710678118654752f));
                    v1 = 0.5f * v1 * (1.0f + erff(v1 * 0.70710678118654752f));
                } else if (ACT == 5) {
                    if (blockIdx.z == 0) { v0 = tanhf(v0); v1 = tanhf(v1); }
                }
                if (RND) { v0 = rnaf(v0); v1 = rnaf(v1); }
                *(float2*)(C + (size_t)r * N + c0) = make_float2(v0, v1);
            }
        }
    }
}

// ---------------- causal A = (C C^T + S S^T) * inv_norm[l], tf32-rounded ----
__global__ void build_A_kernel(const float* __restrict__ C, const float* __restrict__ S,
                               float* __restrict__ A) {
    __shared__ float cl[16][33], sl[16][33], ct[16][33], st[16][33];
    int b = blockIdx.z;
    int tid = threadIdx.y * 16 + threadIdx.x;
    int l0 = blockIdx.y * 16, t0 = blockIdx.x * 16;
    const float* Cb = C + (size_t)b * Lseq * Kp;
    const float* Sb = S + (size_t)b * Lseq * Kp;
    for (int i = tid; i < 16 * 32; i += 256) {
        int r = i >> 5, c = i & 31;
        cl[r][c] = Cb[(size_t)(l0 + r) * Kp + c];
        sl[r][c] = Sb[(size_t)(l0 + r) * Kp + c];
        ct[r][c] = Cb[(size_t)(t0 + r) * Kp + c];
        st[r][c] = Sb[(size_t)(t0 + r) * Kp + c];
    }
    __syncthreads();
    int l = l0 + threadIdx.y, t = t0 + threadIdx.x;
    float acc = 0.f;
    #pragma unroll
    for (int k = 0; k < 32; k++)
        acc += cl[threadIdx.y][k] * ct[threadIdx.x][k]
             + sl[threadIdx.y][k] * st[threadIdx.x][k];
    float out = (t <= l) ? rnaf(acc * rsqrtf((float)((l + 1) * Kp))) : 0.f;
    A[((size_t)b * Lseq + l) * Lseq + t] = out;
}

// ---------------- driver ----------------
extern "C" void kernel_launch(void* const* d_in, const int* in_sizes, int n_in,
                              void* d_out, int out_size) {
    const int*   tokens  = (const int*)  d_in[0];
    const float* embed   = (const float*)d_in[1];
    const float* ln1_g   = (const float*)d_in[2];
    const float* ln1_b   = (const float*)d_in[3];
    const float* cp_w1   = (const float*)d_in[4];
    const float* cp_b1   = (const float*)d_in[5];
    const float* cp_w2   = (const float*)d_in[6];
    const float* cp_b2   = (const float*)d_in[7];
    const float* pscale  = (const float*)d_in[8];
    const float* cscale  = (const float*)d_in[9];
    const float* val_w   = (const float*)d_in[10];
    const float* val_b   = (const float*)d_in[11];
    const float* oln_g   = (const float*)d_in[12];
    const float* oln_b   = (const float*)d_in[13];
    const float* out_w   = (const float*)d_in[14];
    const float* out_b   = (const float*)d_in[15];
    const float* ln2_g   = (const float*)d_in[16];
    const float* ln2_b   = (const float*)d_in[17];
    const float* ffn_w1  = (const float*)d_in[18];
    const float* ffn_b1  = (const float*)d_in[19];
    const float* ffn_w2  = (const float*)d_in[20];
    const float* ffn_b2  = (const float*)d_in[21];
    const float* no_g    = (const float*)d_in[22];
    const float* no_b    = (const float*)d_in[23];
    const float* head_b  = (const float*)d_in[24];
    float* logits = (float*)d_out;

    float *h, *x, *xr, *t1, *cpr, *Cb, *Sb, *v, *A, *ret, *rln, *o, *mid;
    cudaGetSymbolAddress((void**)&h,    g_h);
    cudaGetSymbolAddress((void**)&x,    g_x);
    cudaGetSymbolAddress((void**)&xr,   g_xr);
    cudaGetSymbolAddress((void**)&t1,   g_t1);
    cudaGetSymbolAddress((void**)&cpr,  g_cpr);
    cudaGetSymbolAddress((void**)&Cb,   g_C);
    cudaGetSymbolAddress((void**)&Sb,   g_S);
    cudaGetSymbolAddress((void**)&v,    g_v);
    cudaGetSymbolAddress((void**)&A,    g_A);
    cudaGetSymbolAddress((void**)&ret,  g_ret);
    cudaGetSymbolAddress((void**)&rln,  g_rln);
    cudaGetSymbolAddress((void**)&o,    g_o);
    cudaGetSymbolAddress((void**)&mid,  g_mid);

    // dynamic smem: KS * STAGES * (A + B) tiles
    const int SM_L = 2 * 3 * (64 * 36 + 32 * 72) * 4;   // layers: 110592 (unchanged)
    const int SM_H = 1 * 2 * (128 * 36 + 128 * 36) * 4; // head: STAGES=2 -> 73728
                                                        // => 2 CTAs/SM on the head

    // <ACT, NT, MT, CW, STAGES, KS, CAUSAL, SWAPG, RND, RNB>
    auto kDual = mma_gemm<5, false, 2, 2, 3, 2, false, false, true,  true>;
    auto kCp   = mma_gemm<0, false, 2, 2, 3, 2, false, false, false, true>;
    auto kAv   = mma_gemm<0, false, 2, 2, 3, 2, true,  false, false, false>;
    auto kPlain= mma_gemm<0, false, 2, 2, 3, 2, false, false, false, true>;
    auto kGelu = mma_gemm<3, false, 2, 2, 3, 2, false, false, true,  true>;
    auto kHead = mma_gemm<0, true,  4, 4, 2, 1, false, true,  false, true>;

    cudaFuncSetAttribute(kDual,  cudaFuncAttributeMaxDynamicSharedMemorySize, SM_L);
    cudaFuncSetAttribute(kCp,    cudaFuncAttributeMaxDynamicSharedMemorySize, SM_L);
    cudaFuncSetAttribute(kAv,    cudaFuncAttributeMaxDynamicSharedMemorySize, SM_L);
    cudaFuncSetAttribute(kPlain, cudaFuncAttributeMaxDynamicSharedMemorySize, SM_L);
    cudaFuncSetAttribute(kGelu,  cudaFuncAttributeMaxDynamicSharedMemorySize, SM_L);
    cudaFuncSetAttribute(kHead,  cudaFuncAttributeMaxDynamicSharedMemorySize, SM_H);

    gather_kernel<<<NTOK, 128>>>(tokens, embed, h);
    ln_kernel<<<NTOK, 128>>>(h, ln1_g, ln1_b, x, xr);

    dim3 gDual(Dm / 64, NTOK / 64, 2);
    dim3 gD(Dm / 64,  NTOK / 64);
    dim3 gK(1,        NTOK / 64);
    dim3 gF(FFd / 64, NTOK / 64);
    dim3 gAv(Dm / 64, Lseq / 64, Bsz);

    for (int i = 0; i < NLY; i++) {
        kDual<<<gDual, 256, SM_L>>>(
            xr, cp_w1 + (size_t)i * Dm * Dm, cp_b1 + i * Dm, t1, NTOK, Dm, Dm,
            0, 0, 0, val_w + (size_t)i * Dm * Dm, val_b + i * Dm, v);
        kCp<<<gK, 256, SM_L>>>(
            t1, cp_w2 + (size_t)i * Dm * Kp, cp_b2 + i * Kp, cpr, NTOK, Kp, Dm,
            0, 0, 0, nullptr, nullptr, nullptr);
        phase_kernel<<<(NTOK * Kp) / 256, 256>>>(cpr, pscale, cscale, i, Cb, Sb);
        build_A_kernel<<<dim3(Lseq / 16, Lseq / 16, Bsz), dim3(16, 16)>>>(Cb, Sb, A);
        kAv<<<gAv, 256, SM_L>>>(
            A, v, nullptr, ret, Lseq, Dm, Lseq,
            (size_t)Lseq * Lseq, (size_t)Lseq * Dm, (size_t)Lseq * Dm,
            nullptr, nullptr, nullptr);
        ln_kernel<<<NTOK, 128>>>(ret, oln_g + i * Dm, oln_b + i * Dm, nullptr, rln);
        kPlain<<<gD, 256, SM_L>>>(
            rln, out_w + (size_t)i * Dm * Dm, out_b + i * Dm, o, NTOK, Dm, Dm,
            0, 0, 0, nullptr, nullptr, nullptr);
        add_ln_kernel<true><<<NTOK, 128>>>(h, x, o, ln2_g + i * Dm, ln2_b + i * Dm,
                                           nullptr, xr);
        kGelu<<<gF, 256, SM_L>>>(
            xr, ffn_w1 + (size_t)i * Dm * FFd, ffn_b1 + i * FFd, mid, NTOK, FFd, Dm,
            0, 0, 0, nullptr, nullptr, nullptr);
        kPlain<<<gD, 256, SM_L>>>(
            mid, ffn_w2 + (size_t)i * FFd * Dm, ffn_b2 + i * Dm, o, NTOK, Dm, FFd,
            0, 0, 0, nullptr, nullptr, nullptr);
        const float* ng = (i < NLY - 1) ? (ln1_g + (i + 1) * Dm) : no_g;
        const float* nb = (i < NLY - 1) ? (ln1_b + (i + 1) * Dm) : no_b;
        add_ln_kernel<false><<<NTOK, 128>>>(h, nullptr, o, ng, nb, x, xr);
    }

    // head: 128x128 tiles, STAGES=2 (2 CTAs/SM), row-blocks in x -> embed in L2
    dim3 gH(NTOK / 128, Vocab / 128);
    kHead<<<gH, 256, SM_H>>>(
        xr, embed, head_b, logits, NTOK, Vocab, Dm,
        0, 0, 0, nullptr, nullptr, nullptr);
}